// round 1
// baseline (speedup 1.0000x reference)
#include <cuda_runtime.h>
#include <math.h>

// ---------------- problem constants (fixed by the dataset) ----------------
#define L     131072        // tokens = 32*64*64
#define C     192           // dim
#define NHD   6             // heads
#define HD    32            // head dim
#define NWIN  256           // 4*8*8 windows of 8^3
#define NP    64            // pooled kv tokens per window (4^3)
#define HID   768           // ffn hidden
#define DD    32
#define HHH   64
#define WWW   64

// ---------------- scratch (device globals: allocation-free) ----------------
__device__ float g_xn[L * C];                 // LN output (reused for LN2)
__device__ float g_q [L * C];                 // scaled q, token-major
__device__ float g_k [NWIN * NHD * NP * HD];  // permuted K
__device__ float g_v [NWIN * NHD * NP * HD];  // permuted V
__device__ float g_o [L * C];                 // attention output (pre-proj)
__device__ float g_x1[L * C];                 // post-attention residual
__device__ float g_hid[L * HID];              // gelu(fc1) hidden
__device__ float g_hdn[L * HID];              // hidden + gelu(dwconv)

__device__ __forceinline__ float gelu_f(float v) {
    return 0.5f * v * (1.0f + erff(v * 0.70710678118654752f));
}

// ---------------- LayerNorm: one warp per token (192 elems) ----------------
__global__ void ln_kernel(const float* __restrict__ x, const float* __restrict__ g,
                          const float* __restrict__ b, float* __restrict__ y)
{
    int lane = threadIdx.x & 31;
    int wi   = threadIdx.x >> 5;
    int l    = blockIdx.x * 8 + wi;
    const float* row = x + (size_t)l * C;
    float v[6];
    float s = 0.f, ss = 0.f;
#pragma unroll
    for (int i = 0; i < 6; i++) {
        v[i] = row[lane + 32 * i];
        s  += v[i];
        ss += v[i] * v[i];
    }
#pragma unroll
    for (int off = 16; off > 0; off >>= 1) {
        s  += __shfl_xor_sync(0xffffffffu, s,  off);
        ss += __shfl_xor_sync(0xffffffffu, ss, off);
    }
    float mean = s * (1.0f / C);
    float var  = ss * (1.0f / C) - mean * mean;
    float inv  = rsqrtf(var + 1e-5f);
    float* yr = y + (size_t)l * C;
#pragma unroll
    for (int i = 0; i < 6; i++) {
        int c = lane + 32 * i;
        yr[c] = (v[i] - mean) * inv * g[c] + b[c];
    }
}

// ---------------- fp32 tiled GEMM 64x64x16, 256 thr, 4x4/thread ------------
// C[M,N] = A[M,K] @ B[K,N]; epilogues: 0 = (acc+bias)*scale
//                                      1 = acc+bias+res
//                                      2 = gelu(acc+bias)
template <int EPI>
__global__ void gemm64(const float* __restrict__ A, const float* __restrict__ Bm,
                       const float* __restrict__ bias, const float* __restrict__ res,
                       float* __restrict__ Cm, int M, int N, int K, float scale)
{
    __shared__ float As[16][64];
    __shared__ float Bs[16][64];
    const int tid  = threadIdx.x;
    const int row0 = blockIdx.y * 64, col0 = blockIdx.x * 64;
    const int ty = tid >> 4, tx = tid & 15;
    const int a_row = tid >> 2, a_col = (tid & 3) * 4;
    const int b_row = tid >> 4, b_col = (tid & 15) * 4;

    float acc[4][4];
#pragma unroll
    for (int i = 0; i < 4; i++)
#pragma unroll
        for (int j = 0; j < 4; j++) acc[i][j] = 0.f;

    const float* Ap = A  + (size_t)(row0 + a_row) * K + a_col;
    const float* Bp = Bm + (size_t)b_row * N + col0 + b_col;

    for (int k0 = 0; k0 < K; k0 += 16) {
        float4 av = *(const float4*)(Ap + k0);
        As[a_col + 0][a_row] = av.x;
        As[a_col + 1][a_row] = av.y;
        As[a_col + 2][a_row] = av.z;
        As[a_col + 3][a_row] = av.w;
        *(float4*)&Bs[b_row][b_col] = *(const float4*)(Bp + (size_t)k0 * N);
        __syncthreads();
#pragma unroll
        for (int kk = 0; kk < 16; kk++) {
            float4 a4 = *(const float4*)&As[kk][ty * 4];
            float4 b4 = *(const float4*)&Bs[kk][tx * 4];
            float ar[4] = {a4.x, a4.y, a4.z, a4.w};
            float br[4] = {b4.x, b4.y, b4.z, b4.w};
#pragma unroll
            for (int i = 0; i < 4; i++)
#pragma unroll
                for (int j = 0; j < 4; j++) acc[i][j] += ar[i] * br[j];
        }
        __syncthreads();
    }

#pragma unroll
    for (int i = 0; i < 4; i++) {
        int row = row0 + ty * 4 + i;
        float ov[4];
#pragma unroll
        for (int j = 0; j < 4; j++) {
            int col = col0 + tx * 4 + j;
            float v = acc[i][j] + bias[col];
            if (EPI == 0)      v *= scale;
            else if (EPI == 1) v += res[(size_t)row * N + col];
            else               v = gelu_f(v);
            ov[j] = v;
        }
        *(float4*)&Cm[(size_t)row * N + col0 + tx * 4] =
            make_float4(ov[0], ov[1], ov[2], ov[3]);
    }
}

// ---------------- KV projection + scatter into pooled window layout --------
// 16 tokens/block, 192 threads: thread = (token t, j-group jg of 4 outputs)
__global__ void kvproj_kernel(const float* __restrict__ xn, const float* __restrict__ kvw,
                              const float* __restrict__ kvb,
                              float* __restrict__ ko, float* __restrict__ vo)
{
    __shared__ float sx[16][193];
    const int tid  = threadIdx.x;  // 0..191
    const int base = blockIdx.x * 16;
#pragma unroll
    for (int i = 0; i < 16; i++) sx[i][tid] = xn[(size_t)(base + i) * C + tid];
    __syncthreads();

    const int t  = tid / 12;       // token within block
    const int jg = tid % 12;       // output float4 group: j = jg*4..jg*4+3
    float4 bb = *(const float4*)(kvb + jg * 4);
    float s0 = bb.x, s1 = bb.y, s2 = bb.z, s3 = bb.w;
#pragma unroll 8
    for (int c = 0; c < C; c++) {
        float xv = sx[t][c];
        float4 w4 = *(const float4*)(kvw + c * 48 + jg * 4);
        s0 += xv * w4.x; s1 += xv * w4.y; s2 += xv * w4.z; s3 += xv * w4.w;
    }
    // scatter: token -> (window, pooled m, sub-position), jg -> (kv, head)
    int l  = base + t;
    int z  = l >> 12, y = (l >> 6) & 63, x = l & 63;
    int win = ((z >> 3) << 6) | ((y >> 3) << 3) | (x >> 3);
    int zz = z & 7, yy = y & 7, xx = x & 7;
    int m   = ((zz >> 1) << 4) | ((yy >> 1) << 2) | (xx >> 1);
    int sub = ((zz & 1) << 2)  | ((yy & 1) << 1)  | (xx & 1);
    int head = jg % 6;
    float* dst = (jg < 6) ? ko : vo;
    *(float4*)&dst[(((size_t)(win * NHD + head)) * NP + m) * HD + sub * 4] =
        make_float4(s0, s1, s2, s3);
}

// ---------------- attention: one block per (window, head) ------------------
__global__ void attn_kernel(const float* __restrict__ q, const float* __restrict__ kbuf,
                            const float* __restrict__ vbuf, const float* __restrict__ btab,
                            float* __restrict__ o)
{
    __shared__ float ks[64][33];
    __shared__ float vs[64][33];
    __shared__ float bt[343];
    const int win  = blockIdx.x / NHD;
    const int head = blockIdx.x % NHD;
    const int tid = threadIdx.x, lane = tid & 31, wi = tid >> 5;

    const float* kb = kbuf + (size_t)(win * NHD + head) * NP * HD;
    const float* vb = vbuf + (size_t)(win * NHD + head) * NP * HD;
    for (int i = tid; i < NP * HD; i += 256) {
        ks[i >> 5][i & 31] = kb[i];
        vs[i >> 5][i & 31] = vb[i];
    }
    for (int i = tid; i < 343; i += 256) bt[i] = btab[i * NHD + head];
    __syncthreads();

    const int wz = win >> 6, wy = (win >> 3) & 7, wx = win & 7;

    for (int n = wi; n < 512; n += 8) {
        int zz = n >> 6, yy = (n >> 3) & 7, xx = n & 7;
        int l  = ((wz * 8 + zz) * 64 + (wy * 8 + yy)) * 64 + (wx * 8 + xx);
        float qc = q[(size_t)l * C + head * HD + lane];

        float s0 = 0.f, s1 = 0.f;
#pragma unroll
        for (int c = 0; c < 32; c++) {
            float qv = __shfl_sync(0xffffffffu, qc, c);
            s0 += qv * ks[lane][c];
            s1 += qv * ks[lane + 32][c];
        }
        // relative position bias
        int qz = zz >> 1, qy = yy >> 1, qx = xx >> 1;
        {
            int m0 = lane;
            int kz = m0 >> 4, ky = (m0 >> 2) & 3, kx = m0 & 3;
            s0 += bt[(qz - kz + 3) * 49 + (qy - ky + 3) * 7 + (qx - kx + 3)];
            int m1 = lane + 32;
            kz = m1 >> 4; ky = (m1 >> 2) & 3; kx = m1 & 3;
            s1 += bt[(qz - kz + 3) * 49 + (qy - ky + 3) * 7 + (qx - kx + 3)];
        }
        // softmax over 64 (2 per lane)
        float mx = fmaxf(s0, s1);
#pragma unroll
        for (int off = 16; off > 0; off >>= 1)
            mx = fmaxf(mx, __shfl_xor_sync(0xffffffffu, mx, off));
        float e0 = __expf(s0 - mx), e1 = __expf(s1 - mx);
        float sm = e0 + e1;
#pragma unroll
        for (int off = 16; off > 0; off >>= 1)
            sm += __shfl_xor_sync(0xffffffffu, sm, off);
        float inv = 1.0f / sm;
        float p0 = e0 * inv, p1 = e1 * inv;

        // o[n][lane] = sum_m p_m * v[m][lane]
        float out = 0.f;
#pragma unroll
        for (int mm = 0; mm < 32; mm++) {
            float p = __shfl_sync(0xffffffffu, p0, mm);
            out += p * vs[mm][lane];
        }
#pragma unroll
        for (int mm = 0; mm < 32; mm++) {
            float p = __shfl_sync(0xffffffffu, p1, mm);
            out += p * vs[mm + 32][lane];
        }
        o[(size_t)l * C + head * HD + lane] = out;
    }
}

// ---------------- depthwise 3x3x3 conv + gelu + residual-add ---------------
// block = (z, y, x-quad); 192 threads = channel float4 groups.
// hdn = hid + gelu(conv(hid) + dw_b)
__global__ void dwconv_kernel(const float* __restrict__ hid, const float* __restrict__ wgt,
                              const float* __restrict__ bias, float* __restrict__ hdn)
{
    const int c4  = threadIdx.x;          // 0..191
    const int bid = blockIdx.x;           // 0..32767
    const int x0  = (bid & 15) * 4;
    const int y   = (bid >> 4) & 63;
    const int z   = bid >> 10;

    float4 acc[4];
#pragma unroll
    for (int i = 0; i < 4; i++) acc[i] = make_float4(0.f, 0.f, 0.f, 0.f);

    for (int kd = 0; kd < 3; kd++) {
        int zz = z + kd - 1;
        if (zz < 0 || zz >= DD) continue;
        for (int kh = 0; kh < 3; kh++) {
            int yy = y + kh - 1;
            if (yy < 0 || yy >= HHH) continue;
            const float* base = hid + ((size_t)(zz * HHH + yy) * WWW) * HID + c4 * 4;
            float4 hv[6];
#pragma unroll
            for (int i = 0; i < 6; i++) {
                int xx = x0 - 1 + i;
                hv[i] = (xx >= 0 && xx < WWW) ? *(const float4*)(base + (size_t)xx * HID)
                                              : make_float4(0.f, 0.f, 0.f, 0.f);
            }
#pragma unroll
            for (int kw = 0; kw < 3; kw++) {
                float4 wv = *(const float4*)(wgt + ((kd * 3 + kh) * 3 + kw) * HID + c4 * 4);
#pragma unroll
                for (int xi = 0; xi < 4; xi++) {
                    acc[xi].x += hv[xi + kw].x * wv.x;
                    acc[xi].y += hv[xi + kw].y * wv.y;
                    acc[xi].z += hv[xi + kw].z * wv.z;
                    acc[xi].w += hv[xi + kw].w * wv.w;
                }
            }
        }
    }
    float4 bv = *(const float4*)(bias + c4 * 4);
#pragma unroll
    for (int xi = 0; xi < 4; xi++) {
        size_t idx = ((size_t)((z * HHH + y) * WWW + x0 + xi)) * HID + c4 * 4;
        float4 h0 = *(const float4*)(hid + idx);
        float4 o;
        o.x = h0.x + gelu_f(acc[xi].x + bv.x);
        o.y = h0.y + gelu_f(acc[xi].y + bv.y);
        o.z = h0.z + gelu_f(acc[xi].z + bv.z);
        o.w = h0.w + gelu_f(acc[xi].w + bv.w);
        *(float4*)&hdn[idx] = o;
    }
}

// ---------------- launch ----------------------------------------------------
static float* sym_addr(const void* sym) {
    void* p = nullptr;
    cudaGetSymbolAddress(&p, sym);
    return (float*)p;
}

extern "C" void kernel_launch(void* const* d_in, const int* in_sizes, int n_in,
                              void* d_out, int out_size)
{
    const float* x    = (const float*)d_in[0];
    const float* n1g  = (const float*)d_in[1];
    const float* n1b  = (const float*)d_in[2];
    const float* q_w  = (const float*)d_in[3];
    const float* q_b  = (const float*)d_in[4];
    const float* kv_w = (const float*)d_in[5];
    const float* kv_b = (const float*)d_in[6];
    const float* btab = (const float*)d_in[7];
    const float* p_w  = (const float*)d_in[8];
    const float* p_b  = (const float*)d_in[9];
    const float* n2g  = (const float*)d_in[10];
    const float* n2b  = (const float*)d_in[11];
    const float* f1w  = (const float*)d_in[12];
    const float* f1b  = (const float*)d_in[13];
    const float* dww  = (const float*)d_in[14];
    const float* dwb  = (const float*)d_in[15];
    const float* f2w  = (const float*)d_in[16];
    const float* f2b  = (const float*)d_in[17];
    float* out = (float*)d_out;

    float* xn  = sym_addr(g_xn);
    float* qb_ = sym_addr(g_q);
    float* kb_ = sym_addr(g_k);
    float* vb_ = sym_addr(g_v);
    float* ob_ = sym_addr(g_o);
    float* x1  = sym_addr(g_x1);
    float* hid = sym_addr(g_hid);
    float* hdn = sym_addr(g_hdn);

    const float qscale = 0.17677669529663687f;  // 1/sqrt(32)

    // 1) LN1
    ln_kernel<<<L / 8, 256>>>(x, n1g, n1b, xn);
    // 2) q = (xn @ q_w + q_b) * scale
    gemm64<0><<<dim3(C / 64, L / 64), 256>>>(xn, q_w, q_b, nullptr, qb_, L, C, C, qscale);
    // 3) kv projection + permuted scatter into K/V
    kvproj_kernel<<<L / 16, 192>>>(xn, kv_w, kv_b, kb_, vb_);
    // 4) windowed attention with relative position bias
    attn_kernel<<<NWIN * NHD, 256>>>(qb_, kb_, vb_, btab, ob_);
    // 5) x1 = x + o @ proj_w + proj_b
    gemm64<1><<<dim3(C / 64, L / 64), 256>>>(ob_, p_w, p_b, x, x1, L, C, C, 1.f);
    // 6) LN2
    ln_kernel<<<L / 8, 256>>>(x1, n2g, n2b, xn);
    // 7) hid = gelu(xn @ fc1_w + fc1_b)
    gemm64<2><<<dim3(HID / 64, L / 64), 256>>>(xn, f1w, f1b, nullptr, hid, L, HID, C, 1.f);
    // 8) hdn = hid + gelu(dwconv(hid) + dw_b)
    dwconv_kernel<<<(DD * HHH * WWW) / 4, 192>>>(hid, dww, dwb, hdn);
    // 9) out = x1 + hdn @ fc2_w + fc2_b
    gemm64<1><<<dim3(C / 64, L / 64), 256>>>(hdn, f2w, f2b, x1, out, L, C, HID, 1.f);
}

// round 2
// speedup vs baseline: 1.5960x; 1.5960x over previous
#include <cuda_runtime.h>
#include <math.h>

// ---------------- problem constants (fixed by the dataset) ----------------
#define L     131072        // tokens = 32*64*64
#define C     192           // dim
#define NHD   6             // heads
#define HD    32            // head dim
#define NWIN  256           // 4*8*8 windows of 8^3
#define NP    64            // pooled kv tokens per window (4^3)
#define HID   768           // ffn hidden
#define DD    32
#define HHH   64
#define WWW   64

// ---------------- scratch (device globals: allocation-free) ----------------
__device__ float g_xn[L * C];                 // LN output (reused for LN2)
__device__ float g_q [L * C];                 // scaled q, token-major
__device__ float g_k [NWIN * NHD * NP * HD];  // permuted K
__device__ float g_v [NWIN * NHD * NP * HD];  // permuted V
__device__ float g_o [L * C];                 // attention output (pre-proj)
__device__ float g_x1[L * C];                 // post-attention residual
__device__ float g_hid[L * HID];              // gelu(fc1) hidden
__device__ float g_hdn[L * HID];              // hidden + gelu(dwconv)

__device__ __forceinline__ float gelu_f(float v) {
    return 0.5f * v * (1.0f + erff(v * 0.70710678118654752f));
}

__device__ __forceinline__ unsigned f2tf32(float f) {
    unsigned u;
    asm("cvt.rna.tf32.f32 %0, %1;" : "=r"(u) : "f"(f));
    return u;
}

__device__ __forceinline__ void mma_tf32(float* d, const unsigned* a, const unsigned* b) {
    asm volatile(
        "mma.sync.aligned.m16n8k8.row.col.f32.tf32.tf32.f32 "
        "{%0,%1,%2,%3},{%4,%5,%6,%7},{%8,%9},{%0,%1,%2,%3};"
        : "+f"(d[0]), "+f"(d[1]), "+f"(d[2]), "+f"(d[3])
        : "r"(a[0]), "r"(a[1]), "r"(a[2]), "r"(a[3]), "r"(b[0]), "r"(b[1]));
}

// ---------------- LayerNorm: one warp per token (192 elems) ----------------
__global__ void ln_kernel(const float* __restrict__ x, const float* __restrict__ g,
                          const float* __restrict__ b, float* __restrict__ y)
{
    int lane = threadIdx.x & 31;
    int wi   = threadIdx.x >> 5;
    int l    = blockIdx.x * 8 + wi;
    const float* row = x + (size_t)l * C;
    float v[6];
    float s = 0.f, ss = 0.f;
#pragma unroll
    for (int i = 0; i < 6; i++) {
        v[i] = row[lane + 32 * i];
        s  += v[i];
        ss += v[i] * v[i];
    }
#pragma unroll
    for (int off = 16; off > 0; off >>= 1) {
        s  += __shfl_xor_sync(0xffffffffu, s,  off);
        ss += __shfl_xor_sync(0xffffffffu, ss, off);
    }
    float mean = s * (1.0f / C);
    float var  = ss * (1.0f / C) - mean * mean;
    float inv  = rsqrtf(var + 1e-5f);
    float* yr = y + (size_t)l * C;
#pragma unroll
    for (int i = 0; i < 6; i++) {
        int c = lane + 32 * i;
        yr[c] = (v[i] - mean) * inv * g[c] + b[c];
    }
}

// ---------------- tf32 tensor-core GEMM: 128x64x16, 256 thr ---------------
// C[M,N] = A[M,K] @ B[K,N]; epilogues: 0 = (acc+bias)*scale
//                                      1 = acc+bias+res
//                                      2 = gelu(acc+bias)
// 8 warps in 4(m) x 2(n); warp tile 32x32 via 2x4 m16n8k8 MMAs per k-step.
template <int EPI>
__global__ void __launch_bounds__(256)
gemm_mma(const float* __restrict__ A, const float* __restrict__ Bm,
         const float* __restrict__ bias, const float* __restrict__ res,
         float* __restrict__ Cm, int M, int N, int K, float scale)
{
    __shared__ unsigned As[16][136];   // [k][row], pad 8 -> conflict-free frag LDS
    __shared__ unsigned Bs[16][72];    // [k][col], pad 8

    const int tid  = threadIdx.x;
    const int lane = tid & 31, warp = tid >> 5;
    const int wm = warp & 3, wn = warp >> 2;
    const int row0 = blockIdx.y * 128, col0 = blockIdx.x * 64;

    float acc[2][4][4];
#pragma unroll
    for (int i = 0; i < 2; i++)
#pragma unroll
        for (int j = 0; j < 4; j++)
#pragma unroll
            for (int t = 0; t < 4; t++) acc[i][j][t] = 0.f;

    const int a_row = tid >> 2;            // 0..63 (+64 for second f4)
    const int a_kc  = (tid & 3) * 4;
    const int b_row = tid >> 4, b_c4 = (tid & 15) * 4;

    for (int kt = 0; kt < K; kt += 16) {
        // A tile: 128x16, 2 float4 per thread, transposed store with tf32 cvt
#pragma unroll
        for (int i = 0; i < 2; i++) {
            int r = a_row + i * 64;
            float4 v = *(const float4*)(A + (size_t)(row0 + r) * K + kt + a_kc);
            As[a_kc + 0][r] = f2tf32(v.x);
            As[a_kc + 1][r] = f2tf32(v.y);
            As[a_kc + 2][r] = f2tf32(v.z);
            As[a_kc + 3][r] = f2tf32(v.w);
        }
        // B tile: 16x64, 1 float4 per thread
        {
            float4 v = *(const float4*)(Bm + (size_t)(kt + b_row) * N + col0 + b_c4);
            uint4 u = make_uint4(f2tf32(v.x), f2tf32(v.y), f2tf32(v.z), f2tf32(v.w));
            *(uint4*)&Bs[b_row][b_c4] = u;
        }
        __syncthreads();

#pragma unroll
        for (int ks = 0; ks < 16; ks += 8) {
            unsigned af[2][4], bf[4][2];
            const int k0 = ks + (lane & 3);
            const int rb = wm * 32 + (lane >> 2);
#pragma unroll
            for (int mi = 0; mi < 2; mi++) {
                int r = rb + mi * 16;
                af[mi][0] = As[k0][r];
                af[mi][1] = As[k0][r + 8];
                af[mi][2] = As[k0 + 4][r];
                af[mi][3] = As[k0 + 4][r + 8];
            }
            const int cb = wn * 32 + (lane >> 2);
#pragma unroll
            for (int ni = 0; ni < 4; ni++) {
                bf[ni][0] = Bs[k0][cb + ni * 8];
                bf[ni][1] = Bs[k0 + 4][cb + ni * 8];
            }
#pragma unroll
            for (int mi = 0; mi < 2; mi++)
#pragma unroll
                for (int ni = 0; ni < 4; ni++)
                    mma_tf32(acc[mi][ni], af[mi], bf[ni]);
        }
        __syncthreads();
    }

    // epilogue: c0,c1 at (row, col..col+1); c2,c3 at (row+8, ...)
    const int crow = row0 + wm * 32 + (lane >> 2);
    const int ccol = col0 + wn * 32 + (lane & 3) * 2;
#pragma unroll
    for (int mi = 0; mi < 2; mi++) {
#pragma unroll
        for (int half = 0; half < 2; half++) {
            int row = crow + mi * 16 + half * 8;
#pragma unroll
            for (int ni = 0; ni < 4; ni++) {
                int col = ccol + ni * 8;
                float v0 = acc[mi][ni][half * 2 + 0] + bias[col];
                float v1 = acc[mi][ni][half * 2 + 1] + bias[col + 1];
                if (EPI == 0)      { v0 *= scale; v1 *= scale; }
                else if (EPI == 1) {
                    float2 rv = *(const float2*)(res + (size_t)row * N + col);
                    v0 += rv.x; v1 += rv.y;
                } else             { v0 = gelu_f(v0); v1 = gelu_f(v1); }
                *(float2*)(Cm + (size_t)row * N + col) = make_float2(v0, v1);
            }
        }
    }
}

// ---------------- KV projection + scatter into pooled window layout --------
__global__ void kvproj_kernel(const float* __restrict__ xn, const float* __restrict__ kvw,
                              const float* __restrict__ kvb,
                              float* __restrict__ ko, float* __restrict__ vo)
{
    __shared__ float sx[16][193];
    const int tid  = threadIdx.x;  // 0..191
    const int base = blockIdx.x * 16;
#pragma unroll
    for (int i = 0; i < 16; i++) sx[i][tid] = xn[(size_t)(base + i) * C + tid];
    __syncthreads();

    const int t  = tid / 12;
    const int jg = tid % 12;
    float4 bb = *(const float4*)(kvb + jg * 4);
    float s0 = bb.x, s1 = bb.y, s2 = bb.z, s3 = bb.w;
#pragma unroll 8
    for (int c = 0; c < C; c++) {
        float xv = sx[t][c];
        float4 w4 = *(const float4*)(kvw + c * 48 + jg * 4);
        s0 += xv * w4.x; s1 += xv * w4.y; s2 += xv * w4.z; s3 += xv * w4.w;
    }
    int l  = base + t;
    int z  = l >> 12, y = (l >> 6) & 63, x = l & 63;
    int win = ((z >> 3) << 6) | ((y >> 3) << 3) | (x >> 3);
    int zz = z & 7, yy = y & 7, xx = x & 7;
    int m   = ((zz >> 1) << 4) | ((yy >> 1) << 2) | (xx >> 1);
    int sub = ((zz & 1) << 2)  | ((yy & 1) << 1)  | (xx & 1);
    int head = jg % 6;
    float* dst = (jg < 6) ? ko : vo;
    *(float4*)&dst[(((size_t)(win * NHD + head)) * NP + m) * HD + sub * 4] =
        make_float4(s0, s1, s2, s3);
}

// ---------------- attention: one block per (window, head) ------------------
__global__ void attn_kernel(const float* __restrict__ q, const float* __restrict__ kbuf,
                            const float* __restrict__ vbuf, const float* __restrict__ btab,
                            float* __restrict__ o)
{
    __shared__ float ks[64][33];
    __shared__ float vs[64][33];
    __shared__ float bt[343];
    const int win  = blockIdx.x / NHD;
    const int head = blockIdx.x % NHD;
    const int tid = threadIdx.x, lane = tid & 31, wi = tid >> 5;

    const float* kb = kbuf + (size_t)(win * NHD + head) * NP * HD;
    const float* vb = vbuf + (size_t)(win * NHD + head) * NP * HD;
    for (int i = tid; i < NP * HD; i += 256) {
        ks[i >> 5][i & 31] = kb[i];
        vs[i >> 5][i & 31] = vb[i];
    }
    for (int i = tid; i < 343; i += 256) bt[i] = btab[i * NHD + head];
    __syncthreads();

    const int wz = win >> 6, wy = (win >> 3) & 7, wx = win & 7;

    for (int n = wi; n < 512; n += 8) {
        int zz = n >> 6, yy = (n >> 3) & 7, xx = n & 7;
        int l  = ((wz * 8 + zz) * 64 + (wy * 8 + yy)) * 64 + (wx * 8 + xx);
        float qc = q[(size_t)l * C + head * HD + lane];

        float s0 = 0.f, s1 = 0.f;
#pragma unroll
        for (int c = 0; c < 32; c++) {
            float qv = __shfl_sync(0xffffffffu, qc, c);
            s0 += qv * ks[lane][c];
            s1 += qv * ks[lane + 32][c];
        }
        int qz = zz >> 1, qy = yy >> 1, qx = xx >> 1;
        {
            int m0 = lane;
            int kz = m0 >> 4, ky = (m0 >> 2) & 3, kx = m0 & 3;
            s0 += bt[(qz - kz + 3) * 49 + (qy - ky + 3) * 7 + (qx - kx + 3)];
            int m1 = lane + 32;
            kz = m1 >> 4; ky = (m1 >> 2) & 3; kx = m1 & 3;
            s1 += bt[(qz - kz + 3) * 49 + (qy - ky + 3) * 7 + (qx - kx + 3)];
        }
        float mx = fmaxf(s0, s1);
#pragma unroll
        for (int off = 16; off > 0; off >>= 1)
            mx = fmaxf(mx, __shfl_xor_sync(0xffffffffu, mx, off));
        float e0 = __expf(s0 - mx), e1 = __expf(s1 - mx);
        float sm = e0 + e1;
#pragma unroll
        for (int off = 16; off > 0; off >>= 1)
            sm += __shfl_xor_sync(0xffffffffu, sm, off);
        float inv = 1.0f / sm;
        float p0 = e0 * inv, p1 = e1 * inv;

        float out = 0.f;
#pragma unroll
        for (int mm = 0; mm < 32; mm++) {
            float p = __shfl_sync(0xffffffffu, p0, mm);
            out += p * vs[mm][lane];
        }
#pragma unroll
        for (int mm = 0; mm < 32; mm++) {
            float p = __shfl_sync(0xffffffffu, p1, mm);
            out += p * vs[mm + 32][lane];
        }
        o[(size_t)l * C + head * HD + lane] = out;
    }
}

// ---------------- depthwise 3x3x3 conv + gelu + residual-add ---------------
__global__ void dwconv_kernel(const float* __restrict__ hid, const float* __restrict__ wgt,
                              const float* __restrict__ bias, float* __restrict__ hdn)
{
    const int c4  = threadIdx.x;          // 0..191
    const int bid = blockIdx.x;           // 0..32767
    const int x0  = (bid & 15) * 4;
    const int y   = (bid >> 4) & 63;
    const int z   = bid >> 10;

    float4 acc[4];
#pragma unroll
    for (int i = 0; i < 4; i++) acc[i] = make_float4(0.f, 0.f, 0.f, 0.f);

    for (int kd = 0; kd < 3; kd++) {
        int zz = z + kd - 1;
        if (zz < 0 || zz >= DD) continue;
        for (int kh = 0; kh < 3; kh++) {
            int yy = y + kh - 1;
            if (yy < 0 || yy >= HHH) continue;
            const float* base = hid + ((size_t)(zz * HHH + yy) * WWW) * HID + c4 * 4;
            float4 hv[6];
#pragma unroll
            for (int i = 0; i < 6; i++) {
                int xx = x0 - 1 + i;
                hv[i] = (xx >= 0 && xx < WWW) ? *(const float4*)(base + (size_t)xx * HID)
                                              : make_float4(0.f, 0.f, 0.f, 0.f);
            }
#pragma unroll
            for (int kw = 0; kw < 3; kw++) {
                float4 wv = *(const float4*)(wgt + ((kd * 3 + kh) * 3 + kw) * HID + c4 * 4);
#pragma unroll
                for (int xi = 0; xi < 4; xi++) {
                    acc[xi].x += hv[xi + kw].x * wv.x;
                    acc[xi].y += hv[xi + kw].y * wv.y;
                    acc[xi].z += hv[xi + kw].z * wv.z;
                    acc[xi].w += hv[xi + kw].w * wv.w;
                }
            }
        }
    }
    float4 bv = *(const float4*)(bias + c4 * 4);
#pragma unroll
    for (int xi = 0; xi < 4; xi++) {
        size_t idx = ((size_t)((z * HHH + y) * WWW + x0 + xi)) * HID + c4 * 4;
        float4 h0 = *(const float4*)(hid + idx);
        float4 o;
        o.x = h0.x + gelu_f(acc[xi].x + bv.x);
        o.y = h0.y + gelu_f(acc[xi].y + bv.y);
        o.z = h0.z + gelu_f(acc[xi].z + bv.z);
        o.w = h0.w + gelu_f(acc[xi].w + bv.w);
        *(float4*)&hdn[idx] = o;
    }
}

// ---------------- launch ----------------------------------------------------
static float* sym_addr(const void* sym) {
    void* p = nullptr;
    cudaGetSymbolAddress(&p, sym);
    return (float*)p;
}

extern "C" void kernel_launch(void* const* d_in, const int* in_sizes, int n_in,
                              void* d_out, int out_size)
{
    const float* x    = (const float*)d_in[0];
    const float* n1g  = (const float*)d_in[1];
    const float* n1b  = (const float*)d_in[2];
    const float* q_w  = (const float*)d_in[3];
    const float* q_b  = (const float*)d_in[4];
    const float* kv_w = (const float*)d_in[5];
    const float* kv_b = (const float*)d_in[6];
    const float* btab = (const float*)d_in[7];
    const float* p_w  = (const float*)d_in[8];
    const float* p_b  = (const float*)d_in[9];
    const float* n2g  = (const float*)d_in[10];
    const float* n2b  = (const float*)d_in[11];
    const float* f1w  = (const float*)d_in[12];
    const float* f1b  = (const float*)d_in[13];
    const float* dww  = (const float*)d_in[14];
    const float* dwb  = (const float*)d_in[15];
    const float* f2w  = (const float*)d_in[16];
    const float* f2b  = (const float*)d_in[17];
    float* out = (float*)d_out;

    float* xn  = sym_addr(g_xn);
    float* qb_ = sym_addr(g_q);
    float* kb_ = sym_addr(g_k);
    float* vb_ = sym_addr(g_v);
    float* ob_ = sym_addr(g_o);
    float* x1  = sym_addr(g_x1);
    float* hid = sym_addr(g_hid);
    float* hdn = sym_addr(g_hdn);

    const float qscale = 0.17677669529663687f;  // 1/sqrt(32)

    // 1) LN1
    ln_kernel<<<L / 8, 256>>>(x, n1g, n1b, xn);
    // 2) q = (xn @ q_w + q_b) * scale        [tf32 tensor cores]
    gemm_mma<0><<<dim3(C / 64, L / 128), 256>>>(xn, q_w, q_b, nullptr, qb_, L, C, C, qscale);
    // 3) kv projection + permuted scatter
    kvproj_kernel<<<L / 16, 192>>>(xn, kv_w, kv_b, kb_, vb_);
    // 4) windowed attention with relative position bias
    attn_kernel<<<NWIN * NHD, 256>>>(qb_, kb_, vb_, btab, ob_);
    // 5) x1 = x + o @ proj_w + proj_b        [tf32 tensor cores]
    gemm_mma<1><<<dim3(C / 64, L / 128), 256>>>(ob_, p_w, p_b, x, x1, L, C, C, 1.f);
    // 6) LN2
    ln_kernel<<<L / 8, 256>>>(x1, n2g, n2b, xn);
    // 7) hid = gelu(xn @ fc1_w + fc1_b)      [tf32 tensor cores]
    gemm_mma<2><<<dim3(HID / 64, L / 128), 256>>>(xn, f1w, f1b, nullptr, hid, L, HID, C, 1.f);
    // 8) hdn = hid + gelu(dwconv(hid) + dw_b)
    dwconv_kernel<<<(DD * HHH * WWW) / 4, 192>>>(hid, dww, dwb, hdn);
    // 9) out = x1 + hdn @ fc2_w + fc2_b      [tf32 tensor cores]
    gemm_mma<1><<<dim3(C / 64, L / 128), 256>>>(hdn, f2w, f2b, x1, out, L, C, HID, 1.f);
}

// round 3
// speedup vs baseline: 2.0865x; 1.3073x over previous
#include <cuda_runtime.h>
#include <math.h>

// ---------------- problem constants (fixed by the dataset) ----------------
#define L     131072        // tokens = 32*64*64
#define C     192           // dim
#define NHD   6             // heads
#define HD    32            // head dim
#define NWIN  256           // 4*8*8 windows of 8^3
#define NP    64            // pooled kv tokens per window (4^3)
#define HID   768           // ffn hidden
#define DD    32
#define HHH   64
#define WWW   64

// ---------------- scratch (device globals: allocation-free) ----------------
__device__ float g_xn[L * C];
__device__ float g_q [L * C];
__device__ float g_k [NWIN * NHD * NP * HD];
__device__ float g_v [NWIN * NHD * NP * HD];
__device__ float g_o [L * C];
__device__ float g_x1[L * C];
__device__ float g_hid[L * HID];
__device__ float g_hdn[L * HID];

__device__ __forceinline__ float gelu_f(float v) {
    return 0.5f * v * (1.0f + erff(v * 0.70710678118654752f));
}

__device__ __forceinline__ unsigned f2tf32(float f) {
    unsigned u;
    asm("cvt.rna.tf32.f32 %0, %1;" : "=r"(u) : "f"(f));
    return u;
}

__device__ __forceinline__ void mma_tf32(float* d, const unsigned* a, const unsigned* b) {
    asm volatile(
        "mma.sync.aligned.m16n8k8.row.col.f32.tf32.tf32.f32 "
        "{%0,%1,%2,%3},{%4,%5,%6,%7},{%8,%9},{%0,%1,%2,%3};"
        : "+f"(d[0]), "+f"(d[1]), "+f"(d[2]), "+f"(d[3])
        : "r"(a[0]), "r"(a[1]), "r"(a[2]), "r"(a[3]), "r"(b[0]), "r"(b[1]));
}

// ---------------- LayerNorm: one warp per token (192 elems) ----------------
__global__ void ln_kernel(const float* __restrict__ x, const float* __restrict__ g,
                          const float* __restrict__ b, float* __restrict__ y)
{
    int lane = threadIdx.x & 31;
    int wi   = threadIdx.x >> 5;
    int l    = blockIdx.x * 8 + wi;
    const float* row = x + (size_t)l * C;
    float v[6];
    float s = 0.f, ss = 0.f;
#pragma unroll
    for (int i = 0; i < 6; i++) {
        v[i] = row[lane + 32 * i];
        s  += v[i];
        ss += v[i] * v[i];
    }
#pragma unroll
    for (int off = 16; off > 0; off >>= 1) {
        s  += __shfl_xor_sync(0xffffffffu, s,  off);
        ss += __shfl_xor_sync(0xffffffffu, ss, off);
    }
    float mean = s * (1.0f / C);
    float var  = ss * (1.0f / C) - mean * mean;
    float inv  = rsqrtf(var + 1e-5f);
    float* yr = y + (size_t)l * C;
#pragma unroll
    for (int i = 0; i < 6; i++) {
        int c = lane + 32 * i;
        yr[c] = (v[i] - mean) * inv * g[c] + b[c];
    }
}

// ---------------- tf32 tensor-core GEMM: 128x64x16, 256 thr ---------------
template <int EPI>
__global__ void __launch_bounds__(256)
gemm_mma(const float* __restrict__ A, const float* __restrict__ Bm,
         const float* __restrict__ bias, const float* __restrict__ res,
         float* __restrict__ Cm, int M, int N, int K, float scale)
{
    __shared__ unsigned As[16][136];
    __shared__ unsigned Bs[16][72];

    const int tid  = threadIdx.x;
    const int lane = tid & 31, warp = tid >> 5;
    const int wm = warp & 3, wn = warp >> 2;
    const int row0 = blockIdx.y * 128, col0 = blockIdx.x * 64;

    float acc[2][4][4];
#pragma unroll
    for (int i = 0; i < 2; i++)
#pragma unroll
        for (int j = 0; j < 4; j++)
#pragma unroll
            for (int t = 0; t < 4; t++) acc[i][j][t] = 0.f;

    const int a_row = tid >> 2;
    const int a_kc  = (tid & 3) * 4;
    const int b_row = tid >> 4, b_c4 = (tid & 15) * 4;

    for (int kt = 0; kt < K; kt += 16) {
#pragma unroll
        for (int i = 0; i < 2; i++) {
            int r = a_row + i * 64;
            float4 v = *(const float4*)(A + (size_t)(row0 + r) * K + kt + a_kc);
            As[a_kc + 0][r] = f2tf32(v.x);
            As[a_kc + 1][r] = f2tf32(v.y);
            As[a_kc + 2][r] = f2tf32(v.z);
            As[a_kc + 3][r] = f2tf32(v.w);
        }
        {
            float4 v = *(const float4*)(Bm + (size_t)(kt + b_row) * N + col0 + b_c4);
            uint4 u = make_uint4(f2tf32(v.x), f2tf32(v.y), f2tf32(v.z), f2tf32(v.w));
            *(uint4*)&Bs[b_row][b_c4] = u;
        }
        __syncthreads();

#pragma unroll
        for (int ks = 0; ks < 16; ks += 8) {
            unsigned af[2][4], bf[4][2];
            const int k0 = ks + (lane & 3);
            const int rb = wm * 32 + (lane >> 2);
#pragma unroll
            for (int mi = 0; mi < 2; mi++) {
                int r = rb + mi * 16;
                af[mi][0] = As[k0][r];
                af[mi][1] = As[k0][r + 8];
                af[mi][2] = As[k0 + 4][r];
                af[mi][3] = As[k0 + 4][r + 8];
            }
            const int cb = wn * 32 + (lane >> 2);
#pragma unroll
            for (int ni = 0; ni < 4; ni++) {
                bf[ni][0] = Bs[k0][cb + ni * 8];
                bf[ni][1] = Bs[k0 + 4][cb + ni * 8];
            }
#pragma unroll
            for (int mi = 0; mi < 2; mi++)
#pragma unroll
                for (int ni = 0; ni < 4; ni++)
                    mma_tf32(acc[mi][ni], af[mi], bf[ni]);
        }
        __syncthreads();
    }

    const int crow = row0 + wm * 32 + (lane >> 2);
    const int ccol = col0 + wn * 32 + (lane & 3) * 2;
#pragma unroll
    for (int mi = 0; mi < 2; mi++) {
#pragma unroll
        for (int half = 0; half < 2; half++) {
            int row = crow + mi * 16 + half * 8;
#pragma unroll
            for (int ni = 0; ni < 4; ni++) {
                int col = ccol + ni * 8;
                float v0 = acc[mi][ni][half * 2 + 0] + bias[col];
                float v1 = acc[mi][ni][half * 2 + 1] + bias[col + 1];
                if (EPI == 0)      { v0 *= scale; v1 *= scale; }
                else if (EPI == 1) {
                    float2 rv = *(const float2*)(res + (size_t)row * N + col);
                    v0 += rv.x; v1 += rv.y;
                } else             { v0 = gelu_f(v0); v1 = gelu_f(v1); }
                *(float2*)(Cm + (size_t)row * N + col) = make_float2(v0, v1);
            }
        }
    }
}

// ---------------- KV projection + scatter into pooled window layout --------
__global__ void kvproj_kernel(const float* __restrict__ xn, const float* __restrict__ kvw,
                              const float* __restrict__ kvb,
                              float* __restrict__ ko, float* __restrict__ vo)
{
    __shared__ float sx[16][193];
    const int tid  = threadIdx.x;
    const int base = blockIdx.x * 16;
#pragma unroll
    for (int i = 0; i < 16; i++) sx[i][tid] = xn[(size_t)(base + i) * C + tid];
    __syncthreads();

    const int t  = tid / 12;
    const int jg = tid % 12;
    float4 bb = *(const float4*)(kvb + jg * 4);
    float s0 = bb.x, s1 = bb.y, s2 = bb.z, s3 = bb.w;
#pragma unroll 8
    for (int c = 0; c < C; c++) {
        float xv = sx[t][c];
        float4 w4 = *(const float4*)(kvw + c * 48 + jg * 4);
        s0 += xv * w4.x; s1 += xv * w4.y; s2 += xv * w4.z; s3 += xv * w4.w;
    }
    int l  = base + t;
    int z  = l >> 12, y = (l >> 6) & 63, x = l & 63;
    int win = ((z >> 3) << 6) | ((y >> 3) << 3) | (x >> 3);
    int zz = z & 7, yy = y & 7, xx = x & 7;
    int m   = ((zz >> 1) << 4) | ((yy >> 1) << 2) | (xx >> 1);
    int sub = ((zz & 1) << 2)  | ((yy & 1) << 1)  | (xx & 1);
    int head = jg % 6;
    float* dst = (jg < 6) ? ko : vo;
    *(float4*)&dst[(((size_t)(win * NHD + head)) * NP + m) * HD + sub * 4] =
        make_float4(s0, s1, s2, s3);
}

// ---------------- attention via tensor cores: block = (window, head) -------
// S = Q(512x32) @ K^T, +bias, softmax, O = P @ V(64x32).
// 8 warps, each owns m16; 4 passes of 128 queries.
// smem strides chosen so every fragment LDS hits 32 distinct banks.
#define ATTN_SMEM_WORDS (64*36 + 32*68 + 128*36 + 8*16*68 + 343)
__global__ void __launch_bounds__(256)
attn_mma_kernel(const float* __restrict__ q, const float* __restrict__ kbuf,
                const float* __restrict__ vbuf, const float* __restrict__ btab,
                float* __restrict__ o)
{
    extern __shared__ unsigned sm[];
    unsigned* Ks = sm;                    // [64][36]  K, (m,c)
    unsigned* Vt = Ks + 64 * 36;          // [32][68]  V^T, (c,m)
    unsigned* Qs = Vt + 32 * 68;          // [128][36] Q chunk
    unsigned* Pw = Qs + 128 * 36;         // [8][16][68] per-warp P
    float*    bt = (float*)(Pw + 8 * 16 * 68);  // [343]

    const int win  = blockIdx.x / NHD;
    const int head = blockIdx.x % NHD;
    const int tid = threadIdx.x, lane = tid & 31, w = tid >> 5;
    const int rq = lane >> 2, tq = lane & 3;

    const float* kb = kbuf + (size_t)(win * NHD + head) * NP * HD;
    const float* vb = vbuf + (size_t)(win * NHD + head) * NP * HD;
    for (int i = tid; i < NP * HD; i += 256) {
        int m = i >> 5, c = i & 31;
        Ks[m * 36 + c] = f2tf32(kb[i]);
    }
    for (int i = tid; i < NP * HD; i += 256) {
        int c = i >> 6, m = i & 63;
        Vt[c * 68 + m] = f2tf32(vb[m * 32 + c]);
    }
    for (int i = tid; i < 343; i += 256) bt[i] = btab[i * NHD + head];

    const int wz = win >> 6, wy = (win >> 3) & 7, wx = win & 7;
    const int wbase = wz * 32768 + wy * 512 + wx * 8;
    unsigned* Pme = Pw + w * 16 * 68;

#pragma unroll 1
    for (int p = 0; p < 4; p++) {
        __syncthreads();   // prior pass done with Qs (covers K/V/bt on p==0)
        // ---- load Q chunk 128x32 (gathered by window token order) ----
#pragma unroll
        for (int i = 0; i < 4; i++) {
            int idx = tid + i * 256;           // 0..1023 float4 slots
            int r = idx >> 3, c4 = (idx & 7) * 4;
            int n = p * 128 + r;
            int l = wbase + (n >> 6) * 4096 + ((n >> 3) & 7) * 64 + (n & 7);
            float4 v4 = *(const float4*)(q + (size_t)l * C + head * HD + c4);
            Qs[r * 36 + c4 + 0] = f2tf32(v4.x);
            Qs[r * 36 + c4 + 1] = f2tf32(v4.y);
            Qs[r * 36 + c4 + 2] = f2tf32(v4.z);
            Qs[r * 36 + c4 + 3] = f2tf32(v4.w);
        }
        __syncthreads();

        // ---- S = Qw(16x32) @ K^T(32x64) ----
        float s[8][4];
#pragma unroll
        for (int j = 0; j < 8; j++)
#pragma unroll
            for (int t = 0; t < 4; t++) s[j][t] = 0.f;

        const unsigned* Qrow = Qs + (w * 16 + rq) * 36;
#pragma unroll
        for (int kb0 = 0; kb0 < 32; kb0 += 8) {
            unsigned a[4];
            a[0] = Qrow[kb0 + tq];
            a[1] = Qrow[8 * 36 + kb0 + tq];
            a[2] = Qrow[kb0 + tq + 4];
            a[3] = Qrow[8 * 36 + kb0 + tq + 4];
#pragma unroll
            for (int j = 0; j < 8; j++) {
                unsigned b[2];
                const unsigned* Kr = Ks + (j * 8 + rq) * 36 + kb0 + tq;
                b[0] = Kr[0];
                b[1] = Kr[4];
                mma_tf32(s[j], a, b);
            }
        }

        // ---- relative position bias + softmax (rows n0, n1 = n0+8) ----
        const int n0 = p * 128 + w * 16 + rq;
        const int n1 = n0 + 8;
        int qb0, qb1;
        {
            int zz = n0 >> 6, yy = (n0 >> 3) & 7, xx = n0 & 7;
            qb0 = ((zz >> 1) + 3) * 49 + ((yy >> 1) + 3) * 7 + (xx >> 1) + 3;
            zz = n1 >> 6; yy = (n1 >> 3) & 7; xx = n1 & 7;
            qb1 = ((zz >> 1) + 3) * 49 + ((yy >> 1) + 3) * 7 + (xx >> 1) + 3;
        }
        float mx0 = -1e30f, mx1 = -1e30f;
#pragma unroll
        for (int j = 0; j < 8; j++) {
#pragma unroll
            for (int s2 = 0; s2 < 2; s2++) {
                int m = j * 8 + tq * 2 + s2;
                int koff = (m >> 4) * 49 + ((m >> 2) & 3) * 7 + (m & 3);
                s[j][s2]     += bt[qb0 - koff];
                s[j][2 + s2] += bt[qb1 - koff];
                mx0 = fmaxf(mx0, s[j][s2]);
                mx1 = fmaxf(mx1, s[j][2 + s2]);
            }
        }
        mx0 = fmaxf(mx0, __shfl_xor_sync(0xffffffffu, mx0, 1));
        mx0 = fmaxf(mx0, __shfl_xor_sync(0xffffffffu, mx0, 2));
        mx1 = fmaxf(mx1, __shfl_xor_sync(0xffffffffu, mx1, 1));
        mx1 = fmaxf(mx1, __shfl_xor_sync(0xffffffffu, mx1, 2));
        float sum0 = 0.f, sum1 = 0.f;
#pragma unroll
        for (int j = 0; j < 8; j++) {
#pragma unroll
            for (int s2 = 0; s2 < 2; s2++) {
                s[j][s2]     = __expf(s[j][s2]     - mx0);
                s[j][2 + s2] = __expf(s[j][2 + s2] - mx1);
                sum0 += s[j][s2];
                sum1 += s[j][2 + s2];
            }
        }
        sum0 += __shfl_xor_sync(0xffffffffu, sum0, 1);
        sum0 += __shfl_xor_sync(0xffffffffu, sum0, 2);
        sum1 += __shfl_xor_sync(0xffffffffu, sum1, 1);
        sum1 += __shfl_xor_sync(0xffffffffu, sum1, 2);
        const float inv0 = 1.0f / sum0, inv1 = 1.0f / sum1;

        // ---- P -> per-warp smem (tf32), re-fragment as A ----
#pragma unroll
        for (int j = 0; j < 8; j++) {
#pragma unroll
            for (int s2 = 0; s2 < 2; s2++) {
                int m = j * 8 + tq * 2 + s2;
                Pme[rq * 68 + m]       = f2tf32(s[j][s2] * inv0);
                Pme[(rq + 8) * 68 + m] = f2tf32(s[j][2 + s2] * inv1);
            }
        }
        __syncwarp();

        // ---- O = P(16x64) @ V(64x32) ----
        float oa[4][4];
#pragma unroll
        for (int j = 0; j < 4; j++)
#pragma unroll
            for (int t = 0; t < 4; t++) oa[j][t] = 0.f;

        const unsigned* Prow = Pme + rq * 68;
#pragma unroll
        for (int kb0 = 0; kb0 < 64; kb0 += 8) {
            unsigned a[4];
            a[0] = Prow[kb0 + tq];
            a[1] = Prow[8 * 68 + kb0 + tq];
            a[2] = Prow[kb0 + tq + 4];
            a[3] = Prow[8 * 68 + kb0 + tq + 4];
#pragma unroll
            for (int jn = 0; jn < 4; jn++) {
                unsigned b[2];
                const unsigned* Vr = Vt + (jn * 8 + rq) * 68 + kb0 + tq;
                b[0] = Vr[0];
                b[1] = Vr[4];
                mma_tf32(oa[jn], a, b);
            }
        }

        // ---- write O ----
        const int l0 = wbase + (n0 >> 6) * 4096 + ((n0 >> 3) & 7) * 64 + (n0 & 7);
        const int l1 = wbase + (n1 >> 6) * 4096 + ((n1 >> 3) & 7) * 64 + (n1 & 7);
        float* o0 = o + (size_t)l0 * C + head * HD + tq * 2;
        float* o1 = o + (size_t)l1 * C + head * HD + tq * 2;
#pragma unroll
        for (int jn = 0; jn < 4; jn++) {
            *(float2*)(o0 + jn * 8) = make_float2(oa[jn][0], oa[jn][1]);
            *(float2*)(o1 + jn * 8) = make_float2(oa[jn][2], oa[jn][3]);
        }
    }
}

// ---------------- depthwise 3x3x3 conv + gelu + residual-add ---------------
__global__ void dwconv_kernel(const float* __restrict__ hid, const float* __restrict__ wgt,
                              const float* __restrict__ bias, float* __restrict__ hdn)
{
    const int c4  = threadIdx.x;
    const int bid = blockIdx.x;
    const int x0  = (bid & 15) * 4;
    const int y   = (bid >> 4) & 63;
    const int z   = bid >> 10;

    float4 acc[4];
#pragma unroll
    for (int i = 0; i < 4; i++) acc[i] = make_float4(0.f, 0.f, 0.f, 0.f);

    for (int kd = 0; kd < 3; kd++) {
        int zz = z + kd - 1;
        if (zz < 0 || zz >= DD) continue;
        for (int kh = 0; kh < 3; kh++) {
            int yy = y + kh - 1;
            if (yy < 0 || yy >= HHH) continue;
            const float* base = hid + ((size_t)(zz * HHH + yy) * WWW) * HID + c4 * 4;
            float4 hv[6];
#pragma unroll
            for (int i = 0; i < 6; i++) {
                int xx = x0 - 1 + i;
                hv[i] = (xx >= 0 && xx < WWW) ? *(const float4*)(base + (size_t)xx * HID)
                                              : make_float4(0.f, 0.f, 0.f, 0.f);
            }
#pragma unroll
            for (int kw = 0; kw < 3; kw++) {
                float4 wv = *(const float4*)(wgt + ((kd * 3 + kh) * 3 + kw) * HID + c4 * 4);
#pragma unroll
                for (int xi = 0; xi < 4; xi++) {
                    acc[xi].x += hv[xi + kw].x * wv.x;
                    acc[xi].y += hv[xi + kw].y * wv.y;
                    acc[xi].z += hv[xi + kw].z * wv.z;
                    acc[xi].w += hv[xi + kw].w * wv.w;
                }
            }
        }
    }
    float4 bv = *(const float4*)(bias + c4 * 4);
#pragma unroll
    for (int xi = 0; xi < 4; xi++) {
        size_t idx = ((size_t)((z * HHH + y) * WWW + x0 + xi)) * HID + c4 * 4;
        float4 h0 = *(const float4*)(hid + idx);
        float4 o;
        o.x = h0.x + gelu_f(acc[xi].x + bv.x);
        o.y = h0.y + gelu_f(acc[xi].y + bv.y);
        o.z = h0.z + gelu_f(acc[xi].z + bv.z);
        o.w = h0.w + gelu_f(acc[xi].w + bv.w);
        *(float4*)&hdn[idx] = o;
    }
}

// ---------------- launch ----------------------------------------------------
static float* sym_addr(const void* sym) {
    void* p = nullptr;
    cudaGetSymbolAddress(&p, sym);
    return (float*)p;
}

extern "C" void kernel_launch(void* const* d_in, const int* in_sizes, int n_in,
                              void* d_out, int out_size)
{
    const float* x    = (const float*)d_in[0];
    const float* n1g  = (const float*)d_in[1];
    const float* n1b  = (const float*)d_in[2];
    const float* q_w  = (const float*)d_in[3];
    const float* q_b  = (const float*)d_in[4];
    const float* kv_w = (const float*)d_in[5];
    const float* kv_b = (const float*)d_in[6];
    const float* btab = (const float*)d_in[7];
    const float* p_w  = (const float*)d_in[8];
    const float* p_b  = (const float*)d_in[9];
    const float* n2g  = (const float*)d_in[10];
    const float* n2b  = (const float*)d_in[11];
    const float* f1w  = (const float*)d_in[12];
    const float* f1b  = (const float*)d_in[13];
    const float* dww  = (const float*)d_in[14];
    const float* dwb  = (const float*)d_in[15];
    const float* f2w  = (const float*)d_in[16];
    const float* f2b  = (const float*)d_in[17];
    float* out = (float*)d_out;

    float* xn  = sym_addr(g_xn);
    float* qb_ = sym_addr(g_q);
    float* kb_ = sym_addr(g_k);
    float* vb_ = sym_addr(g_v);
    float* ob_ = sym_addr(g_o);
    float* x1  = sym_addr(g_x1);
    float* hid = sym_addr(g_hid);
    float* hdn = sym_addr(g_hdn);

    const float qscale = 0.17677669529663687f;  // 1/sqrt(32)
    const int attn_smem = ATTN_SMEM_WORDS * 4;  // ~72.5 KB
    static int smem_set = 0;
    if (!smem_set) {
        cudaFuncSetAttribute(attn_mma_kernel,
                             cudaFuncAttributeMaxDynamicSharedMemorySize, attn_smem);
        smem_set = 1;
    }

    // 1) LN1
    ln_kernel<<<L / 8, 256>>>(x, n1g, n1b, xn);
    // 2) q = (xn @ q_w + q_b) * scale        [tf32 mma]
    gemm_mma<0><<<dim3(C / 64, L / 128), 256>>>(xn, q_w, q_b, nullptr, qb_, L, C, C, qscale);
    // 3) kv projection + permuted scatter
    kvproj_kernel<<<L / 16, 192>>>(xn, kv_w, kv_b, kb_, vb_);
    // 4) windowed attention                  [tf32 mma]
    attn_mma_kernel<<<NWIN * NHD, 256, attn_smem>>>(qb_, kb_, vb_, btab, ob_);
    // 5) x1 = x + o @ proj_w + proj_b        [tf32 mma]
    gemm_mma<1><<<dim3(C / 64, L / 128), 256>>>(ob_, p_w, p_b, x, x1, L, C, C, 1.f);
    // 6) LN2
    ln_kernel<<<L / 8, 256>>>(x1, n2g, n2b, xn);
    // 7) hid = gelu(xn @ fc1_w + fc1_b)      [tf32 mma]
    gemm_mma<2><<<dim3(HID / 64, L / 128), 256>>>(xn, f1w, f1b, nullptr, hid, L, HID, C, 1.f);
    // 8) hdn = hid + gelu(dwconv(hid) + dw_b)
    dwconv_kernel<<<(DD * HHH * WWW) / 4, 192>>>(hid, dww, dwb, hdn);
    // 9) out = x1 + hdn @ fc2_w + fc2_b      [tf32 mma]
    gemm_mma<1><<<dim3(C / 64, L / 128), 256>>>(hdn, f2w, f2b, x1, out, L, C, HID, 1.f);
}

// round 4
// speedup vs baseline: 2.6222x; 1.2568x over previous
#include <cuda_runtime.h>
#include <math.h>

// ---------------- problem constants (fixed by the dataset) ----------------
#define L     131072        // tokens = 32*64*64
#define C     192           // dim
#define NHD   6             // heads
#define HD    32            // head dim
#define NWIN  256           // 4*8*8 windows of 8^3
#define NP    64            // pooled kv tokens per window (4^3)
#define HID   768           // ffn hidden
#define DD    32
#define HHH   64
#define WWW   64

// ---------------- scratch (device globals: allocation-free) ----------------
__device__ float g_xn[L * C];
__device__ float g_q [L * C];
__device__ float g_k [NWIN * NHD * NP * HD];
__device__ float g_v [NWIN * NHD * NP * HD];
__device__ float g_o [L * C];
__device__ float g_x1[L * C];
__device__ float g_hid[L * HID];
__device__ float g_hdn[L * HID];

__device__ __forceinline__ float gelu_f(float v) {
    return 0.5f * v * (1.0f + erff(v * 0.70710678118654752f));
}

__device__ __forceinline__ void mma_tf32(float* d, const unsigned* a, const unsigned* b) {
    asm volatile(
        "mma.sync.aligned.m16n8k8.row.col.f32.tf32.tf32.f32 "
        "{%0,%1,%2,%3},{%4,%5,%6,%7},{%8,%9},{%0,%1,%2,%3};"
        : "+f"(d[0]), "+f"(d[1]), "+f"(d[2]), "+f"(d[3])
        : "r"(a[0]), "r"(a[1]), "r"(a[2]), "r"(a[3]), "r"(b[0]), "r"(b[1]));
}

#define CP16(dst_smem_u32, src_ptr) \
    asm volatile("cp.async.cg.shared.global [%0], [%1], 16;\n" \
                 :: "r"(dst_smem_u32), "l"(src_ptr))
#define CP_COMMIT() asm volatile("cp.async.commit_group;\n" ::: "memory")
#define CP_WAIT1()  asm volatile("cp.async.wait_group 1;\n" ::: "memory")
#define CP_WAIT0()  asm volatile("cp.async.wait_group 0;\n" ::: "memory")

// ---------------- LayerNorm: one warp per token (192 elems) ----------------
__global__ void ln_kernel(const float* __restrict__ x, const float* __restrict__ g,
                          const float* __restrict__ b, float* __restrict__ y)
{
    int lane = threadIdx.x & 31;
    int wi   = threadIdx.x >> 5;
    int l    = blockIdx.x * 8 + wi;
    const float* row = x + (size_t)l * C;
    float v[6];
    float s = 0.f, ss = 0.f;
#pragma unroll
    for (int i = 0; i < 6; i++) {
        v[i] = row[lane + 32 * i];
        s  += v[i];
        ss += v[i] * v[i];
    }
#pragma unroll
    for (int off = 16; off > 0; off >>= 1) {
        s  += __shfl_xor_sync(0xffffffffu, s,  off);
        ss += __shfl_xor_sync(0xffffffffu, ss, off);
    }
    float mean = s * (1.0f / C);
    float var  = ss * (1.0f / C) - mean * mean;
    float inv  = rsqrtf(var + 1e-5f);
    float* yr = y + (size_t)l * C;
#pragma unroll
    for (int i = 0; i < 6; i++) {
        int c = lane + 32 * i;
        yr[c] = (v[i] - mean) * inv * g[c] + b[c];
    }
}

// -------- tf32 GEMM: 128x64 tile, k-step 32, cp.async double buffer --------
// A raw fp32 bits fed as tf32 (truncation). smem strides: A row 36w, B row 72w
// -> all fragment LDS conflict-free. Dynamic smem: 2*(128*36 + 32*72) floats.
#define GEMM_SMEM_BYTES ((2 * (128 * 36 + 32 * 72)) * 4)
template <int EPI>
__global__ void __launch_bounds__(256)
gemm_mma(const float* __restrict__ A, const float* __restrict__ Bm,
         const float* __restrict__ bias, const float* __restrict__ res,
         float* __restrict__ Cm, int M, int N, int K, float scale)
{
    extern __shared__ float gsm[];
    float* As = gsm;                       // [2][128][36]
    float* Bs = gsm + 2 * 128 * 36;        // [2][32][72]

    const int tid  = threadIdx.x;
    const int lane = tid & 31, warp = tid >> 5;
    const int wm = warp & 3, wn = warp >> 2;
    const int row0 = blockIdx.y * 128, col0 = blockIdx.x * 64;

    float acc[2][4][4];
#pragma unroll
    for (int i = 0; i < 2; i++)
#pragma unroll
        for (int j = 0; j < 4; j++)
#pragma unroll
            for (int t = 0; t < 4; t++) acc[i][j][t] = 0.f;

    // async-load mapping
    const int a_r  = tid >> 1;                 // rows: 2 chunks per row half
    const int a_k4 = (tid & 1) * 16;           // +0 / +16 ; 2 iters cover +0..28
    const int b_kr = tid >> 4, b_c4 = (tid & 15) * 4;

    const float* Abase = A + (size_t)(row0 + a_r) * K + a_k4;
    const float* Bbase = Bm + (size_t)b_kr * N + col0 + b_c4;

    const unsigned sA = (unsigned)__cvta_generic_to_shared(As);
    const unsigned sB = (unsigned)__cvta_generic_to_shared(Bs);

    const int ntiles = K >> 5;

    // load_tile(kt, stage)
    auto load_tile = [&](int kt, int st) {
        unsigned aOff = sA + (unsigned)(st * 128 * 36) * 4;
        // A: 128 rows x 32 k : thread covers (a_r, a_k4..a_k4+3w) and (+ 16w shifted by 8w? )
        // chunks: each thread does 4 x 16B: rows a_r, a_r+? -> simpler: 1024 chunks of 16B
#pragma unroll
        for (int i = 0; i < 2; i++) {
            // chunk index = tid*2 + i spread as: row = a_r, kword = a_k4 + i*? no:
            // use flat id: id = tid + i*256 -> covers 512; need 1024/2? recompute below
            ;
        }
        // A: 128*32 words = 1024 x 16B chunks; 256 threads x 4
#pragma unroll
        for (int i = 0; i < 4; i++) {
            int id = tid + i * 256;
            int r = id >> 3, kc = (id & 7) * 4;
            CP16(aOff + (unsigned)(r * 36 + kc) * 4,
                 A + (size_t)(row0 + r) * K + kt + kc);
        }
        // B: 32*64 words = 512 chunks; 256 threads x 2
        unsigned bOff = sB + (unsigned)(st * 32 * 72) * 4;
#pragma unroll
        for (int i = 0; i < 2; i++) {
            int id = tid + i * 256;
            int kr = id >> 4, c4 = (id & 15) * 4;
            CP16(bOff + (unsigned)(kr * 72 + c4) * 4,
                 Bm + (size_t)(kt + kr) * N + col0 + c4);
        }
        CP_COMMIT();
    };

    load_tile(0, 0);

    const int rb = wm * 32 + (lane >> 2);
    const int cb = wn * 32 + (lane >> 2);
    const int tq = lane & 3;

    for (int t = 0; t < ntiles; t++) {
        if (t + 1 < ntiles) { load_tile((t + 1) << 5, (t + 1) & 1); CP_WAIT1(); }
        else                { CP_WAIT0(); }
        __syncthreads();

        const float* Ast = As + (t & 1) * 128 * 36;
        const float* Bst = Bs + (t & 1) * 32 * 72;
#pragma unroll
        for (int ks = 0; ks < 32; ks += 8) {
            unsigned af[2][4], bf[4][2];
            const int k0 = ks + tq;
#pragma unroll
            for (int mi = 0; mi < 2; mi++) {
                const float* Ar = Ast + (rb + mi * 16) * 36;
                af[mi][0] = __float_as_uint(Ar[k0]);
                af[mi][1] = __float_as_uint(Ar[8 * 36 + k0]);
                af[mi][2] = __float_as_uint(Ar[k0 + 4]);
                af[mi][3] = __float_as_uint(Ar[8 * 36 + k0 + 4]);
            }
#pragma unroll
            for (int ni = 0; ni < 4; ni++) {
                bf[ni][0] = __float_as_uint(Bst[k0 * 72 + cb + ni * 8]);
                bf[ni][1] = __float_as_uint(Bst[(k0 + 4) * 72 + cb + ni * 8]);
            }
#pragma unroll
            for (int mi = 0; mi < 2; mi++)
#pragma unroll
                for (int ni = 0; ni < 4; ni++)
                    mma_tf32(acc[mi][ni], af[mi], bf[ni]);
        }
        __syncthreads();
    }

    const int crow = row0 + wm * 32 + (lane >> 2);
    const int ccol = col0 + wn * 32 + (lane & 3) * 2;
#pragma unroll
    for (int mi = 0; mi < 2; mi++) {
#pragma unroll
        for (int half = 0; half < 2; half++) {
            int row = crow + mi * 16 + half * 8;
#pragma unroll
            for (int ni = 0; ni < 4; ni++) {
                int col = ccol + ni * 8;
                float v0 = acc[mi][ni][half * 2 + 0] + bias[col];
                float v1 = acc[mi][ni][half * 2 + 1] + bias[col + 1];
                if (EPI == 0)      { v0 *= scale; v1 *= scale; }
                else if (EPI == 1) {
                    float2 rv = *(const float2*)(res + (size_t)row * N + col);
                    v0 += rv.x; v1 += rv.y;
                } else             { v0 = gelu_f(v0); v1 = gelu_f(v1); }
                *(float2*)(Cm + (size_t)row * N + col) = make_float2(v0, v1);
            }
        }
    }
}

// ---------------- KV projection + scatter into pooled window layout --------
__global__ void kvproj_kernel(const float* __restrict__ xn, const float* __restrict__ kvw,
                              const float* __restrict__ kvb,
                              float* __restrict__ ko, float* __restrict__ vo)
{
    __shared__ float sx[16][193];
    const int tid  = threadIdx.x;
    const int base = blockIdx.x * 16;
#pragma unroll
    for (int i = 0; i < 16; i++) sx[i][tid] = xn[(size_t)(base + i) * C + tid];
    __syncthreads();

    const int t  = tid / 12;
    const int jg = tid % 12;
    float4 bb = *(const float4*)(kvb + jg * 4);
    float s0 = bb.x, s1 = bb.y, s2 = bb.z, s3 = bb.w;
#pragma unroll 8
    for (int c = 0; c < C; c++) {
        float xv = sx[t][c];
        float4 w4 = *(const float4*)(kvw + c * 48 + jg * 4);
        s0 += xv * w4.x; s1 += xv * w4.y; s2 += xv * w4.z; s3 += xv * w4.w;
    }
    int l  = base + t;
    int z  = l >> 12, y = (l >> 6) & 63, x = l & 63;
    int win = ((z >> 3) << 6) | ((y >> 3) << 3) | (x >> 3);
    int zz = z & 7, yy = y & 7, xx = x & 7;
    int m   = ((zz >> 1) << 4) | ((yy >> 1) << 2) | (xx >> 1);
    int sub = ((zz & 1) << 2)  | ((yy & 1) << 1)  | (xx & 1);
    int head = jg % 6;
    float* dst = (jg < 6) ? ko : vo;
    *(float4*)&dst[(((size_t)(win * NHD + head)) * NP + m) * HD + sub * 4] =
        make_float4(s0, s1, s2, s3);
}

// ---------------- attention via tensor cores: block = (window, head) -------
#define ATTN_SMEM_WORDS (64*36 + 32*68 + 128*36 + 8*16*68 + 343)
__global__ void __launch_bounds__(256)
attn_mma_kernel(const float* __restrict__ q, const float* __restrict__ kbuf,
                const float* __restrict__ vbuf, const float* __restrict__ btab,
                float* __restrict__ o)
{
    extern __shared__ unsigned sm[];
    unsigned* Ks = sm;                    // [64][36]  K, (m,c)
    unsigned* Vt = Ks + 64 * 36;          // [32][68]  V^T, (c,m)
    unsigned* Qs = Vt + 32 * 68;          // [128][36] Q chunk
    unsigned* Pw = Qs + 128 * 36;         // [8][16][68] per-warp P
    float*    bt = (float*)(Pw + 8 * 16 * 68);  // [343]

    const int win  = blockIdx.x / NHD;
    const int head = blockIdx.x % NHD;
    const int tid = threadIdx.x, lane = tid & 31, w = tid >> 5;
    const int rq = lane >> 2, tq = lane & 3;

    const float* kb = kbuf + (size_t)(win * NHD + head) * NP * HD;
    const float* vb = vbuf + (size_t)(win * NHD + head) * NP * HD;
    for (int i = tid; i < NP * HD; i += 256) {
        int m = i >> 5, c = i & 31;
        Ks[m * 36 + c] = __float_as_uint(kb[i]);
    }
    for (int i = tid; i < NP * HD; i += 256) {
        int c = i >> 6, m = i & 63;
        Vt[c * 68 + m] = __float_as_uint(vb[m * 32 + c]);
    }
    for (int i = tid; i < 343; i += 256) bt[i] = btab[i * NHD + head];

    const int wz = win >> 6, wy = (win >> 3) & 7, wx = win & 7;
    const int wbase = wz * 32768 + wy * 512 + wx * 8;
    unsigned* Pme = Pw + w * 16 * 68;

#pragma unroll 1
    for (int p = 0; p < 4; p++) {
        __syncthreads();
#pragma unroll
        for (int i = 0; i < 4; i++) {
            int idx = tid + i * 256;
            int r = idx >> 3, c4 = (idx & 7) * 4;
            int n = p * 128 + r;
            int l = wbase + (n >> 6) * 4096 + ((n >> 3) & 7) * 64 + (n & 7);
            float4 v4 = *(const float4*)(q + (size_t)l * C + head * HD + c4);
            Qs[r * 36 + c4 + 0] = __float_as_uint(v4.x);
            Qs[r * 36 + c4 + 1] = __float_as_uint(v4.y);
            Qs[r * 36 + c4 + 2] = __float_as_uint(v4.z);
            Qs[r * 36 + c4 + 3] = __float_as_uint(v4.w);
        }
        __syncthreads();

        float s[8][4];
#pragma unroll
        for (int j = 0; j < 8; j++)
#pragma unroll
            for (int t = 0; t < 4; t++) s[j][t] = 0.f;

        const unsigned* Qrow = Qs + (w * 16 + rq) * 36;
#pragma unroll
        for (int kb0 = 0; kb0 < 32; kb0 += 8) {
            unsigned a[4];
            a[0] = Qrow[kb0 + tq];
            a[1] = Qrow[8 * 36 + kb0 + tq];
            a[2] = Qrow[kb0 + tq + 4];
            a[3] = Qrow[8 * 36 + kb0 + tq + 4];
#pragma unroll
            for (int j = 0; j < 8; j++) {
                unsigned b[2];
                const unsigned* Kr = Ks + (j * 8 + rq) * 36 + kb0 + tq;
                b[0] = Kr[0];
                b[1] = Kr[4];
                mma_tf32(s[j], a, b);
            }
        }

        const int n0 = p * 128 + w * 16 + rq;
        const int n1 = n0 + 8;
        int qb0, qb1;
        {
            int zz = n0 >> 6, yy = (n0 >> 3) & 7, xx = n0 & 7;
            qb0 = ((zz >> 1) + 3) * 49 + ((yy >> 1) + 3) * 7 + (xx >> 1) + 3;
            zz = n1 >> 6; yy = (n1 >> 3) & 7; xx = n1 & 7;
            qb1 = ((zz >> 1) + 3) * 49 + ((yy >> 1) + 3) * 7 + (xx >> 1) + 3;
        }
        float mx0 = -1e30f, mx1 = -1e30f;
#pragma unroll
        for (int j = 0; j < 8; j++) {
#pragma unroll
            for (int s2 = 0; s2 < 2; s2++) {
                int m = j * 8 + tq * 2 + s2;
                int koff = (m >> 4) * 49 + ((m >> 2) & 3) * 7 + (m & 3);
                s[j][s2]     += bt[qb0 - koff];
                s[j][2 + s2] += bt[qb1 - koff];
                mx0 = fmaxf(mx0, s[j][s2]);
                mx1 = fmaxf(mx1, s[j][2 + s2]);
            }
        }
        mx0 = fmaxf(mx0, __shfl_xor_sync(0xffffffffu, mx0, 1));
        mx0 = fmaxf(mx0, __shfl_xor_sync(0xffffffffu, mx0, 2));
        mx1 = fmaxf(mx1, __shfl_xor_sync(0xffffffffu, mx1, 1));
        mx1 = fmaxf(mx1, __shfl_xor_sync(0xffffffffu, mx1, 2));
        float sum0 = 0.f, sum1 = 0.f;
#pragma unroll
        for (int j = 0; j < 8; j++) {
#pragma unroll
            for (int s2 = 0; s2 < 2; s2++) {
                s[j][s2]     = __expf(s[j][s2]     - mx0);
                s[j][2 + s2] = __expf(s[j][2 + s2] - mx1);
                sum0 += s[j][s2];
                sum1 += s[j][2 + s2];
            }
        }
        sum0 += __shfl_xor_sync(0xffffffffu, sum0, 1);
        sum0 += __shfl_xor_sync(0xffffffffu, sum0, 2);
        sum1 += __shfl_xor_sync(0xffffffffu, sum1, 1);
        sum1 += __shfl_xor_sync(0xffffffffu, sum1, 2);
        const float inv0 = 1.0f / sum0, inv1 = 1.0f / sum1;

#pragma unroll
        for (int j = 0; j < 8; j++) {
#pragma unroll
            for (int s2 = 0; s2 < 2; s2++) {
                int m = j * 8 + tq * 2 + s2;
                Pme[rq * 68 + m]       = __float_as_uint(s[j][s2] * inv0);
                Pme[(rq + 8) * 68 + m] = __float_as_uint(s[j][2 + s2] * inv1);
            }
        }
        __syncwarp();

        float oa[4][4];
#pragma unroll
        for (int j = 0; j < 4; j++)
#pragma unroll
            for (int t = 0; t < 4; t++) oa[j][t] = 0.f;

        const unsigned* Prow = Pme + rq * 68;
#pragma unroll
        for (int kb0 = 0; kb0 < 64; kb0 += 8) {
            unsigned a[4];
            a[0] = Prow[kb0 + tq];
            a[1] = Prow[8 * 68 + kb0 + tq];
            a[2] = Prow[kb0 + tq + 4];
            a[3] = Prow[8 * 68 + kb0 + tq + 4];
#pragma unroll
            for (int jn = 0; jn < 4; jn++) {
                unsigned b[2];
                const unsigned* Vr = Vt + (jn * 8 + rq) * 68 + kb0 + tq;
                b[0] = Vr[0];
                b[1] = Vr[4];
                mma_tf32(oa[jn], a, b);
            }
        }

        const int l0 = wbase + (n0 >> 6) * 4096 + ((n0 >> 3) & 7) * 64 + (n0 & 7);
        const int l1 = wbase + (n1 >> 6) * 4096 + ((n1 >> 3) & 7) * 64 + (n1 & 7);
        float* o0 = o + (size_t)l0 * C + head * HD + tq * 2;
        float* o1 = o + (size_t)l1 * C + head * HD + tq * 2;
#pragma unroll
        for (int jn = 0; jn < 4; jn++) {
            *(float2*)(o0 + jn * 8) = make_float2(oa[jn][0], oa[jn][1]);
            *(float2*)(o1 + jn * 8) = make_float2(oa[jn][2], oa[jn][3]);
        }
    }
}

// ---------------- depthwise 3x3x3 conv + gelu + residual-add ---------------
__global__ void dwconv_kernel(const float* __restrict__ hid, const float* __restrict__ wgt,
                              const float* __restrict__ bias, float* __restrict__ hdn)
{
    const int c4  = threadIdx.x;
    const int bid = blockIdx.x;
    const int x0  = (bid & 15) * 4;
    const int y   = (bid >> 4) & 63;
    const int z   = bid >> 10;

    float4 acc[4];
#pragma unroll
    for (int i = 0; i < 4; i++) acc[i] = make_float4(0.f, 0.f, 0.f, 0.f);

    for (int kd = 0; kd < 3; kd++) {
        int zz = z + kd - 1;
        if (zz < 0 || zz >= DD) continue;
        for (int kh = 0; kh < 3; kh++) {
            int yy = y + kh - 1;
            if (yy < 0 || yy >= HHH) continue;
            const float* base = hid + ((size_t)(zz * HHH + yy) * WWW) * HID + c4 * 4;
            float4 hv[6];
#pragma unroll
            for (int i = 0; i < 6; i++) {
                int xx = x0 - 1 + i;
                hv[i] = (xx >= 0 && xx < WWW) ? *(const float4*)(base + (size_t)xx * HID)
                                              : make_float4(0.f, 0.f, 0.f, 0.f);
            }
#pragma unroll
            for (int kw = 0; kw < 3; kw++) {
                float4 wv = *(const float4*)(wgt + ((kd * 3 + kh) * 3 + kw) * HID + c4 * 4);
#pragma unroll
                for (int xi = 0; xi < 4; xi++) {
                    acc[xi].x += hv[xi + kw].x * wv.x;
                    acc[xi].y += hv[xi + kw].y * wv.y;
                    acc[xi].z += hv[xi + kw].z * wv.z;
                    acc[xi].w += hv[xi + kw].w * wv.w;
                }
            }
        }
    }
    float4 bv = *(const float4*)(bias + c4 * 4);
#pragma unroll
    for (int xi = 0; xi < 4; xi++) {
        size_t idx = ((size_t)((z * HHH + y) * WWW + x0 + xi)) * HID + c4 * 4;
        float4 h0 = *(const float4*)(hid + idx);
        float4 o;
        o.x = h0.x + gelu_f(acc[xi].x + bv.x);
        o.y = h0.y + gelu_f(acc[xi].y + bv.y);
        o.z = h0.z + gelu_f(acc[xi].z + bv.z);
        o.w = h0.w + gelu_f(acc[xi].w + bv.w);
        *(float4*)&hdn[idx] = o;
    }
}

// ---------------- launch ----------------------------------------------------
static float* sym_addr(const void* sym) {
    void* p = nullptr;
    cudaGetSymbolAddress(&p, sym);
    return (float*)p;
}

extern "C" void kernel_launch(void* const* d_in, const int* in_sizes, int n_in,
                              void* d_out, int out_size)
{
    const float* x    = (const float*)d_in[0];
    const float* n1g  = (const float*)d_in[1];
    const float* n1b  = (const float*)d_in[2];
    const float* q_w  = (const float*)d_in[3];
    const float* q_b  = (const float*)d_in[4];
    const float* kv_w = (const float*)d_in[5];
    const float* kv_b = (const float*)d_in[6];
    const float* btab = (const float*)d_in[7];
    const float* p_w  = (const float*)d_in[8];
    const float* p_b  = (const float*)d_in[9];
    const float* n2g  = (const float*)d_in[10];
    const float* n2b  = (const float*)d_in[11];
    const float* f1w  = (const float*)d_in[12];
    const float* f1b  = (const float*)d_in[13];
    const float* dww  = (const float*)d_in[14];
    const float* dwb  = (const float*)d_in[15];
    const float* f2w  = (const float*)d_in[16];
    const float* f2b  = (const float*)d_in[17];
    float* out = (float*)d_out;

    float* xn  = sym_addr(g_xn);
    float* qb_ = sym_addr(g_q);
    float* kb_ = sym_addr(g_k);
    float* vb_ = sym_addr(g_v);
    float* ob_ = sym_addr(g_o);
    float* x1  = sym_addr(g_x1);
    float* hid = sym_addr(g_hid);
    float* hdn = sym_addr(g_hdn);

    const float qscale = 0.17677669529663687f;  // 1/sqrt(32)
    const int attn_smem = ATTN_SMEM_WORDS * 4;

    cudaFuncSetAttribute(attn_mma_kernel,
                         cudaFuncAttributeMaxDynamicSharedMemorySize, attn_smem);
    cudaFuncSetAttribute(gemm_mma<0>,
                         cudaFuncAttributeMaxDynamicSharedMemorySize, GEMM_SMEM_BYTES);
    cudaFuncSetAttribute(gemm_mma<1>,
                         cudaFuncAttributeMaxDynamicSharedMemorySize, GEMM_SMEM_BYTES);
    cudaFuncSetAttribute(gemm_mma<2>,
                         cudaFuncAttributeMaxDynamicSharedMemorySize, GEMM_SMEM_BYTES);

    // 1) LN1
    ln_kernel<<<L / 8, 256>>>(x, n1g, n1b, xn);
    // 2) q = (xn @ q_w + q_b) * scale        [tf32 mma, cp.async pipeline]
    gemm_mma<0><<<dim3(C / 64, L / 128), 256, GEMM_SMEM_BYTES>>>(
        xn, q_w, q_b, nullptr, qb_, L, C, C, qscale);
    // 3) kv projection + permuted scatter
    kvproj_kernel<<<L / 16, 192>>>(xn, kv_w, kv_b, kb_, vb_);
    // 4) windowed attention                  [tf32 mma]
    attn_mma_kernel<<<NWIN * NHD, 256, attn_smem>>>(qb_, kb_, vb_, btab, ob_);
    // 5) x1 = x + o @ proj_w + proj_b
    gemm_mma<1><<<dim3(C / 64, L / 128), 256, GEMM_SMEM_BYTES>>>(
        ob_, p_w, p_b, x, x1, L, C, C, 1.f);
    // 6) LN2
    ln_kernel<<<L / 8, 256>>>(x1, n2g, n2b, xn);
    // 7) hid = gelu(xn @ fc1_w + fc1_b)
    gemm_mma<2><<<dim3(HID / 64, L / 128), 256, GEMM_SMEM_BYTES>>>(
        xn, f1w, f1b, nullptr, hid, L, HID, C, 1.f);
    // 8) hdn = hid + gelu(dwconv(hid) + dw_b)
    dwconv_kernel<<<(DD * HHH * WWW) / 4, 192>>>(hid, dww, dwb, hdn);
    // 9) out = x1 + hdn @ fc2_w + fc2_b
    gemm_mma<1><<<dim3(C / 64, L / 128), 256, GEMM_SMEM_BYTES>>>(
        hdn, f2w, f2b, x1, out, L, C, HID, 1.f);
}

// round 5
// speedup vs baseline: 2.7967x; 1.0666x over previous
#include <cuda_runtime.h>
#include <math.h>

// ---------------- problem constants (fixed by the dataset) ----------------
#define L     131072        // tokens = 32*64*64
#define C     192           // dim
#define NHD   6             // heads
#define HD    32            // head dim
#define NWIN  256           // 4*8*8 windows of 8^3
#define NP    64            // pooled kv tokens per window (4^3)
#define HID   768           // ffn hidden
#define DD    32
#define HHH   64
#define WWW   64

// ---------------- scratch (device globals: allocation-free) ----------------
__device__ float g_xn[L * C];
__device__ float g_q [L * C];
__device__ float g_k [NWIN * NHD * NP * HD];
__device__ float g_v [NWIN * NHD * NP * HD];
__device__ float g_o [L * C];
__device__ float g_x1[L * C];
__device__ float g_hid[L * HID];
__device__ float g_hdn[L * HID];

__device__ __forceinline__ float gelu_f(float v) {
    return 0.5f * v * (1.0f + erff(v * 0.70710678118654752f));
}

__device__ __forceinline__ void mma_tf32(float* d, const unsigned* a, const unsigned* b) {
    asm volatile(
        "mma.sync.aligned.m16n8k8.row.col.f32.tf32.tf32.f32 "
        "{%0,%1,%2,%3},{%4,%5,%6,%7},{%8,%9},{%0,%1,%2,%3};"
        : "+f"(d[0]), "+f"(d[1]), "+f"(d[2]), "+f"(d[3])
        : "r"(a[0]), "r"(a[1]), "r"(a[2]), "r"(a[3]), "r"(b[0]), "r"(b[1]));
}

#define CP16(dst_smem_u32, src_ptr) \
    asm volatile("cp.async.cg.shared.global [%0], [%1], 16;\n" \
                 :: "r"(dst_smem_u32), "l"(src_ptr))
#define CP_COMMIT() asm volatile("cp.async.commit_group;\n" ::: "memory")
#define CP_WAIT0()  asm volatile("cp.async.wait_group 0;\n" ::: "memory")

// ---------------- LayerNorm: one warp per token (192 elems) ----------------
__global__ void ln_kernel(const float* __restrict__ x, const float* __restrict__ g,
                          const float* __restrict__ b, float* __restrict__ y)
{
    int lane = threadIdx.x & 31;
    int wi   = threadIdx.x >> 5;
    int l    = blockIdx.x * 8 + wi;
    const float* row = x + (size_t)l * C;
    float v[6];
    float s = 0.f, ss = 0.f;
#pragma unroll
    for (int i = 0; i < 6; i++) {
        v[i] = row[lane + 32 * i];
        s  += v[i];
        ss += v[i] * v[i];
    }
#pragma unroll
    for (int off = 16; off > 0; off >>= 1) {
        s  += __shfl_xor_sync(0xffffffffu, s,  off);
        ss += __shfl_xor_sync(0xffffffffu, ss, off);
    }
    float mean = s * (1.0f / C);
    float var  = ss * (1.0f / C) - mean * mean;
    float inv  = rsqrtf(var + 1e-5f);
    float* yr = y + (size_t)l * C;
#pragma unroll
    for (int i = 0; i < 6; i++) {
        int c = lane + 32 * i;
        yr[c] = (v[i] - mean) * inv * g[c] + b[c];
    }
}

// -------- tf32 GEMM: 128x64 block, 4 warps x (64x32) warp tile -------------
// k-step 32, 2-stage cp.async, ONE syncthreads per k-tile.
// A smem [2][128][36], B smem [2][32][72]; raw fp32 bits fed as tf32.
#define GEMM_SMEM_BYTES ((2 * (128 * 36 + 32 * 72)) * 4)
template <int EPI>
__global__ void __launch_bounds__(128)
gemm_mma(const float* __restrict__ A, const float* __restrict__ Bm,
         const float* __restrict__ bias, const float* __restrict__ res,
         float* __restrict__ Cm, int M, int N, int K, float scale)
{
    extern __shared__ float gsm[];
    float* As = gsm;                       // [2][128][36]
    float* Bs = gsm + 2 * 128 * 36;        // [2][32][72]

    const int tid  = threadIdx.x;
    const int lane = tid & 31, warp = tid >> 5;
    const int wm = warp & 1, wn = warp >> 1;
    const int row0 = blockIdx.y * 128, col0 = blockIdx.x * 64;

    float acc[4][4][4];
#pragma unroll
    for (int i = 0; i < 4; i++)
#pragma unroll
        for (int j = 0; j < 4; j++)
#pragma unroll
            for (int t = 0; t < 4; t++) acc[i][j][t] = 0.f;

    const unsigned sA = (unsigned)__cvta_generic_to_shared(As);
    const unsigned sB = (unsigned)__cvta_generic_to_shared(Bs);
    const int ntiles = K >> 5;

    auto load_tile = [&](int kt, int st) {
        unsigned aOff = sA + (unsigned)(st * 128 * 36) * 4;
        // A: 128x32 words = 1024 x 16B chunks; 128 thr x 8
#pragma unroll
        for (int i = 0; i < 8; i++) {
            int id = tid + i * 128;
            int r = id >> 3, kc = (id & 7) * 4;
            CP16(aOff + (unsigned)(r * 36 + kc) * 4,
                 A + (size_t)(row0 + r) * K + kt + kc);
        }
        // B: 32x64 words = 512 chunks; 128 thr x 4
        unsigned bOff = sB + (unsigned)(st * 32 * 72) * 4;
#pragma unroll
        for (int i = 0; i < 4; i++) {
            int id = tid + i * 128;
            int kr = id >> 4, c4 = (id & 15) * 4;
            CP16(bOff + (unsigned)(kr * 72 + c4) * 4,
                 Bm + (size_t)(kt + kr) * N + col0 + c4);
        }
        CP_COMMIT();
    };

    load_tile(0, 0);

    const int rq = lane >> 2, tq = lane & 3;
    const int rb = wm * 64 + rq;
    const int cb = wn * 32 + rq;

    for (int t = 0; t < ntiles; t++) {
        CP_WAIT0();
        __syncthreads();
        if (t + 1 < ntiles) load_tile((t + 1) << 5, (t + 1) & 1);

        const float* Ast = As + (t & 1) * 128 * 36;
        const float* Bst = Bs + (t & 1) * 32 * 72;
#pragma unroll
        for (int ks = 0; ks < 32; ks += 8) {
            const int k0 = ks + tq;
            unsigned af[4][4], bf[4][2];
#pragma unroll
            for (int mi = 0; mi < 4; mi++) {
                const float* Ar = Ast + (rb + mi * 16) * 36;
                af[mi][0] = __float_as_uint(Ar[k0]);
                af[mi][1] = __float_as_uint(Ar[8 * 36 + k0]);
                af[mi][2] = __float_as_uint(Ar[k0 + 4]);
                af[mi][3] = __float_as_uint(Ar[8 * 36 + k0 + 4]);
            }
#pragma unroll
            for (int ni = 0; ni < 4; ni++) {
                bf[ni][0] = __float_as_uint(Bst[k0 * 72 + cb + ni * 8]);
                bf[ni][1] = __float_as_uint(Bst[(k0 + 4) * 72 + cb + ni * 8]);
            }
#pragma unroll
            for (int mi = 0; mi < 4; mi++)
#pragma unroll
                for (int ni = 0; ni < 4; ni++)
                    mma_tf32(acc[mi][ni], af[mi], bf[ni]);
        }
        __syncthreads();   // all warps done reading stage t before it is refilled
    }

    const int crow0 = row0 + wm * 64 + rq;
    const int ccol  = col0 + wn * 32 + tq * 2;
#pragma unroll
    for (int mi = 0; mi < 4; mi++) {
#pragma unroll
        for (int half = 0; half < 2; half++) {
            int row = crow0 + mi * 16 + half * 8;
#pragma unroll
            for (int ni = 0; ni < 4; ni++) {
                int col = ccol + ni * 8;
                float v0 = acc[mi][ni][half * 2 + 0] + bias[col];
                float v1 = acc[mi][ni][half * 2 + 1] + bias[col + 1];
                if (EPI == 0)      { v0 *= scale; v1 *= scale; }
                else if (EPI == 1) {
                    float2 rv = *(const float2*)(res + (size_t)row * N + col);
                    v0 += rv.x; v1 += rv.y;
                } else             { v0 = gelu_f(v0); v1 = gelu_f(v1); }
                *(float2*)(Cm + (size_t)row * N + col) = make_float2(v0, v1);
            }
        }
    }
}

// ---------------- KV projection + scatter into pooled window layout --------
__global__ void kvproj_kernel(const float* __restrict__ xn, const float* __restrict__ kvw,
                              const float* __restrict__ kvb,
                              float* __restrict__ ko, float* __restrict__ vo)
{
    __shared__ float sx[16][193];
    const int tid  = threadIdx.x;
    const int base = blockIdx.x * 16;
#pragma unroll
    for (int i = 0; i < 16; i++) sx[i][tid] = xn[(size_t)(base + i) * C + tid];
    __syncthreads();

    const int t  = tid / 12;
    const int jg = tid % 12;
    float4 bb = *(const float4*)(kvb + jg * 4);
    float s0 = bb.x, s1 = bb.y, s2 = bb.z, s3 = bb.w;
#pragma unroll 8
    for (int c = 0; c < C; c++) {
        float xv = sx[t][c];
        float4 w4 = *(const float4*)(kvw + c * 48 + jg * 4);
        s0 += xv * w4.x; s1 += xv * w4.y; s2 += xv * w4.z; s3 += xv * w4.w;
    }
    int l  = base + t;
    int z  = l >> 12, y = (l >> 6) & 63, x = l & 63;
    int win = ((z >> 3) << 6) | ((y >> 3) << 3) | (x >> 3);
    int zz = z & 7, yy = y & 7, xx = x & 7;
    int m   = ((zz >> 1) << 4) | ((yy >> 1) << 2) | (xx >> 1);
    int sub = ((zz & 1) << 2)  | ((yy & 1) << 1)  | (xx & 1);
    int head = jg % 6;
    float* dst = (jg < 6) ? ko : vo;
    *(float4*)&dst[(((size_t)(win * NHD + head)) * NP + m) * HD + sub * 4] =
        make_float4(s0, s1, s2, s3);
}

// ---------------- attention via tensor cores: block = (window, head) -------
#define ATTN_SMEM_WORDS (64*36 + 32*68 + 128*36 + 8*16*68 + 343)
__global__ void __launch_bounds__(256)
attn_mma_kernel(const float* __restrict__ q, const float* __restrict__ kbuf,
                const float* __restrict__ vbuf, const float* __restrict__ btab,
                float* __restrict__ o)
{
    extern __shared__ unsigned sm[];
    unsigned* Ks = sm;                    // [64][36]  K, (m,c)
    unsigned* Vt = Ks + 64 * 36;          // [32][68]  V^T, (c,m)
    unsigned* Qs = Vt + 32 * 68;          // [128][36] Q chunk
    unsigned* Pw = Qs + 128 * 36;         // [8][16][68] per-warp P
    float*    bt = (float*)(Pw + 8 * 16 * 68);  // [343]

    const int win  = blockIdx.x / NHD;
    const int head = blockIdx.x % NHD;
    const int tid = threadIdx.x, lane = tid & 31, w = tid >> 5;
    const int rq = lane >> 2, tq = lane & 3;

    const float* kb = kbuf + (size_t)(win * NHD + head) * NP * HD;
    const float* vb = vbuf + (size_t)(win * NHD + head) * NP * HD;
    for (int i = tid; i < NP * HD; i += 256) {
        int m = i >> 5, c = i & 31;
        Ks[m * 36 + c] = __float_as_uint(kb[i]);
    }
    for (int i = tid; i < NP * HD; i += 256) {
        int c = i >> 6, m = i & 63;
        Vt[c * 68 + m] = __float_as_uint(vb[m * 32 + c]);
    }
    for (int i = tid; i < 343; i += 256) bt[i] = btab[i * NHD + head];

    const int wz = win >> 6, wy = (win >> 3) & 7, wx = win & 7;
    const int wbase = wz * 32768 + wy * 512 + wx * 8;
    unsigned* Pme = Pw + w * 16 * 68;

#pragma unroll 1
    for (int p = 0; p < 4; p++) {
        __syncthreads();
#pragma unroll
        for (int i = 0; i < 4; i++) {
            int idx = tid + i * 256;
            int r = idx >> 3, c4 = (idx & 7) * 4;
            int n = p * 128 + r;
            int l = wbase + (n >> 6) * 4096 + ((n >> 3) & 7) * 64 + (n & 7);
            float4 v4 = *(const float4*)(q + (size_t)l * C + head * HD + c4);
            Qs[r * 36 + c4 + 0] = __float_as_uint(v4.x);
            Qs[r * 36 + c4 + 1] = __float_as_uint(v4.y);
            Qs[r * 36 + c4 + 2] = __float_as_uint(v4.z);
            Qs[r * 36 + c4 + 3] = __float_as_uint(v4.w);
        }
        __syncthreads();

        float s[8][4];
#pragma unroll
        for (int j = 0; j < 8; j++)
#pragma unroll
            for (int t = 0; t < 4; t++) s[j][t] = 0.f;

        const unsigned* Qrow = Qs + (w * 16 + rq) * 36;
#pragma unroll
        for (int kb0 = 0; kb0 < 32; kb0 += 8) {
            unsigned a[4];
            a[0] = Qrow[kb0 + tq];
            a[1] = Qrow[8 * 36 + kb0 + tq];
            a[2] = Qrow[kb0 + tq + 4];
            a[3] = Qrow[8 * 36 + kb0 + tq + 4];
#pragma unroll
            for (int j = 0; j < 8; j++) {
                unsigned b[2];
                const unsigned* Kr = Ks + (j * 8 + rq) * 36 + kb0 + tq;
                b[0] = Kr[0];
                b[1] = Kr[4];
                mma_tf32(s[j], a, b);
            }
        }

        const int n0 = p * 128 + w * 16 + rq;
        const int n1 = n0 + 8;
        int qb0, qb1;
        {
            int zz = n0 >> 6, yy = (n0 >> 3) & 7, xx = n0 & 7;
            qb0 = ((zz >> 1) + 3) * 49 + ((yy >> 1) + 3) * 7 + (xx >> 1) + 3;
            zz = n1 >> 6; yy = (n1 >> 3) & 7; xx = n1 & 7;
            qb1 = ((zz >> 1) + 3) * 49 + ((yy >> 1) + 3) * 7 + (xx >> 1) + 3;
        }
        float mx0 = -1e30f, mx1 = -1e30f;
#pragma unroll
        for (int j = 0; j < 8; j++) {
#pragma unroll
            for (int s2 = 0; s2 < 2; s2++) {
                int m = j * 8 + tq * 2 + s2;
                int koff = (m >> 4) * 49 + ((m >> 2) & 3) * 7 + (m & 3);
                s[j][s2]     += bt[qb0 - koff];
                s[j][2 + s2] += bt[qb1 - koff];
                mx0 = fmaxf(mx0, s[j][s2]);
                mx1 = fmaxf(mx1, s[j][2 + s2]);
            }
        }
        mx0 = fmaxf(mx0, __shfl_xor_sync(0xffffffffu, mx0, 1));
        mx0 = fmaxf(mx0, __shfl_xor_sync(0xffffffffu, mx0, 2));
        mx1 = fmaxf(mx1, __shfl_xor_sync(0xffffffffu, mx1, 1));
        mx1 = fmaxf(mx1, __shfl_xor_sync(0xffffffffu, mx1, 2));
        float sum0 = 0.f, sum1 = 0.f;
#pragma unroll
        for (int j = 0; j < 8; j++) {
#pragma unroll
            for (int s2 = 0; s2 < 2; s2++) {
                s[j][s2]     = __expf(s[j][s2]     - mx0);
                s[j][2 + s2] = __expf(s[j][2 + s2] - mx1);
                sum0 += s[j][s2];
                sum1 += s[j][2 + s2];
            }
        }
        sum0 += __shfl_xor_sync(0xffffffffu, sum0, 1);
        sum0 += __shfl_xor_sync(0xffffffffu, sum0, 2);
        sum1 += __shfl_xor_sync(0xffffffffu, sum1, 1);
        sum1 += __shfl_xor_sync(0xffffffffu, sum1, 2);
        const float inv0 = 1.0f / sum0, inv1 = 1.0f / sum1;

#pragma unroll
        for (int j = 0; j < 8; j++) {
#pragma unroll
            for (int s2 = 0; s2 < 2; s2++) {
                int m = j * 8 + tq * 2 + s2;
                Pme[rq * 68 + m]       = __float_as_uint(s[j][s2] * inv0);
                Pme[(rq + 8) * 68 + m] = __float_as_uint(s[j][2 + s2] * inv1);
            }
        }
        __syncwarp();

        float oa[4][4];
#pragma unroll
        for (int j = 0; j < 4; j++)
#pragma unroll
            for (int t = 0; t < 4; t++) oa[j][t] = 0.f;

        const unsigned* Prow = Pme + rq * 68;
#pragma unroll
        for (int kb0 = 0; kb0 < 64; kb0 += 8) {
            unsigned a[4];
            a[0] = Prow[kb0 + tq];
            a[1] = Prow[8 * 68 + kb0 + tq];
            a[2] = Prow[kb0 + tq + 4];
            a[3] = Prow[8 * 68 + kb0 + tq + 4];
#pragma unroll
            for (int jn = 0; jn < 4; jn++) {
                unsigned b[2];
                const unsigned* Vr = Vt + (jn * 8 + rq) * 68 + kb0 + tq;
                b[0] = Vr[0];
                b[1] = Vr[4];
                mma_tf32(oa[jn], a, b);
            }
        }

        const int l0 = wbase + (n0 >> 6) * 4096 + ((n0 >> 3) & 7) * 64 + (n0 & 7);
        const int l1 = wbase + (n1 >> 6) * 4096 + ((n1 >> 3) & 7) * 64 + (n1 & 7);
        float* o0 = o + (size_t)l0 * C + head * HD + tq * 2;
        float* o1 = o + (size_t)l1 * C + head * HD + tq * 2;
#pragma unroll
        for (int jn = 0; jn < 4; jn++) {
            *(float2*)(o0 + jn * 8) = make_float2(oa[jn][0], oa[jn][1]);
            *(float2*)(o1 + jn * 8) = make_float2(oa[jn][2], oa[jn][3]);
        }
    }
}

// ---------------- depthwise 3x3x3 conv + gelu + residual-add ---------------
// x-tile of 8: register sliding window, 11.25 words/output vs 13.5 at tile 4.
__global__ void dwconv_kernel(const float* __restrict__ hid, const float* __restrict__ wgt,
                              const float* __restrict__ bias, float* __restrict__ hdn)
{
    const int c4  = threadIdx.x;          // 0..191
    const int bid = blockIdx.x;           // 0..16383
    const int x0  = (bid & 7) * 8;
    const int y   = (bid >> 3) & 63;
    const int z   = bid >> 9;

    float4 acc[8];
#pragma unroll
    for (int i = 0; i < 8; i++) acc[i] = make_float4(0.f, 0.f, 0.f, 0.f);

    for (int kd = 0; kd < 3; kd++) {
        int zz = z + kd - 1;
        if (zz < 0 || zz >= DD) continue;
        for (int kh = 0; kh < 3; kh++) {
            int yy = y + kh - 1;
            if (yy < 0 || yy >= HHH) continue;
            const float* base = hid + ((size_t)(zz * HHH + yy) * WWW) * HID + c4 * 4;
            float4 hv[10];
#pragma unroll
            for (int i = 0; i < 10; i++) {
                int xx = x0 - 1 + i;
                hv[i] = (xx >= 0 && xx < WWW) ? *(const float4*)(base + (size_t)xx * HID)
                                              : make_float4(0.f, 0.f, 0.f, 0.f);
            }
#pragma unroll
            for (int kw = 0; kw < 3; kw++) {
                float4 wv = *(const float4*)(wgt + ((kd * 3 + kh) * 3 + kw) * HID + c4 * 4);
#pragma unroll
                for (int xi = 0; xi < 8; xi++) {
                    acc[xi].x += hv[xi + kw].x * wv.x;
                    acc[xi].y += hv[xi + kw].y * wv.y;
                    acc[xi].z += hv[xi + kw].z * wv.z;
                    acc[xi].w += hv[xi + kw].w * wv.w;
                }
            }
        }
    }
    float4 bv = *(const float4*)(bias + c4 * 4);
#pragma unroll
    for (int xi = 0; xi < 8; xi++) {
        size_t idx = ((size_t)((z * HHH + y) * WWW + x0 + xi)) * HID + c4 * 4;
        float4 h0 = *(const float4*)(hid + idx);
        float4 o;
        o.x = h0.x + gelu_f(acc[xi].x + bv.x);
        o.y = h0.y + gelu_f(acc[xi].y + bv.y);
        o.z = h0.z + gelu_f(acc[xi].z + bv.z);
        o.w = h0.w + gelu_f(acc[xi].w + bv.w);
        *(float4*)&hdn[idx] = o;
    }
}

// ---------------- launch ----------------------------------------------------
static float* sym_addr(const void* sym) {
    void* p = nullptr;
    cudaGetSymbolAddress(&p, sym);
    return (float*)p;
}

extern "C" void kernel_launch(void* const* d_in, const int* in_sizes, int n_in,
                              void* d_out, int out_size)
{
    const float* x    = (const float*)d_in[0];
    const float* n1g  = (const float*)d_in[1];
    const float* n1b  = (const float*)d_in[2];
    const float* q_w  = (const float*)d_in[3];
    const float* q_b  = (const float*)d_in[4];
    const float* kv_w = (const float*)d_in[5];
    const float* kv_b = (const float*)d_in[6];
    const float* btab = (const float*)d_in[7];
    const float* p_w  = (const float*)d_in[8];
    const float* p_b  = (const float*)d_in[9];
    const float* n2g  = (const float*)d_in[10];
    const float* n2b  = (const float*)d_in[11];
    const float* f1w  = (const float*)d_in[12];
    const float* f1b  = (const float*)d_in[13];
    const float* dww  = (const float*)d_in[14];
    const float* dwb  = (const float*)d_in[15];
    const float* f2w  = (const float*)d_in[16];
    const float* f2b  = (const float*)d_in[17];
    float* out = (float*)d_out;

    float* xn  = sym_addr(g_xn);
    float* qb_ = sym_addr(g_q);
    float* kb_ = sym_addr(g_k);
    float* vb_ = sym_addr(g_v);
    float* ob_ = sym_addr(g_o);
    float* x1  = sym_addr(g_x1);
    float* hid = sym_addr(g_hid);
    float* hdn = sym_addr(g_hdn);

    const float qscale = 0.17677669529663687f;  // 1/sqrt(32)
    const int attn_smem = ATTN_SMEM_WORDS * 4;

    cudaFuncSetAttribute(attn_mma_kernel,
                         cudaFuncAttributeMaxDynamicSharedMemorySize, attn_smem);
    cudaFuncSetAttribute(gemm_mma<0>,
                         cudaFuncAttributeMaxDynamicSharedMemorySize, GEMM_SMEM_BYTES);
    cudaFuncSetAttribute(gemm_mma<1>,
                         cudaFuncAttributeMaxDynamicSharedMemorySize, GEMM_SMEM_BYTES);
    cudaFuncSetAttribute(gemm_mma<2>,
                         cudaFuncAttributeMaxDynamicSharedMemorySize, GEMM_SMEM_BYTES);

    // 1) LN1
    ln_kernel<<<L / 8, 256>>>(x, n1g, n1b, xn);
    // 2) q = (xn @ q_w + q_b) * scale
    gemm_mma<0><<<dim3(C / 64, L / 128), 128, GEMM_SMEM_BYTES>>>(
        xn, q_w, q_b, nullptr, qb_, L, C, C, qscale);
    // 3) kv projection + permuted scatter
    kvproj_kernel<<<L / 16, 192>>>(xn, kv_w, kv_b, kb_, vb_);
    // 4) windowed attention
    attn_mma_kernel<<<NWIN * NHD, 256, attn_smem>>>(qb_, kb_, vb_, btab, ob_);
    // 5) x1 = x + o @ proj_w + proj_b
    gemm_mma<1><<<dim3(C / 64, L / 128), 128, GEMM_SMEM_BYTES>>>(
        ob_, p_w, p_b, x, x1, L, C, C, 1.f);
    // 6) LN2
    ln_kernel<<<L / 8, 256>>>(x1, n2g, n2b, xn);
    // 7) hid = gelu(xn @ fc1_w + fc1_b)
    gemm_mma<2><<<dim3(HID / 64, L / 128), 128, GEMM_SMEM_BYTES>>>(
        xn, f1w, f1b, nullptr, hid, L, HID, C, 1.f);
    // 8) hdn = hid + gelu(dwconv(hid) + dw_b)
    dwconv_kernel<<<(DD * HHH * WWW) / 8, 192>>>(hid, dww, dwb, hdn);
    // 9) out = x1 + hdn @ fc2_w + fc2_b
    gemm_mma<1><<<dim3(C / 64, L / 128), 128, GEMM_SMEM_BYTES>>>(
        hdn, f2w, f2b, x1, out, L, C, HID, 1.f);
}

// round 6
// speedup vs baseline: 3.1572x; 1.1289x over previous
#include <cuda_runtime.h>
#include <cuda_bf16.h>
#include <math.h>

// ---------------- problem constants (fixed by the dataset) ----------------
#define L     131072        // tokens = 32*64*64
#define C     192           // dim
#define NHD   6             // heads
#define HD    32            // head dim
#define NWIN  256           // 4*8*8 windows of 8^3
#define NP    64            // pooled kv tokens per window (4^3)
#define HID   768           // ffn hidden
#define DD    32
#define HHH   64
#define WWW   64

// ---------------- scratch (device globals: allocation-free) ----------------
__device__ __nv_bfloat16 g_xnb [L * C];    // LN output (bf16, reused LN2)
__device__ float         g_q   [L * C];    // scaled q (fp32, attn reads f4)
__device__ float         g_k   [NWIN * NHD * NP * HD];
__device__ float         g_v   [NWIN * NHD * NP * HD];
__device__ __nv_bfloat16 g_ob  [L * C];    // attention output (bf16)
__device__ float         g_x1  [L * C];    // post-attn residual (fp32)
__device__ __nv_bfloat16 g_hidb[L * HID];  // gelu(fc1) hidden (bf16)
__device__ __nv_bfloat16 g_hdnb[L * HID];  // hidden + gelu(dwconv) (bf16)
// transposed bf16 weights [N][K]
__device__ __nv_bfloat16 g_qwT [C * C];
__device__ __nv_bfloat16 g_pwT [C * C];
__device__ __nv_bfloat16 g_f1wT[C * HID];
__device__ __nv_bfloat16 g_f2wT[HID * C];

__device__ __forceinline__ float gelu_f(float v) {
    return 0.5f * v * (1.0f + erff(v * 0.70710678118654752f));
}

__device__ __forceinline__ void mma_tf32(float* d, const unsigned* a, const unsigned* b) {
    asm volatile(
        "mma.sync.aligned.m16n8k8.row.col.f32.tf32.tf32.f32 "
        "{%0,%1,%2,%3},{%4,%5,%6,%7},{%8,%9},{%0,%1,%2,%3};"
        : "+f"(d[0]), "+f"(d[1]), "+f"(d[2]), "+f"(d[3])
        : "r"(a[0]), "r"(a[1]), "r"(a[2]), "r"(a[3]), "r"(b[0]), "r"(b[1]));
}

__device__ __forceinline__ void mma_bf16(float* d, const unsigned* a, const unsigned* b) {
    asm volatile(
        "mma.sync.aligned.m16n8k16.row.col.f32.bf16.bf16.f32 "
        "{%0,%1,%2,%3},{%4,%5,%6,%7},{%8,%9},{%0,%1,%2,%3};"
        : "+f"(d[0]), "+f"(d[1]), "+f"(d[2]), "+f"(d[3])
        : "r"(a[0]), "r"(a[1]), "r"(a[2]), "r"(a[3]), "r"(b[0]), "r"(b[1]));
}

#define CP16(dst_smem_u32, src_ptr) \
    asm volatile("cp.async.cg.shared.global [%0], [%1], 16;\n" \
                 :: "r"(dst_smem_u32), "l"(src_ptr))
#define CP_COMMIT() asm volatile("cp.async.commit_group;\n" ::: "memory")
#define CP_WAIT0()  asm volatile("cp.async.wait_group 0;\n" ::: "memory")

__device__ __forceinline__ float4 ldbf4(const __nv_bfloat16* p) {
    uint2 u = *(const uint2*)p;
    float2 a = __bfloat1622float2(*(__nv_bfloat162*)&u.x);
    float2 b = __bfloat1622float2(*(__nv_bfloat162*)&u.y);
    return make_float4(a.x, a.y, b.x, b.y);
}
__device__ __forceinline__ void stbf4(__nv_bfloat16* p, float4 v) {
    uint2 u;
    *(__nv_bfloat162*)&u.x = __floats2bfloat162_rn(v.x, v.y);
    *(__nv_bfloat162*)&u.y = __floats2bfloat162_rn(v.z, v.w);
    *(uint2*)p = u;
}

// ---------------- weight convert + transpose: wt[n][k] = bf16(w[k][n]) -----
__global__ void wconv_kernel(const float* __restrict__ w, __nv_bfloat16* __restrict__ wt,
                             int K, int N)
{
    int id = blockIdx.x * 256 + threadIdx.x;
    if (id >= K * N) return;
    int k = id / N, n = id % N;
    wt[(size_t)n * K + k] = __float2bfloat16(w[id]);
}

// ---------------- LayerNorm (fp32 in, bf16 out): one warp per token --------
__global__ void ln_kernel(const float* __restrict__ x, const float* __restrict__ g,
                          const float* __restrict__ b, __nv_bfloat16* __restrict__ y)
{
    int lane = threadIdx.x & 31;
    int wi   = threadIdx.x >> 5;
    int l    = blockIdx.x * 8 + wi;
    const float* row = x + (size_t)l * C;
    float v[6];
    float s = 0.f, ss = 0.f;
#pragma unroll
    for (int i = 0; i < 6; i++) {
        v[i] = row[lane + 32 * i];
        s  += v[i];
        ss += v[i] * v[i];
    }
#pragma unroll
    for (int off = 16; off > 0; off >>= 1) {
        s  += __shfl_xor_sync(0xffffffffu, s,  off);
        ss += __shfl_xor_sync(0xffffffffu, ss, off);
    }
    float mean = s * (1.0f / C);
    float var  = ss * (1.0f / C) - mean * mean;
    float inv  = rsqrtf(var + 1e-5f);
    __nv_bfloat16* yr = y + (size_t)l * C;
#pragma unroll
    for (int i = 0; i < 6; i++) {
        int c = lane + 32 * i;
        yr[c] = __float2bfloat16((v[i] - mean) * inv * g[c] + b[c]);
    }
}

// -------- bf16 GEMM: 128x64 block, 4 warps x (64x32), k-step 32 ------------
// A bf16 [M][K] row-major, B bf16 [N][K] (pre-transposed weights).
// cp.async double buffer, one syncthreads per k-tile.
// smem rows padded to 20 words (32 bf16 + 8 pad) -> conflict-free frag LDS.
// EPI: 0 = (acc+bias)*scale -> fp32 ; 1 = acc+bias+res -> fp32 ; 2 = gelu -> bf16
#define GEMM_SMEM_BYTES ((2 * (128 * 20 + 64 * 20)) * 4)
template <int EPI>
__global__ void __launch_bounds__(128)
gemm_bf16(const __nv_bfloat16* __restrict__ A, const __nv_bfloat16* __restrict__ Wt,
          const float* __restrict__ bias, const float* __restrict__ res,
          void* __restrict__ Cm, int M, int N, int K, float scale)
{
    extern __shared__ unsigned gsm[];
    unsigned* As = gsm;                    // [2][128][20] words
    unsigned* Bs = gsm + 2 * 128 * 20;     // [2][64][20] words

    const int tid  = threadIdx.x;
    const int lane = tid & 31, warp = tid >> 5;
    const int wm = warp & 1, wn = warp >> 1;
    const int row0 = blockIdx.y * 128, col0 = blockIdx.x * 64;

    float acc[4][4][4];
#pragma unroll
    for (int i = 0; i < 4; i++)
#pragma unroll
        for (int j = 0; j < 4; j++)
#pragma unroll
            for (int t = 0; t < 4; t++) acc[i][j][t] = 0.f;

    const unsigned sA = (unsigned)__cvta_generic_to_shared(As);
    const unsigned sB = (unsigned)__cvta_generic_to_shared(Bs);
    const int ntiles = K >> 5;

    auto load_tile = [&](int kt, int st) {
        unsigned aOff = sA + (unsigned)(st * 128 * 20) * 4;
        // A: 128 rows x 16 words = 512 x 16B chunks; 128 thr x 4
#pragma unroll
        for (int i = 0; i < 4; i++) {
            int id = tid + i * 128;
            int r = id >> 2, wc = (id & 3) * 4;
            CP16(aOff + (unsigned)(r * 20 + wc) * 4,
                 A + (size_t)(row0 + r) * K + kt + wc * 2);
        }
        // B: 64 rows x 16 words = 256 chunks; 128 thr x 2
        unsigned bOff = sB + (unsigned)(st * 64 * 20) * 4;
#pragma unroll
        for (int i = 0; i < 2; i++) {
            int id = tid + i * 128;
            int r = id >> 2, wc = (id & 3) * 4;
            CP16(bOff + (unsigned)(r * 20 + wc) * 4,
                 Wt + (size_t)(col0 + r) * K + kt + wc * 2);
        }
        CP_COMMIT();
    };

    load_tile(0, 0);

    const int rq = lane >> 2, tq = lane & 3;
    const int rb = wm * 64 + rq;      // A frag base row
    const int cq = wn * 32 + rq;      // B frag base col

    for (int t = 0; t < ntiles; t++) {
        CP_WAIT0();
        __syncthreads();
        if (t + 1 < ntiles) load_tile((t + 1) << 5, (t + 1) & 1);

        const unsigned* Ast = As + (t & 1) * 128 * 20;
        const unsigned* Bst = Bs + (t & 1) * 64 * 20;
#pragma unroll
        for (int ks = 0; ks < 2; ks++) {
            const int kw = ks * 8 + tq;
            unsigned af[4][4], bf[4][2];
#pragma unroll
            for (int mi = 0; mi < 4; mi++) {
                const unsigned* Ar = Ast + (rb + mi * 16) * 20;
                af[mi][0] = Ar[kw];
                af[mi][1] = Ar[8 * 20 + kw];
                af[mi][2] = Ar[kw + 4];
                af[mi][3] = Ar[8 * 20 + kw + 4];
            }
#pragma unroll
            for (int ni = 0; ni < 4; ni++) {
                const unsigned* Br = Bst + (cq + ni * 8) * 20;
                bf[ni][0] = Br[kw];
                bf[ni][1] = Br[kw + 4];
            }
#pragma unroll
            for (int mi = 0; mi < 4; mi++)
#pragma unroll
                for (int ni = 0; ni < 4; ni++)
                    mma_bf16(acc[mi][ni], af[mi], bf[ni]);
        }
        __syncthreads();
    }

    const int crow0 = row0 + wm * 64 + rq;
    const int ccol  = col0 + wn * 32 + tq * 2;
#pragma unroll
    for (int mi = 0; mi < 4; mi++) {
#pragma unroll
        for (int half = 0; half < 2; half++) {
            int row = crow0 + mi * 16 + half * 8;
#pragma unroll
            for (int ni = 0; ni < 4; ni++) {
                int col = ccol + ni * 8;
                float v0 = acc[mi][ni][half * 2 + 0] + bias[col];
                float v1 = acc[mi][ni][half * 2 + 1] + bias[col + 1];
                if (EPI == 0) {
                    v0 *= scale; v1 *= scale;
                    *(float2*)((float*)Cm + (size_t)row * N + col) = make_float2(v0, v1);
                } else if (EPI == 1) {
                    float2 rv = *(const float2*)(res + (size_t)row * N + col);
                    *(float2*)((float*)Cm + (size_t)row * N + col) =
                        make_float2(v0 + rv.x, v1 + rv.y);
                } else {
                    *(__nv_bfloat162*)((__nv_bfloat16*)Cm + (size_t)row * N + col) =
                        __floats2bfloat162_rn(gelu_f(v0), gelu_f(v1));
                }
            }
        }
    }
}

// ---------------- KV projection (bf16 xn in) + pooled window scatter -------
__global__ void kvproj_kernel(const __nv_bfloat16* __restrict__ xn,
                              const float* __restrict__ kvw, const float* __restrict__ kvb,
                              float* __restrict__ ko, float* __restrict__ vo)
{
    __shared__ float sx[16][193];
    const int tid  = threadIdx.x;
    const int base = blockIdx.x * 16;
#pragma unroll
    for (int i = 0; i < 16; i++)
        sx[i][tid] = __bfloat162float(xn[(size_t)(base + i) * C + tid]);
    __syncthreads();

    const int t  = tid / 12;
    const int jg = tid % 12;
    float4 bb = *(const float4*)(kvb + jg * 4);
    float s0 = bb.x, s1 = bb.y, s2 = bb.z, s3 = bb.w;
#pragma unroll 8
    for (int c = 0; c < C; c++) {
        float xv = sx[t][c];
        float4 w4 = *(const float4*)(kvw + c * 48 + jg * 4);
        s0 += xv * w4.x; s1 += xv * w4.y; s2 += xv * w4.z; s3 += xv * w4.w;
    }
    int l  = base + t;
    int z  = l >> 12, y = (l >> 6) & 63, x = l & 63;
    int win = ((z >> 3) << 6) | ((y >> 3) << 3) | (x >> 3);
    int zz = z & 7, yy = y & 7, xx = x & 7;
    int m   = ((zz >> 1) << 4) | ((yy >> 1) << 2) | (xx >> 1);
    int sub = ((zz & 1) << 2)  | ((yy & 1) << 1)  | (xx & 1);
    int head = jg % 6;
    float* dst = (jg < 6) ? ko : vo;
    *(float4*)&dst[(((size_t)(win * NHD + head)) * NP + m) * HD + sub * 4] =
        make_float4(s0, s1, s2, s3);
}

// ---------------- attention via tensor cores: block = (window, head) -------
#define ATTN_SMEM_WORDS (64*36 + 32*68 + 128*36 + 8*16*68 + 343)
__global__ void __launch_bounds__(256)
attn_mma_kernel(const float* __restrict__ q, const float* __restrict__ kbuf,
                const float* __restrict__ vbuf, const float* __restrict__ btab,
                __nv_bfloat16* __restrict__ o)
{
    extern __shared__ unsigned sm[];
    unsigned* Ks = sm;                    // [64][36]  K, (m,c)
    unsigned* Vt = Ks + 64 * 36;          // [32][68]  V^T, (c,m)
    unsigned* Qs = Vt + 32 * 68;          // [128][36] Q chunk
    unsigned* Pw = Qs + 128 * 36;         // [8][16][68] per-warp P
    float*    bt = (float*)(Pw + 8 * 16 * 68);  // [343]

    const int win  = blockIdx.x / NHD;
    const int head = blockIdx.x % NHD;
    const int tid = threadIdx.x, lane = tid & 31, w = tid >> 5;
    const int rq = lane >> 2, tq = lane & 3;

    const float* kb = kbuf + (size_t)(win * NHD + head) * NP * HD;
    const float* vb = vbuf + (size_t)(win * NHD + head) * NP * HD;
    for (int i = tid; i < NP * HD; i += 256) {
        int m = i >> 5, c = i & 31;
        Ks[m * 36 + c] = __float_as_uint(kb[i]);
    }
    for (int i = tid; i < NP * HD; i += 256) {
        int c = i >> 6, m = i & 63;
        Vt[c * 68 + m] = __float_as_uint(vb[m * 32 + c]);
    }
    for (int i = tid; i < 343; i += 256) bt[i] = btab[i * NHD + head];

    const int wz = win >> 6, wy = (win >> 3) & 7, wx = win & 7;
    const int wbase = wz * 32768 + wy * 512 + wx * 8;
    unsigned* Pme = Pw + w * 16 * 68;

#pragma unroll 1
    for (int p = 0; p < 4; p++) {
        __syncthreads();
#pragma unroll
        for (int i = 0; i < 4; i++) {
            int idx = tid + i * 256;
            int r = idx >> 3, c4 = (idx & 7) * 4;
            int n = p * 128 + r;
            int l = wbase + (n >> 6) * 4096 + ((n >> 3) & 7) * 64 + (n & 7);
            float4 v4 = *(const float4*)(q + (size_t)l * C + head * HD + c4);
            Qs[r * 36 + c4 + 0] = __float_as_uint(v4.x);
            Qs[r * 36 + c4 + 1] = __float_as_uint(v4.y);
            Qs[r * 36 + c4 + 2] = __float_as_uint(v4.z);
            Qs[r * 36 + c4 + 3] = __float_as_uint(v4.w);
        }
        __syncthreads();

        float s[8][4];
#pragma unroll
        for (int j = 0; j < 8; j++)
#pragma unroll
            for (int t = 0; t < 4; t++) s[j][t] = 0.f;

        const unsigned* Qrow = Qs + (w * 16 + rq) * 36;
#pragma unroll
        for (int kb0 = 0; kb0 < 32; kb0 += 8) {
            unsigned a[4];
            a[0] = Qrow[kb0 + tq];
            a[1] = Qrow[8 * 36 + kb0 + tq];
            a[2] = Qrow[kb0 + tq + 4];
            a[3] = Qrow[8 * 36 + kb0 + tq + 4];
#pragma unroll
            for (int j = 0; j < 8; j++) {
                unsigned b[2];
                const unsigned* Kr = Ks + (j * 8 + rq) * 36 + kb0 + tq;
                b[0] = Kr[0];
                b[1] = Kr[4];
                mma_tf32(s[j], a, b);
            }
        }

        const int n0 = p * 128 + w * 16 + rq;
        const int n1 = n0 + 8;
        int qb0, qb1;
        {
            int zz = n0 >> 6, yy = (n0 >> 3) & 7, xx = n0 & 7;
            qb0 = ((zz >> 1) + 3) * 49 + ((yy >> 1) + 3) * 7 + (xx >> 1) + 3;
            zz = n1 >> 6; yy = (n1 >> 3) & 7; xx = n1 & 7;
            qb1 = ((zz >> 1) + 3) * 49 + ((yy >> 1) + 3) * 7 + (xx >> 1) + 3;
        }
        float mx0 = -1e30f, mx1 = -1e30f;
#pragma unroll
        for (int j = 0; j < 8; j++) {
#pragma unroll
            for (int s2 = 0; s2 < 2; s2++) {
                int m = j * 8 + tq * 2 + s2;
                int koff = (m >> 4) * 49 + ((m >> 2) & 3) * 7 + (m & 3);
                s[j][s2]     += bt[qb0 - koff];
                s[j][2 + s2] += bt[qb1 - koff];
                mx0 = fmaxf(mx0, s[j][s2]);
                mx1 = fmaxf(mx1, s[j][2 + s2]);
            }
        }
        mx0 = fmaxf(mx0, __shfl_xor_sync(0xffffffffu, mx0, 1));
        mx0 = fmaxf(mx0, __shfl_xor_sync(0xffffffffu, mx0, 2));
        mx1 = fmaxf(mx1, __shfl_xor_sync(0xffffffffu, mx1, 1));
        mx1 = fmaxf(mx1, __shfl_xor_sync(0xffffffffu, mx1, 2));
        float sum0 = 0.f, sum1 = 0.f;
#pragma unroll
        for (int j = 0; j < 8; j++) {
#pragma unroll
            for (int s2 = 0; s2 < 2; s2++) {
                s[j][s2]     = __expf(s[j][s2]     - mx0);
                s[j][2 + s2] = __expf(s[j][2 + s2] - mx1);
                sum0 += s[j][s2];
                sum1 += s[j][2 + s2];
            }
        }
        sum0 += __shfl_xor_sync(0xffffffffu, sum0, 1);
        sum0 += __shfl_xor_sync(0xffffffffu, sum0, 2);
        sum1 += __shfl_xor_sync(0xffffffffu, sum1, 1);
        sum1 += __shfl_xor_sync(0xffffffffu, sum1, 2);
        const float inv0 = 1.0f / sum0, inv1 = 1.0f / sum1;

#pragma unroll
        for (int j = 0; j < 8; j++) {
#pragma unroll
            for (int s2 = 0; s2 < 2; s2++) {
                int m = j * 8 + tq * 2 + s2;
                Pme[rq * 68 + m]       = __float_as_uint(s[j][s2] * inv0);
                Pme[(rq + 8) * 68 + m] = __float_as_uint(s[j][2 + s2] * inv1);
            }
        }
        __syncwarp();

        float oa[4][4];
#pragma unroll
        for (int j = 0; j < 4; j++)
#pragma unroll
            for (int t = 0; t < 4; t++) oa[j][t] = 0.f;

        const unsigned* Prow = Pme + rq * 68;
#pragma unroll
        for (int kb0 = 0; kb0 < 64; kb0 += 8) {
            unsigned a[4];
            a[0] = Prow[kb0 + tq];
            a[1] = Prow[8 * 68 + kb0 + tq];
            a[2] = Prow[kb0 + tq + 4];
            a[3] = Prow[8 * 68 + kb0 + tq + 4];
#pragma unroll
            for (int jn = 0; jn < 4; jn++) {
                unsigned b[2];
                const unsigned* Vr = Vt + (jn * 8 + rq) * 68 + kb0 + tq;
                b[0] = Vr[0];
                b[1] = Vr[4];
                mma_tf32(oa[jn], a, b);
            }
        }

        const int l0 = wbase + (n0 >> 6) * 4096 + ((n0 >> 3) & 7) * 64 + (n0 & 7);
        const int l1 = wbase + (n1 >> 6) * 4096 + ((n1 >> 3) & 7) * 64 + (n1 & 7);
        __nv_bfloat16* o0 = o + (size_t)l0 * C + head * HD + tq * 2;
        __nv_bfloat16* o1 = o + (size_t)l1 * C + head * HD + tq * 2;
#pragma unroll
        for (int jn = 0; jn < 4; jn++) {
            *(__nv_bfloat162*)(o0 + jn * 8) = __floats2bfloat162_rn(oa[jn][0], oa[jn][1]);
            *(__nv_bfloat162*)(o1 + jn * 8) = __floats2bfloat162_rn(oa[jn][2], oa[jn][3]);
        }
    }
}

// ---------------- depthwise 3x3x3 conv (bf16 io) + gelu + residual ---------
__global__ void dwconv_kernel(const __nv_bfloat16* __restrict__ hid,
                              const float* __restrict__ wgt, const float* __restrict__ bias,
                              __nv_bfloat16* __restrict__ hdn)
{
    const int c4  = threadIdx.x;          // 0..191
    const int bid = blockIdx.x;           // 0..16383
    const int x0  = (bid & 7) * 8;
    const int y   = (bid >> 3) & 63;
    const int z   = bid >> 9;

    float4 acc[8];
#pragma unroll
    for (int i = 0; i < 8; i++) acc[i] = make_float4(0.f, 0.f, 0.f, 0.f);

    for (int kd = 0; kd < 3; kd++) {
        int zz = z + kd - 1;
        if (zz < 0 || zz >= DD) continue;
        for (int kh = 0; kh < 3; kh++) {
            int yy = y + kh - 1;
            if (yy < 0 || yy >= HHH) continue;
            const __nv_bfloat16* base =
                hid + ((size_t)(zz * HHH + yy) * WWW) * HID + c4 * 4;
            float4 hv[10];
#pragma unroll
            for (int i = 0; i < 10; i++) {
                int xx = x0 - 1 + i;
                hv[i] = (xx >= 0 && xx < WWW) ? ldbf4(base + (size_t)xx * HID)
                                              : make_float4(0.f, 0.f, 0.f, 0.f);
            }
#pragma unroll
            for (int kw = 0; kw < 3; kw++) {
                float4 wv = *(const float4*)(wgt + ((kd * 3 + kh) * 3 + kw) * HID + c4 * 4);
#pragma unroll
                for (int xi = 0; xi < 8; xi++) {
                    acc[xi].x += hv[xi + kw].x * wv.x;
                    acc[xi].y += hv[xi + kw].y * wv.y;
                    acc[xi].z += hv[xi + kw].z * wv.z;
                    acc[xi].w += hv[xi + kw].w * wv.w;
                }
            }
        }
    }
    float4 bv = *(const float4*)(bias + c4 * 4);
#pragma unroll
    for (int xi = 0; xi < 8; xi++) {
        size_t idx = ((size_t)((z * HHH + y) * WWW + x0 + xi)) * HID + c4 * 4;
        float4 h0 = ldbf4(hid + idx);
        float4 o;
        o.x = h0.x + gelu_f(acc[xi].x + bv.x);
        o.y = h0.y + gelu_f(acc[xi].y + bv.y);
        o.z = h0.z + gelu_f(acc[xi].z + bv.z);
        o.w = h0.w + gelu_f(acc[xi].w + bv.w);
        stbf4(hdn + idx, o);
    }
}

// ---------------- launch ----------------------------------------------------
static void* sym_addr(const void* sym) {
    void* p = nullptr;
    cudaGetSymbolAddress(&p, sym);
    return p;
}

extern "C" void kernel_launch(void* const* d_in, const int* in_sizes, int n_in,
                              void* d_out, int out_size)
{
    const float* x    = (const float*)d_in[0];
    const float* n1g  = (const float*)d_in[1];
    const float* n1b  = (const float*)d_in[2];
    const float* q_w  = (const float*)d_in[3];
    const float* q_b  = (const float*)d_in[4];
    const float* kv_w = (const float*)d_in[5];
    const float* kv_b = (const float*)d_in[6];
    const float* btab = (const float*)d_in[7];
    const float* p_w  = (const float*)d_in[8];
    const float* p_b  = (const float*)d_in[9];
    const float* n2g  = (const float*)d_in[10];
    const float* n2b  = (const float*)d_in[11];
    const float* f1w  = (const float*)d_in[12];
    const float* f1b  = (const float*)d_in[13];
    const float* dww  = (const float*)d_in[14];
    const float* dwb  = (const float*)d_in[15];
    const float* f2w  = (const float*)d_in[16];
    const float* f2b  = (const float*)d_in[17];
    float* out = (float*)d_out;

    __nv_bfloat16* xnb  = (__nv_bfloat16*)sym_addr(g_xnb);
    float*         qb_  = (float*)sym_addr(g_q);
    float*         kb_  = (float*)sym_addr(g_k);
    float*         vb_  = (float*)sym_addr(g_v);
    __nv_bfloat16* ob   = (__nv_bfloat16*)sym_addr(g_ob);
    float*         x1   = (float*)sym_addr(g_x1);
    __nv_bfloat16* hidb = (__nv_bfloat16*)sym_addr(g_hidb);
    __nv_bfloat16* hdnb = (__nv_bfloat16*)sym_addr(g_hdnb);
    __nv_bfloat16* qwT  = (__nv_bfloat16*)sym_addr(g_qwT);
    __nv_bfloat16* pwT  = (__nv_bfloat16*)sym_addr(g_pwT);
    __nv_bfloat16* f1wT = (__nv_bfloat16*)sym_addr(g_f1wT);
    __nv_bfloat16* f2wT = (__nv_bfloat16*)sym_addr(g_f2wT);

    const float qscale = 0.17677669529663687f;  // 1/sqrt(32)
    const int attn_smem = ATTN_SMEM_WORDS * 4;
    cudaFuncSetAttribute(attn_mma_kernel,
                         cudaFuncAttributeMaxDynamicSharedMemorySize, attn_smem);

    // 0) convert + transpose weights to bf16 [N][K]
    wconv_kernel<<<(C * C   + 255) / 256, 256>>>(q_w,  qwT,  C,   C);
    wconv_kernel<<<(C * C   + 255) / 256, 256>>>(p_w,  pwT,  C,   C);
    wconv_kernel<<<(C * HID + 255) / 256, 256>>>(f1w,  f1wT, C,   HID);
    wconv_kernel<<<(HID * C + 255) / 256, 256>>>(f2w,  f2wT, HID, C);

    // 1) LN1 -> bf16
    ln_kernel<<<L / 8, 256>>>(x, n1g, n1b, xnb);
    // 2) q = (xn @ q_w + q_b) * scale    [bf16 mma -> fp32]
    gemm_bf16<0><<<dim3(C / 64, L / 128), 128, GEMM_SMEM_BYTES>>>(
        xnb, qwT, q_b, nullptr, qb_, L, C, C, qscale);
    // 3) kv projection + permuted scatter (fp32 math)
    kvproj_kernel<<<L / 16, 192>>>(xnb, kv_w, kv_b, kb_, vb_);
    // 4) windowed attention (tf32 mma) -> bf16 o
    attn_mma_kernel<<<NWIN * NHD, 256, attn_smem>>>(qb_, kb_, vb_, btab, ob);
    // 5) x1 = x + o @ proj_w + proj_b    [bf16 mma -> fp32]
    gemm_bf16<1><<<dim3(C / 64, L / 128), 128, GEMM_SMEM_BYTES>>>(
        ob, pwT, p_b, x, x1, L, C, C, 1.f);
    // 6) LN2 -> bf16
    ln_kernel<<<L / 8, 256>>>(x1, n2g, n2b, xnb);
    // 7) hid = gelu(xn @ fc1_w + fc1_b)  [bf16 mma -> bf16]
    gemm_bf16<2><<<dim3(HID / 64, L / 128), 128, GEMM_SMEM_BYTES>>>(
        xnb, f1wT, f1b, nullptr, hidb, L, HID, C, 1.f);
    // 8) hdn = hid + gelu(dwconv(hid) + dw_b)   [bf16 io]
    dwconv_kernel<<<(DD * HHH * WWW) / 8, 192>>>(hidb, dww, dwb, hdnb);
    // 9) out = x1 + hdn @ fc2_w + fc2_b  [bf16 mma -> fp32]
    gemm_bf16<1><<<dim3(C / 64, L / 128), 128, GEMM_SMEM_BYTES>>>(
        hdnb, f2wT, f2b, x1, out, L, C, HID, 1.f);
}

// round 7
// speedup vs baseline: 3.2054x; 1.0153x over previous
#include <cuda_runtime.h>
#include <cuda_bf16.h>
#include <math.h>

// ---------------- problem constants (fixed by the dataset) ----------------
#define L     131072        // tokens = 32*64*64
#define C     192           // dim
#define NHD   6             // heads
#define HD    32            // head dim
#define NWIN  256           // 4*8*8 windows of 8^3
#define NP    64            // pooled kv tokens per window (4^3)
#define HID   768           // ffn hidden
#define DD    32
#define HHH   64
#define WWW   64

// ---------------- scratch (device globals: allocation-free) ----------------
__device__ __nv_bfloat16 g_xnb [L * C];
__device__ float         g_q   [L * C];
__device__ float         g_k   [NWIN * NHD * NP * HD];
__device__ float         g_v   [NWIN * NHD * NP * HD];
__device__ __nv_bfloat16 g_ob  [L * C];
__device__ float         g_x1  [L * C];
__device__ __nv_bfloat16 g_hidb[L * HID];
__device__ __nv_bfloat16 g_hdnb[L * HID];
__device__ __nv_bfloat16 g_qwT [C * C];
__device__ __nv_bfloat16 g_pwT [C * C];
__device__ __nv_bfloat16 g_f1wT[C * HID];
__device__ __nv_bfloat16 g_f2wT[HID * C];

__device__ __forceinline__ float gelu_f(float v) {
    return 0.5f * v * (1.0f + erff(v * 0.70710678118654752f));
}

__device__ __forceinline__ void mma_tf32(float* d, const unsigned* a, const unsigned* b) {
    asm volatile(
        "mma.sync.aligned.m16n8k8.row.col.f32.tf32.tf32.f32 "
        "{%0,%1,%2,%3},{%4,%5,%6,%7},{%8,%9},{%0,%1,%2,%3};"
        : "+f"(d[0]), "+f"(d[1]), "+f"(d[2]), "+f"(d[3])
        : "r"(a[0]), "r"(a[1]), "r"(a[2]), "r"(a[3]), "r"(b[0]), "r"(b[1]));
}

__device__ __forceinline__ void mma_bf16(float* d, const unsigned* a, const unsigned* b) {
    asm volatile(
        "mma.sync.aligned.m16n8k16.row.col.f32.bf16.bf16.f32 "
        "{%0,%1,%2,%3},{%4,%5,%6,%7},{%8,%9},{%0,%1,%2,%3};"
        : "+f"(d[0]), "+f"(d[1]), "+f"(d[2]), "+f"(d[3])
        : "r"(a[0]), "r"(a[1]), "r"(a[2]), "r"(a[3]), "r"(b[0]), "r"(b[1]));
}

#define CP16(dst_smem_u32, src_ptr) \
    asm volatile("cp.async.cg.shared.global [%0], [%1], 16;\n" \
                 :: "r"(dst_smem_u32), "l"(src_ptr))
#define CP_COMMIT() asm volatile("cp.async.commit_group;\n" ::: "memory")
#define CP_WAIT1()  asm volatile("cp.async.wait_group 1;\n" ::: "memory")

__device__ __forceinline__ float4 ldbf4(const __nv_bfloat16* p) {
    uint2 u = *(const uint2*)p;
    float2 a = __bfloat1622float2(*(__nv_bfloat162*)&u.x);
    float2 b = __bfloat1622float2(*(__nv_bfloat162*)&u.y);
    return make_float4(a.x, a.y, b.x, b.y);
}
__device__ __forceinline__ void stbf4(__nv_bfloat16* p, float4 v) {
    uint2 u;
    *(__nv_bfloat162*)&u.x = __floats2bfloat162_rn(v.x, v.y);
    *(__nv_bfloat162*)&u.y = __floats2bfloat162_rn(v.z, v.w);
    *(uint2*)p = u;
}

// ---------------- weight convert + transpose: wt[n][k] = bf16(w[k][n]) -----
__global__ void wconv_kernel(const float* __restrict__ w, __nv_bfloat16* __restrict__ wt,
                             int K, int N)
{
    int id = blockIdx.x * 256 + threadIdx.x;
    if (id >= K * N) return;
    int k = id / N, n = id % N;
    wt[(size_t)n * K + k] = __float2bfloat16(w[id]);
}

// ---------------- LayerNorm (fp32 in, bf16 out): one warp per token --------
__global__ void ln_kernel(const float* __restrict__ x, const float* __restrict__ g,
                          const float* __restrict__ b, __nv_bfloat16* __restrict__ y)
{
    int lane = threadIdx.x & 31;
    int wi   = threadIdx.x >> 5;
    int l    = blockIdx.x * 8 + wi;
    const float* row = x + (size_t)l * C;
    float v[6];
    float s = 0.f, ss = 0.f;
#pragma unroll
    for (int i = 0; i < 6; i++) {
        v[i] = row[lane + 32 * i];
        s  += v[i];
        ss += v[i] * v[i];
    }
#pragma unroll
    for (int off = 16; off > 0; off >>= 1) {
        s  += __shfl_xor_sync(0xffffffffu, s,  off);
        ss += __shfl_xor_sync(0xffffffffu, ss, off);
    }
    float mean = s * (1.0f / C);
    float var  = ss * (1.0f / C) - mean * mean;
    float inv  = rsqrtf(var + 1e-5f);
    __nv_bfloat16* yr = y + (size_t)l * C;
#pragma unroll
    for (int i = 0; i < 6; i++) {
        int c = lane + 32 * i;
        yr[c] = __float2bfloat16((v[i] - mean) * inv * g[c] + b[c]);
    }
}

// -------- bf16 GEMM: 128x64 block, 4 warps x (64x32), k-step 32 ------------
// 3-stage cp.async pipeline, ONE syncthreads per k-tile.
// A bf16 [M][K], B bf16 [N][K] (pre-transposed). smem rows 20 words.
#define GEMM_SMEM_BYTES ((3 * (128 * 20 + 64 * 20)) * 4)
template <int EPI>
__global__ void __launch_bounds__(128)
gemm_bf16(const __nv_bfloat16* __restrict__ A, const __nv_bfloat16* __restrict__ Wt,
          const float* __restrict__ bias, const float* __restrict__ res,
          void* __restrict__ Cm, int M, int N, int K, float scale)
{
    extern __shared__ unsigned gsm[];
    unsigned* As = gsm;                    // [3][128][20]
    unsigned* Bs = gsm + 3 * 128 * 20;     // [3][64][20]

    const int tid  = threadIdx.x;
    const int lane = tid & 31, warp = tid >> 5;
    const int wm = warp & 1, wn = warp >> 1;
    const int row0 = blockIdx.y * 128, col0 = blockIdx.x * 64;

    float acc[4][4][4];
#pragma unroll
    for (int i = 0; i < 4; i++)
#pragma unroll
        for (int j = 0; j < 4; j++)
#pragma unroll
            for (int t = 0; t < 4; t++) acc[i][j][t] = 0.f;

    const unsigned sA = (unsigned)__cvta_generic_to_shared(As);
    const unsigned sB = (unsigned)__cvta_generic_to_shared(Bs);
    const int ntiles = K >> 5;

    auto load_tile = [&](int kt, int st) {
        unsigned aOff = sA + (unsigned)(st * 128 * 20) * 4;
#pragma unroll
        for (int i = 0; i < 4; i++) {
            int id = tid + i * 128;
            int r = id >> 2, wc = (id & 3) * 4;
            CP16(aOff + (unsigned)(r * 20 + wc) * 4,
                 A + (size_t)(row0 + r) * K + kt + wc * 2);
        }
        unsigned bOff = sB + (unsigned)(st * 64 * 20) * 4;
#pragma unroll
        for (int i = 0; i < 2; i++) {
            int id = tid + i * 128;
            int r = id >> 2, wc = (id & 3) * 4;
            CP16(bOff + (unsigned)(r * 20 + wc) * 4,
                 Wt + (size_t)(col0 + r) * K + kt + wc * 2);
        }
        CP_COMMIT();
    };

    load_tile(0, 0);
    load_tile(32, 1);      // ntiles >= 6 always here

    const int rq = lane >> 2, tq = lane & 3;
    const int rb = wm * 64 + rq;
    const int cq = wn * 32 + rq;

    int st = 0;
    for (int t = 0; t < ntiles; t++) {
        CP_WAIT1();          // tile t's group complete (t+1 may stay in flight)
        __syncthreads();     // also: all warps done with iter t-1 (buffer st+2 free)
        if (t + 2 < ntiles) {
            int st2 = st + 2; if (st2 >= 3) st2 -= 3;
            load_tile((t + 2) << 5, st2);
        }

        const unsigned* Ast = As + st * 128 * 20;
        const unsigned* Bst = Bs + st * 64 * 20;
#pragma unroll
        for (int ks = 0; ks < 2; ks++) {
            const int kw = ks * 8 + tq;
            unsigned af[4][4], bf[4][2];
#pragma unroll
            for (int mi = 0; mi < 4; mi++) {
                const unsigned* Ar = Ast + (rb + mi * 16) * 20;
                af[mi][0] = Ar[kw];
                af[mi][1] = Ar[8 * 20 + kw];
                af[mi][2] = Ar[kw + 4];
                af[mi][3] = Ar[8 * 20 + kw + 4];
            }
#pragma unroll
            for (int ni = 0; ni < 4; ni++) {
                const unsigned* Br = Bst + (cq + ni * 8) * 20;
                bf[ni][0] = Br[kw];
                bf[ni][1] = Br[kw + 4];
            }
#pragma unroll
            for (int mi = 0; mi < 4; mi++)
#pragma unroll
                for (int ni = 0; ni < 4; ni++)
                    mma_bf16(acc[mi][ni], af[mi], bf[ni]);
        }
        if (++st == 3) st = 0;
    }

    const int crow0 = row0 + wm * 64 + rq;
    const int ccol  = col0 + wn * 32 + tq * 2;
#pragma unroll
    for (int mi = 0; mi < 4; mi++) {
#pragma unroll
        for (int half = 0; half < 2; half++) {
            int row = crow0 + mi * 16 + half * 8;
#pragma unroll
            for (int ni = 0; ni < 4; ni++) {
                int col = ccol + ni * 8;
                float v0 = acc[mi][ni][half * 2 + 0] + bias[col];
                float v1 = acc[mi][ni][half * 2 + 1] + bias[col + 1];
                if (EPI == 0) {
                    v0 *= scale; v1 *= scale;
                    *(float2*)((float*)Cm + (size_t)row * N + col) = make_float2(v0, v1);
                } else if (EPI == 1) {
                    float2 rv = *(const float2*)(res + (size_t)row * N + col);
                    *(float2*)((float*)Cm + (size_t)row * N + col) =
                        make_float2(v0 + rv.x, v1 + rv.y);
                } else {
                    *(__nv_bfloat162*)((__nv_bfloat16*)Cm + (size_t)row * N + col) =
                        __floats2bfloat162_rn(gelu_f(v0), gelu_f(v1));
                }
            }
        }
    }
}

// ---------------- KV projection (bf16 xn in) + pooled window scatter -------
__global__ void kvproj_kernel(const __nv_bfloat16* __restrict__ xn,
                              const float* __restrict__ kvw, const float* __restrict__ kvb,
                              float* __restrict__ ko, float* __restrict__ vo)
{
    __shared__ float sx[16][193];
    const int tid  = threadIdx.x;
    const int base = blockIdx.x * 16;
#pragma unroll
    for (int i = 0; i < 16; i++)
        sx[i][tid] = __bfloat162float(xn[(size_t)(base + i) * C + tid]);
    __syncthreads();

    const int t  = tid / 12;
    const int jg = tid % 12;
    float4 bb = *(const float4*)(kvb + jg * 4);
    float s0 = bb.x, s1 = bb.y, s2 = bb.z, s3 = bb.w;
#pragma unroll 8
    for (int c = 0; c < C; c++) {
        float xv = sx[t][c];
        float4 w4 = *(const float4*)(kvw + c * 48 + jg * 4);
        s0 += xv * w4.x; s1 += xv * w4.y; s2 += xv * w4.z; s3 += xv * w4.w;
    }
    int l  = base + t;
    int z  = l >> 12, y = (l >> 6) & 63, x = l & 63;
    int win = ((z >> 3) << 6) | ((y >> 3) << 3) | (x >> 3);
    int zz = z & 7, yy = y & 7, xx = x & 7;
    int m   = ((zz >> 1) << 4) | ((yy >> 1) << 2) | (xx >> 1);
    int sub = ((zz & 1) << 2)  | ((yy & 1) << 1)  | (xx & 1);
    int head = jg % 6;
    float* dst = (jg < 6) ? ko : vo;
    *(float4*)&dst[(((size_t)(win * NHD + head)) * NP + m) * HD + sub * 4] =
        make_float4(s0, s1, s2, s3);
}

// ---------------- attention via tensor cores: block = (window, head) -------
#define ATTN_SMEM_WORDS (64*36 + 32*68 + 128*36 + 8*16*68 + 343)
__global__ void __launch_bounds__(256)
attn_mma_kernel(const float* __restrict__ q, const float* __restrict__ kbuf,
                const float* __restrict__ vbuf, const float* __restrict__ btab,
                __nv_bfloat16* __restrict__ o)
{
    extern __shared__ unsigned sm[];
    unsigned* Ks = sm;
    unsigned* Vt = Ks + 64 * 36;
    unsigned* Qs = Vt + 32 * 68;
    unsigned* Pw = Qs + 128 * 36;
    float*    bt = (float*)(Pw + 8 * 16 * 68);

    const int win  = blockIdx.x / NHD;
    const int head = blockIdx.x % NHD;
    const int tid = threadIdx.x, lane = tid & 31, w = tid >> 5;
    const int rq = lane >> 2, tq = lane & 3;

    const float* kb = kbuf + (size_t)(win * NHD + head) * NP * HD;
    const float* vb = vbuf + (size_t)(win * NHD + head) * NP * HD;
    for (int i = tid; i < NP * HD; i += 256) {
        int m = i >> 5, c = i & 31;
        Ks[m * 36 + c] = __float_as_uint(kb[i]);
    }
    for (int i = tid; i < NP * HD; i += 256) {
        int c = i >> 6, m = i & 63;
        Vt[c * 68 + m] = __float_as_uint(vb[m * 32 + c]);
    }
    for (int i = tid; i < 343; i += 256) bt[i] = btab[i * NHD + head];

    const int wz = win >> 6, wy = (win >> 3) & 7, wx = win & 7;
    const int wbase = wz * 32768 + wy * 512 + wx * 8;
    unsigned* Pme = Pw + w * 16 * 68;

#pragma unroll 1
    for (int p = 0; p < 4; p++) {
        __syncthreads();
#pragma unroll
        for (int i = 0; i < 4; i++) {
            int idx = tid + i * 256;
            int r = idx >> 3, c4 = (idx & 7) * 4;
            int n = p * 128 + r;
            int l = wbase + (n >> 6) * 4096 + ((n >> 3) & 7) * 64 + (n & 7);
            float4 v4 = *(const float4*)(q + (size_t)l * C + head * HD + c4);
            Qs[r * 36 + c4 + 0] = __float_as_uint(v4.x);
            Qs[r * 36 + c4 + 1] = __float_as_uint(v4.y);
            Qs[r * 36 + c4 + 2] = __float_as_uint(v4.z);
            Qs[r * 36 + c4 + 3] = __float_as_uint(v4.w);
        }
        __syncthreads();

        float s[8][4];
#pragma unroll
        for (int j = 0; j < 8; j++)
#pragma unroll
            for (int t = 0; t < 4; t++) s[j][t] = 0.f;

        const unsigned* Qrow = Qs + (w * 16 + rq) * 36;
#pragma unroll
        for (int kb0 = 0; kb0 < 32; kb0 += 8) {
            unsigned a[4];
            a[0] = Qrow[kb0 + tq];
            a[1] = Qrow[8 * 36 + kb0 + tq];
            a[2] = Qrow[kb0 + tq + 4];
            a[3] = Qrow[8 * 36 + kb0 + tq + 4];
#pragma unroll
            for (int j = 0; j < 8; j++) {
                unsigned b[2];
                const unsigned* Kr = Ks + (j * 8 + rq) * 36 + kb0 + tq;
                b[0] = Kr[0];
                b[1] = Kr[4];
                mma_tf32(s[j], a, b);
            }
        }

        const int n0 = p * 128 + w * 16 + rq;
        const int n1 = n0 + 8;
        int qb0, qb1;
        {
            int zz = n0 >> 6, yy = (n0 >> 3) & 7, xx = n0 & 7;
            qb0 = ((zz >> 1) + 3) * 49 + ((yy >> 1) + 3) * 7 + (xx >> 1) + 3;
            zz = n1 >> 6; yy = (n1 >> 3) & 7; xx = n1 & 7;
            qb1 = ((zz >> 1) + 3) * 49 + ((yy >> 1) + 3) * 7 + (xx >> 1) + 3;
        }
        float mx0 = -1e30f, mx1 = -1e30f;
#pragma unroll
        for (int j = 0; j < 8; j++) {
#pragma unroll
            for (int s2 = 0; s2 < 2; s2++) {
                int m = j * 8 + tq * 2 + s2;
                int koff = (m >> 4) * 49 + ((m >> 2) & 3) * 7 + (m & 3);
                s[j][s2]     += bt[qb0 - koff];
                s[j][2 + s2] += bt[qb1 - koff];
                mx0 = fmaxf(mx0, s[j][s2]);
                mx1 = fmaxf(mx1, s[j][2 + s2]);
            }
        }
        mx0 = fmaxf(mx0, __shfl_xor_sync(0xffffffffu, mx0, 1));
        mx0 = fmaxf(mx0, __shfl_xor_sync(0xffffffffu, mx0, 2));
        mx1 = fmaxf(mx1, __shfl_xor_sync(0xffffffffu, mx1, 1));
        mx1 = fmaxf(mx1, __shfl_xor_sync(0xffffffffu, mx1, 2));
        float sum0 = 0.f, sum1 = 0.f;
#pragma unroll
        for (int j = 0; j < 8; j++) {
#pragma unroll
            for (int s2 = 0; s2 < 2; s2++) {
                s[j][s2]     = __expf(s[j][s2]     - mx0);
                s[j][2 + s2] = __expf(s[j][2 + s2] - mx1);
                sum0 += s[j][s2];
                sum1 += s[j][2 + s2];
            }
        }
        sum0 += __shfl_xor_sync(0xffffffffu, sum0, 1);
        sum0 += __shfl_xor_sync(0xffffffffu, sum0, 2);
        sum1 += __shfl_xor_sync(0xffffffffu, sum1, 1);
        sum1 += __shfl_xor_sync(0xffffffffu, sum1, 2);
        const float inv0 = 1.0f / sum0, inv1 = 1.0f / sum1;

#pragma unroll
        for (int j = 0; j < 8; j++) {
#pragma unroll
            for (int s2 = 0; s2 < 2; s2++) {
                int m = j * 8 + tq * 2 + s2;
                Pme[rq * 68 + m]       = __float_as_uint(s[j][s2] * inv0);
                Pme[(rq + 8) * 68 + m] = __float_as_uint(s[j][2 + s2] * inv1);
            }
        }
        __syncwarp();

        float oa[4][4];
#pragma unroll
        for (int j = 0; j < 4; j++)
#pragma unroll
            for (int t = 0; t < 4; t++) oa[j][t] = 0.f;

        const unsigned* Prow = Pme + rq * 68;
#pragma unroll
        for (int kb0 = 0; kb0 < 64; kb0 += 8) {
            unsigned a[4];
            a[0] = Prow[kb0 + tq];
            a[1] = Prow[8 * 68 + kb0 + tq];
            a[2] = Prow[kb0 + tq + 4];
            a[3] = Prow[8 * 68 + kb0 + tq + 4];
#pragma unroll
            for (int jn = 0; jn < 4; jn++) {
                unsigned b[2];
                const unsigned* Vr = Vt + (jn * 8 + rq) * 68 + kb0 + tq;
                b[0] = Vr[0];
                b[1] = Vr[4];
                mma_tf32(oa[jn], a, b);
            }
        }

        const int l0 = wbase + (n0 >> 6) * 4096 + ((n0 >> 3) & 7) * 64 + (n0 & 7);
        const int l1 = wbase + (n1 >> 6) * 4096 + ((n1 >> 3) & 7) * 64 + (n1 & 7);
        __nv_bfloat16* o0 = o + (size_t)l0 * C + head * HD + tq * 2;
        __nv_bfloat16* o1 = o + (size_t)l1 * C + head * HD + tq * 2;
#pragma unroll
        for (int jn = 0; jn < 4; jn++) {
            *(__nv_bfloat162*)(o0 + jn * 8) = __floats2bfloat162_rn(oa[jn][0], oa[jn][1]);
            *(__nv_bfloat162*)(o1 + jn * 8) = __floats2bfloat162_rn(oa[jn][2], oa[jn][3]);
        }
    }
}

// ---------------- depthwise 3x3x3 conv (bf16 io) + gelu + residual ---------
// tile: 2 y-rows x 8 x, rows shared between both y outputs -> 7.5 taps/out.
__global__ void dwconv_kernel(const __nv_bfloat16* __restrict__ hid,
                              const float* __restrict__ wgt, const float* __restrict__ bias,
                              __nv_bfloat16* __restrict__ hdn)
{
    const int c4  = threadIdx.x;          // 0..191
    const int bid = blockIdx.x;           // 0..8191
    const int x0  = (bid & 7) * 8;
    const int y0  = ((bid >> 3) & 31) * 2;
    const int z   = bid >> 8;

    float4 acc[2][8];
#pragma unroll
    for (int yi = 0; yi < 2; yi++)
#pragma unroll
        for (int i = 0; i < 8; i++) acc[yi][i] = make_float4(0.f, 0.f, 0.f, 0.f);

    for (int kd = 0; kd < 3; kd++) {
        int zz = z + kd - 1;
        if (zz < 0 || zz >= DD) continue;
#pragma unroll
        for (int r = 0; r < 4; r++) {         // rows y0-1 .. y0+2
            int yy = y0 - 1 + r;
            if (yy < 0 || yy >= HHH) continue;
            const __nv_bfloat16* base =
                hid + ((size_t)(zz * HHH + yy) * WWW) * HID + c4 * 4;
            float4 hv[10];
#pragma unroll
            for (int i = 0; i < 10; i++) {
                int xx = x0 - 1 + i;
                hv[i] = (xx >= 0 && xx < WWW) ? ldbf4(base + (size_t)xx * HID)
                                              : make_float4(0.f, 0.f, 0.f, 0.f);
            }
            // row r is tap kh=r for output y0 (valid r<=2), tap kh=r-1 for y0+1 (r>=1)
#pragma unroll
            for (int yi = 0; yi < 2; yi++) {
                int kh = r - yi;
                if (kh < 0 || kh > 2) continue;
#pragma unroll
                for (int kw = 0; kw < 3; kw++) {
                    float4 wv = *(const float4*)(wgt + ((kd * 3 + kh) * 3 + kw) * HID + c4 * 4);
#pragma unroll
                    for (int xi = 0; xi < 8; xi++) {
                        acc[yi][xi].x += hv[xi + kw].x * wv.x;
                        acc[yi][xi].y += hv[xi + kw].y * wv.y;
                        acc[yi][xi].z += hv[xi + kw].z * wv.z;
                        acc[yi][xi].w += hv[xi + kw].w * wv.w;
                    }
                }
            }
        }
    }
    float4 bv = *(const float4*)(bias + c4 * 4);
#pragma unroll
    for (int yi = 0; yi < 2; yi++) {
#pragma unroll
        for (int xi = 0; xi < 8; xi++) {
            size_t idx = ((size_t)((z * HHH + y0 + yi) * WWW + x0 + xi)) * HID + c4 * 4;
            float4 h0 = ldbf4(hid + idx);
            float4 o;
            o.x = h0.x + gelu_f(acc[yi][xi].x + bv.x);
            o.y = h0.y + gelu_f(acc[yi][xi].y + bv.y);
            o.z = h0.z + gelu_f(acc[yi][xi].z + bv.z);
            o.w = h0.w + gelu_f(acc[yi][xi].w + bv.w);
            stbf4(hdn + idx, o);
        }
    }
}

// ---------------- launch ----------------------------------------------------
static void* sym_addr(const void* sym) {
    void* p = nullptr;
    cudaGetSymbolAddress(&p, sym);
    return p;
}

extern "C" void kernel_launch(void* const* d_in, const int* in_sizes, int n_in,
                              void* d_out, int out_size)
{
    const float* x    = (const float*)d_in[0];
    const float* n1g  = (const float*)d_in[1];
    const float* n1b  = (const float*)d_in[2];
    const float* q_w  = (const float*)d_in[3];
    const float* q_b  = (const float*)d_in[4];
    const float* kv_w = (const float*)d_in[5];
    const float* kv_b = (const float*)d_in[6];
    const float* btab = (const float*)d_in[7];
    const float* p_w  = (const float*)d_in[8];
    const float* p_b  = (const float*)d_in[9];
    const float* n2g  = (const float*)d_in[10];
    const float* n2b  = (const float*)d_in[11];
    const float* f1w  = (const float*)d_in[12];
    const float* f1b  = (const float*)d_in[13];
    const float* dww  = (const float*)d_in[14];
    const float* dwb  = (const float*)d_in[15];
    const float* f2w  = (const float*)d_in[16];
    const float* f2b  = (const float*)d_in[17];
    float* out = (float*)d_out;

    __nv_bfloat16* xnb  = (__nv_bfloat16*)sym_addr(g_xnb);
    float*         qb_  = (float*)sym_addr(g_q);
    float*         kb_  = (float*)sym_addr(g_k);
    float*         vb_  = (float*)sym_addr(g_v);
    __nv_bfloat16* ob   = (__nv_bfloat16*)sym_addr(g_ob);
    float*         x1   = (float*)sym_addr(g_x1);
    __nv_bfloat16* hidb = (__nv_bfloat16*)sym_addr(g_hidb);
    __nv_bfloat16* hdnb = (__nv_bfloat16*)sym_addr(g_hdnb);
    __nv_bfloat16* qwT  = (__nv_bfloat16*)sym_addr(g_qwT);
    __nv_bfloat16* pwT  = (__nv_bfloat16*)sym_addr(g_pwT);
    __nv_bfloat16* f1wT = (__nv_bfloat16*)sym_addr(g_f1wT);
    __nv_bfloat16* f2wT = (__nv_bfloat16*)sym_addr(g_f2wT);

    const float qscale = 0.17677669529663687f;  // 1/sqrt(32)
    const int attn_smem = ATTN_SMEM_WORDS * 4;
    cudaFuncSetAttribute(attn_mma_kernel,
                         cudaFuncAttributeMaxDynamicSharedMemorySize, attn_smem);
    cudaFuncSetAttribute(gemm_bf16<0>,
                         cudaFuncAttributeMaxDynamicSharedMemorySize, GEMM_SMEM_BYTES);
    cudaFuncSetAttribute(gemm_bf16<1>,
                         cudaFuncAttributeMaxDynamicSharedMemorySize, GEMM_SMEM_BYTES);
    cudaFuncSetAttribute(gemm_bf16<2>,
                         cudaFuncAttributeMaxDynamicSharedMemorySize, GEMM_SMEM_BYTES);

    // 0) convert + transpose weights to bf16 [N][K]
    wconv_kernel<<<(C * C   + 255) / 256, 256>>>(q_w,  qwT,  C,   C);
    wconv_kernel<<<(C * C   + 255) / 256, 256>>>(p_w,  pwT,  C,   C);
    wconv_kernel<<<(C * HID + 255) / 256, 256>>>(f1w,  f1wT, C,   HID);
    wconv_kernel<<<(HID * C + 255) / 256, 256>>>(f2w,  f2wT, HID, C);

    // 1) LN1 -> bf16
    ln_kernel<<<L / 8, 256>>>(x, n1g, n1b, xnb);
    // 2) q = (xn @ q_w + q_b) * scale    [bf16 mma, 3-stage pipe]
    gemm_bf16<0><<<dim3(C / 64, L / 128), 128, GEMM_SMEM_BYTES>>>(
        xnb, qwT, q_b, nullptr, qb_, L, C, C, qscale);
    // 3) kv projection + permuted scatter
    kvproj_kernel<<<L / 16, 192>>>(xnb, kv_w, kv_b, kb_, vb_);
    // 4) windowed attention (tf32 mma) -> bf16 o
    attn_mma_kernel<<<NWIN * NHD, 256, attn_smem>>>(qb_, kb_, vb_, btab, ob);
    // 5) x1 = x + o @ proj_w + proj_b
    gemm_bf16<1><<<dim3(C / 64, L / 128), 128, GEMM_SMEM_BYTES>>>(
        ob, pwT, p_b, x, x1, L, C, C, 1.f);
    // 6) LN2 -> bf16
    ln_kernel<<<L / 8, 256>>>(x1, n2g, n2b, xnb);
    // 7) hid = gelu(xn @ fc1_w + fc1_b)
    gemm_bf16<2><<<dim3(HID / 64, L / 128), 128, GEMM_SMEM_BYTES>>>(
        xnb, f1wT, f1b, nullptr, hidb, L, HID, C, 1.f);
    // 8) hdn = hid + gelu(dwconv(hid) + dw_b)  [y-pair tile]
    dwconv_kernel<<<(DD * HHH * WWW) / 16, 192>>>(hidb, dww, dwb, hdnb);
    // 9) out = x1 + hdn @ fc2_w + fc2_b
    gemm_bf16<1><<<dim3(C / 64, L / 128), 128, GEMM_SMEM_BYTES>>>(
        hdnb, f2wT, f2b, x1, out, L, C, HID, 1.f);
}

// round 8
// speedup vs baseline: 3.2132x; 1.0024x over previous
#include <cuda_runtime.h>
#include <cuda_bf16.h>
#include <math.h>

// ---------------- problem constants (fixed by the dataset) ----------------
#define L     131072        // tokens = 32*64*64
#define C     192           // dim
#define NHD   6             // heads
#define HD    32            // head dim
#define NWIN  256           // 4*8*8 windows of 8^3
#define NP    64            // pooled kv tokens per window (4^3)
#define HID   768           // ffn hidden
#define DD    32
#define HHH   64
#define WWW   64

// ---------------- scratch (device globals: allocation-free) ----------------
__device__ __nv_bfloat16 g_xnb [L * C];
__device__ float         g_q   [L * C];
__device__ float         g_k   [NWIN * NHD * NP * HD];
__device__ float         g_v   [NWIN * NHD * NP * HD];
__device__ __nv_bfloat16 g_ob  [L * C];
__device__ float         g_x1  [L * C];
__device__ __nv_bfloat16 g_hidb[L * HID];
__device__ __nv_bfloat16 g_hdnb[L * HID];
__device__ __nv_bfloat16 g_qwT [C * C];
__device__ __nv_bfloat16 g_pwT [C * C];
__device__ __nv_bfloat16 g_f1wT[C * HID];
__device__ __nv_bfloat16 g_f2wT[HID * C];

__device__ __forceinline__ float gelu_f(float v) {
    return 0.5f * v * (1.0f + erff(v * 0.70710678118654752f));
}

__device__ __forceinline__ void mma_tf32(float* d, const unsigned* a, const unsigned* b) {
    asm volatile(
        "mma.sync.aligned.m16n8k8.row.col.f32.tf32.tf32.f32 "
        "{%0,%1,%2,%3},{%4,%5,%6,%7},{%8,%9},{%0,%1,%2,%3};"
        : "+f"(d[0]), "+f"(d[1]), "+f"(d[2]), "+f"(d[3])
        : "r"(a[0]), "r"(a[1]), "r"(a[2]), "r"(a[3]), "r"(b[0]), "r"(b[1]));
}

__device__ __forceinline__ void mma_bf16(float* d, const unsigned* a, const unsigned* b) {
    asm volatile(
        "mma.sync.aligned.m16n8k16.row.col.f32.bf16.bf16.f32 "
        "{%0,%1,%2,%3},{%4,%5,%6,%7},{%8,%9},{%0,%1,%2,%3};"
        : "+f"(d[0]), "+f"(d[1]), "+f"(d[2]), "+f"(d[3])
        : "r"(a[0]), "r"(a[1]), "r"(a[2]), "r"(a[3]), "r"(b[0]), "r"(b[1]));
}

#define LDSM_X4(r0, r1, r2, r3, addr) \
    asm volatile("ldmatrix.sync.aligned.m8n8.x4.shared.b16 {%0,%1,%2,%3}, [%4];" \
                 : "=r"(r0), "=r"(r1), "=r"(r2), "=r"(r3) : "r"(addr))

#define CP16(dst_smem_u32, src_ptr) \
    asm volatile("cp.async.cg.shared.global [%0], [%1], 16;\n" \
                 :: "r"(dst_smem_u32), "l"(src_ptr))
#define CP_COMMIT() asm volatile("cp.async.commit_group;\n" ::: "memory")
#define CP_WAIT1()  asm volatile("cp.async.wait_group 1;\n" ::: "memory")

__device__ __forceinline__ float4 ldbf4(const __nv_bfloat16* p) {
    uint2 u = *(const uint2*)p;
    float2 a = __bfloat1622float2(*(__nv_bfloat162*)&u.x);
    float2 b = __bfloat1622float2(*(__nv_bfloat162*)&u.y);
    return make_float4(a.x, a.y, b.x, b.y);
}
__device__ __forceinline__ void stbf4(__nv_bfloat16* p, float4 v) {
    uint2 u;
    *(__nv_bfloat162*)&u.x = __floats2bfloat162_rn(v.x, v.y);
    *(__nv_bfloat162*)&u.y = __floats2bfloat162_rn(v.z, v.w);
    *(uint2*)p = u;
}

// ---------------- weight convert + transpose: wt[n][k] = bf16(w[k][n]) -----
__global__ void wconv_kernel(const float* __restrict__ w, __nv_bfloat16* __restrict__ wt,
                             int K, int N)
{
    int id = blockIdx.x * 256 + threadIdx.x;
    if (id >= K * N) return;
    int k = id / N, n = id % N;
    wt[(size_t)n * K + k] = __float2bfloat16(w[id]);
}

// ---------------- LayerNorm (fp32 in, bf16 out): one warp per token --------
__global__ void ln_kernel(const float* __restrict__ x, const float* __restrict__ g,
                          const float* __restrict__ b, __nv_bfloat16* __restrict__ y)
{
    int lane = threadIdx.x & 31;
    int wi   = threadIdx.x >> 5;
    int l    = blockIdx.x * 8 + wi;
    const float* row = x + (size_t)l * C;
    float v[6];
    float s = 0.f, ss = 0.f;
#pragma unroll
    for (int i = 0; i < 6; i++) {
        v[i] = row[lane + 32 * i];
        s  += v[i];
        ss += v[i] * v[i];
    }
#pragma unroll
    for (int off = 16; off > 0; off >>= 1) {
        s  += __shfl_xor_sync(0xffffffffu, s,  off);
        ss += __shfl_xor_sync(0xffffffffu, ss, off);
    }
    float mean = s * (1.0f / C);
    float var  = ss * (1.0f / C) - mean * mean;
    float inv  = rsqrtf(var + 1e-5f);
    __nv_bfloat16* yr = y + (size_t)l * C;
#pragma unroll
    for (int i = 0; i < 6; i++) {
        int c = lane + 32 * i;
        yr[c] = __float2bfloat16((v[i] - mean) * inv * g[c] + b[c]);
    }
}

// -------- bf16 GEMM: 128x64 block, 4 warps x (64x32), ldmatrix frags -------
// 3-stage cp.async pipeline, one syncthreads per k-tile, LDSM fragment loads.
#define GEMM_SMEM_BYTES ((3 * (128 * 20 + 64 * 20)) * 4)
template <int EPI>
__global__ void __launch_bounds__(128)
gemm_bf16(const __nv_bfloat16* __restrict__ A, const __nv_bfloat16* __restrict__ Wt,
          const float* __restrict__ bias, const float* __restrict__ res,
          void* __restrict__ Cm, int M, int N, int K, float scale)
{
    extern __shared__ unsigned gsm[];
    unsigned* As = gsm;                    // [3][128][20]
    unsigned* Bs = gsm + 3 * 128 * 20;     // [3][64][20]

    const int tid  = threadIdx.x;
    const int lane = tid & 31, warp = tid >> 5;
    const int wm = warp & 1, wn = warp >> 1;
    const int row0 = blockIdx.y * 128, col0 = blockIdx.x * 64;

    float acc[4][4][4];
#pragma unroll
    for (int i = 0; i < 4; i++)
#pragma unroll
        for (int j = 0; j < 4; j++)
#pragma unroll
            for (int t = 0; t < 4; t++) acc[i][j][t] = 0.f;

    const unsigned sA = (unsigned)__cvta_generic_to_shared(As);
    const unsigned sB = (unsigned)__cvta_generic_to_shared(Bs);
    const int ntiles = K >> 5;

    auto load_tile = [&](int kt, int st) {
        unsigned aOff = sA + (unsigned)(st * 128 * 20) * 4;
#pragma unroll
        for (int i = 0; i < 4; i++) {
            int id = tid + i * 128;
            int r = id >> 2, wc = (id & 3) * 4;
            CP16(aOff + (unsigned)(r * 20 + wc) * 4,
                 A + (size_t)(row0 + r) * K + kt + wc * 2);
        }
        unsigned bOff = sB + (unsigned)(st * 64 * 20) * 4;
#pragma unroll
        for (int i = 0; i < 2; i++) {
            int id = tid + i * 128;
            int r = id >> 2, wc = (id & 3) * 4;
            CP16(bOff + (unsigned)(r * 20 + wc) * 4,
                 Wt + (size_t)(col0 + r) * K + kt + wc * 2);
        }
        CP_COMMIT();
    };

    load_tile(0, 0);
    load_tile(32, 1);      // K >= 192 -> ntiles >= 6

    // ldmatrix lane-derived offsets (in words)
    const int a_row_sel = lane & 15;                       // row within m16
    const int a_k_sel   = (lane >> 4) * 4;                 // 16B k-chunk
    const int b_row_sel = (lane & 7) + (lane >> 4) * 8;    // n row within 16
    const int b_k_sel   = ((lane >> 3) & 1) * 4;           // 16B k-chunk
    const int rb0 = wm * 64;
    const int cb0 = wn * 32;

    int st = 0;
    for (int t = 0; t < ntiles; t++) {
        CP_WAIT1();
        __syncthreads();
        if (t + 2 < ntiles) {
            int st2 = st + 2; if (st2 >= 3) st2 -= 3;
            load_tile((t + 2) << 5, st2);
        }

        const unsigned sAst = sA + (unsigned)(st * 128 * 20) * 4;
        const unsigned sBst = sB + (unsigned)(st * 64 * 20) * 4;
#pragma unroll
        for (int ks = 0; ks < 2; ks++) {
            const int koff = ks * 8;   // 32B in words
            unsigned af[4][4], bf[4][2];
#pragma unroll
            for (int mi = 0; mi < 4; mi++) {
                unsigned addr = sAst +
                    (unsigned)(((rb0 + mi * 16 + a_row_sel) * 20 + a_k_sel + koff) * 4);
                LDSM_X4(af[mi][0], af[mi][1], af[mi][2], af[mi][3], addr);
            }
#pragma unroll
            for (int g = 0; g < 2; g++) {
                unsigned r0, r1, r2, r3;
                unsigned addr = sBst +
                    (unsigned)(((cb0 + g * 16 + b_row_sel) * 20 + b_k_sel + koff) * 4);
                LDSM_X4(r0, r1, r2, r3, addr);
                bf[g * 2 + 0][0] = r0; bf[g * 2 + 0][1] = r1;
                bf[g * 2 + 1][0] = r2; bf[g * 2 + 1][1] = r3;
            }
#pragma unroll
            for (int mi = 0; mi < 4; mi++)
#pragma unroll
                for (int ni = 0; ni < 4; ni++)
                    mma_bf16(acc[mi][ni], af[mi], bf[ni]);
        }
        if (++st == 3) st = 0;
    }

    const int rq = lane >> 2, tq = lane & 3;
    const int crow0 = row0 + wm * 64 + rq;
    const int ccol  = col0 + wn * 32 + tq * 2;
#pragma unroll
    for (int mi = 0; mi < 4; mi++) {
#pragma unroll
        for (int half = 0; half < 2; half++) {
            int row = crow0 + mi * 16 + half * 8;
#pragma unroll
            for (int ni = 0; ni < 4; ni++) {
                int col = ccol + ni * 8;
                float v0 = acc[mi][ni][half * 2 + 0] + bias[col];
                float v1 = acc[mi][ni][half * 2 + 1] + bias[col + 1];
                if (EPI == 0) {
                    v0 *= scale; v1 *= scale;
                    *(float2*)((float*)Cm + (size_t)row * N + col) = make_float2(v0, v1);
                } else if (EPI == 1) {
                    float2 rv = *(const float2*)(res + (size_t)row * N + col);
                    *(float2*)((float*)Cm + (size_t)row * N + col) =
                        make_float2(v0 + rv.x, v1 + rv.y);
                } else {
                    *(__nv_bfloat162*)((__nv_bfloat16*)Cm + (size_t)row * N + col) =
                        __floats2bfloat162_rn(gelu_f(v0), gelu_f(v1));
                }
            }
        }
    }
}

// ---------------- KV projection (bf16 xn in) + pooled window scatter -------
__global__ void kvproj_kernel(const __nv_bfloat16* __restrict__ xn,
                              const float* __restrict__ kvw, const float* __restrict__ kvb,
                              float* __restrict__ ko, float* __restrict__ vo)
{
    __shared__ float sx[16][193];
    const int tid  = threadIdx.x;
    const int base = blockIdx.x * 16;
#pragma unroll
    for (int i = 0; i < 16; i++)
        sx[i][tid] = __bfloat162float(xn[(size_t)(base + i) * C + tid]);
    __syncthreads();

    const int t  = tid / 12;
    const int jg = tid % 12;
    float4 bb = *(const float4*)(kvb + jg * 4);
    float s0 = bb.x, s1 = bb.y, s2 = bb.z, s3 = bb.w;
#pragma unroll 8
    for (int c = 0; c < C; c++) {
        float xv = sx[t][c];
        float4 w4 = *(const float4*)(kvw + c * 48 + jg * 4);
        s0 += xv * w4.x; s1 += xv * w4.y; s2 += xv * w4.z; s3 += xv * w4.w;
    }
    int l  = base + t;
    int z  = l >> 12, y = (l >> 6) & 63, x = l & 63;
    int win = ((z >> 3) << 6) | ((y >> 3) << 3) | (x >> 3);
    int zz = z & 7, yy = y & 7, xx = x & 7;
    int m   = ((zz >> 1) << 4) | ((yy >> 1) << 2) | (xx >> 1);
    int sub = ((zz & 1) << 2)  | ((yy & 1) << 1)  | (xx & 1);
    int head = jg % 6;
    float* dst = (jg < 6) ? ko : vo;
    *(float4*)&dst[(((size_t)(win * NHD + head)) * NP + m) * HD + sub * 4] =
        make_float4(s0, s1, s2, s3);
}

// ---------------- attention via tensor cores: block = (window, head) -------
#define ATTN_SMEM_WORDS (64*36 + 32*68 + 128*36 + 8*16*68 + 343)
__global__ void __launch_bounds__(256)
attn_mma_kernel(const float* __restrict__ q, const float* __restrict__ kbuf,
                const float* __restrict__ vbuf, const float* __restrict__ btab,
                __nv_bfloat16* __restrict__ o)
{
    extern __shared__ unsigned sm[];
    unsigned* Ks = sm;
    unsigned* Vt = Ks + 64 * 36;
    unsigned* Qs = Vt + 32 * 68;
    unsigned* Pw = Qs + 128 * 36;
    float*    bt = (float*)(Pw + 8 * 16 * 68);

    const int win  = blockIdx.x / NHD;
    const int head = blockIdx.x % NHD;
    const int tid = threadIdx.x, lane = tid & 31, w = tid >> 5;
    const int rq = lane >> 2, tq = lane & 3;

    const float* kb = kbuf + (size_t)(win * NHD + head) * NP * HD;
    const float* vb = vbuf + (size_t)(win * NHD + head) * NP * HD;
    for (int i = tid; i < NP * HD; i += 256) {
        int m = i >> 5, c = i & 31;
        Ks[m * 36 + c] = __float_as_uint(kb[i]);
    }
    for (int i = tid; i < NP * HD; i += 256) {
        int c = i >> 6, m = i & 63;
        Vt[c * 68 + m] = __float_as_uint(vb[m * 32 + c]);
    }
    for (int i = tid; i < 343; i += 256) bt[i] = btab[i * NHD + head];

    const int wz = win >> 6, wy = (win >> 3) & 7, wx = win & 7;
    const int wbase = wz * 32768 + wy * 512 + wx * 8;
    unsigned* Pme = Pw + w * 16 * 68;

#pragma unroll 1
    for (int p = 0; p < 4; p++) {
        __syncthreads();
#pragma unroll
        for (int i = 0; i < 4; i++) {
            int idx = tid + i * 256;
            int r = idx >> 3, c4 = (idx & 7) * 4;
            int n = p * 128 + r;
            int l = wbase + (n >> 6) * 4096 + ((n >> 3) & 7) * 64 + (n & 7);
            float4 v4 = *(const float4*)(q + (size_t)l * C + head * HD + c4);
            Qs[r * 36 + c4 + 0] = __float_as_uint(v4.x);
            Qs[r * 36 + c4 + 1] = __float_as_uint(v4.y);
            Qs[r * 36 + c4 + 2] = __float_as_uint(v4.z);
            Qs[r * 36 + c4 + 3] = __float_as_uint(v4.w);
        }
        __syncthreads();

        float s[8][4];
#pragma unroll
        for (int j = 0; j < 8; j++)
#pragma unroll
            for (int t = 0; t < 4; t++) s[j][t] = 0.f;

        const unsigned* Qrow = Qs + (w * 16 + rq) * 36;
#pragma unroll
        for (int kb0 = 0; kb0 < 32; kb0 += 8) {
            unsigned a[4];
            a[0] = Qrow[kb0 + tq];
            a[1] = Qrow[8 * 36 + kb0 + tq];
            a[2] = Qrow[kb0 + tq + 4];
            a[3] = Qrow[8 * 36 + kb0 + tq + 4];
#pragma unroll
            for (int j = 0; j < 8; j++) {
                unsigned b[2];
                const unsigned* Kr = Ks + (j * 8 + rq) * 36 + kb0 + tq;
                b[0] = Kr[0];
                b[1] = Kr[4];
                mma_tf32(s[j], a, b);
            }
        }

        const int n0 = p * 128 + w * 16 + rq;
        const int n1 = n0 + 8;
        int qb0, qb1;
        {
            int zz = n0 >> 6, yy = (n0 >> 3) & 7, xx = n0 & 7;
            qb0 = ((zz >> 1) + 3) * 49 + ((yy >> 1) + 3) * 7 + (xx >> 1) + 3;
            zz = n1 >> 6; yy = (n1 >> 3) & 7; xx = n1 & 7;
            qb1 = ((zz >> 1) + 3) * 49 + ((yy >> 1) + 3) * 7 + (xx >> 1) + 3;
        }
        float mx0 = -1e30f, mx1 = -1e30f;
#pragma unroll
        for (int j = 0; j < 8; j++) {
#pragma unroll
            for (int s2 = 0; s2 < 2; s2++) {
                int m = j * 8 + tq * 2 + s2;
                int koff = (m >> 4) * 49 + ((m >> 2) & 3) * 7 + (m & 3);
                s[j][s2]     += bt[qb0 - koff];
                s[j][2 + s2] += bt[qb1 - koff];
                mx0 = fmaxf(mx0, s[j][s2]);
                mx1 = fmaxf(mx1, s[j][2 + s2]);
            }
        }
        mx0 = fmaxf(mx0, __shfl_xor_sync(0xffffffffu, mx0, 1));
        mx0 = fmaxf(mx0, __shfl_xor_sync(0xffffffffu, mx0, 2));
        mx1 = fmaxf(mx1, __shfl_xor_sync(0xffffffffu, mx1, 1));
        mx1 = fmaxf(mx1, __shfl_xor_sync(0xffffffffu, mx1, 2));
        float sum0 = 0.f, sum1 = 0.f;
#pragma unroll
        for (int j = 0; j < 8; j++) {
#pragma unroll
            for (int s2 = 0; s2 < 2; s2++) {
                s[j][s2]     = __expf(s[j][s2]     - mx0);
                s[j][2 + s2] = __expf(s[j][2 + s2] - mx1);
                sum0 += s[j][s2];
                sum1 += s[j][2 + s2];
            }
        }
        sum0 += __shfl_xor_sync(0xffffffffu, sum0, 1);
        sum0 += __shfl_xor_sync(0xffffffffu, sum0, 2);
        sum1 += __shfl_xor_sync(0xffffffffu, sum1, 1);
        sum1 += __shfl_xor_sync(0xffffffffu, sum1, 2);
        const float inv0 = 1.0f / sum0, inv1 = 1.0f / sum1;

#pragma unroll
        for (int j = 0; j < 8; j++) {
#pragma unroll
            for (int s2 = 0; s2 < 2; s2++) {
                int m = j * 8 + tq * 2 + s2;
                Pme[rq * 68 + m]       = __float_as_uint(s[j][s2] * inv0);
                Pme[(rq + 8) * 68 + m] = __float_as_uint(s[j][2 + s2] * inv1);
            }
        }
        __syncwarp();

        float oa[4][4];
#pragma unroll
        for (int j = 0; j < 4; j++)
#pragma unroll
            for (int t = 0; t < 4; t++) oa[j][t] = 0.f;

        const unsigned* Prow = Pme + rq * 68;
#pragma unroll
        for (int kb0 = 0; kb0 < 64; kb0 += 8) {
            unsigned a[4];
            a[0] = Prow[kb0 + tq];
            a[1] = Prow[8 * 68 + kb0 + tq];
            a[2] = Prow[kb0 + tq + 4];
            a[3] = Prow[8 * 68 + kb0 + tq + 4];
#pragma unroll
            for (int jn = 0; jn < 4; jn++) {
                unsigned b[2];
                const unsigned* Vr = Vt + (jn * 8 + rq) * 68 + kb0 + tq;
                b[0] = Vr[0];
                b[1] = Vr[4];
                mma_tf32(oa[jn], a, b);
            }
        }

        const int l0 = wbase + (n0 >> 6) * 4096 + ((n0 >> 3) & 7) * 64 + (n0 & 7);
        const int l1 = wbase + (n1 >> 6) * 4096 + ((n1 >> 3) & 7) * 64 + (n1 & 7);
        __nv_bfloat16* o0 = o + (size_t)l0 * C + head * HD + tq * 2;
        __nv_bfloat16* o1 = o + (size_t)l1 * C + head * HD + tq * 2;
#pragma unroll
        for (int jn = 0; jn < 4; jn++) {
            *(__nv_bfloat162*)(o0 + jn * 8) = __floats2bfloat162_rn(oa[jn][0], oa[jn][1]);
            *(__nv_bfloat162*)(o1 + jn * 8) = __floats2bfloat162_rn(oa[jn][2], oa[jn][3]);
        }
    }
}

// ---------------- depthwise 3x3x3 conv (bf16 io) + gelu + residual ---------
__global__ void dwconv_kernel(const __nv_bfloat16* __restrict__ hid,
                              const float* __restrict__ wgt, const float* __restrict__ bias,
                              __nv_bfloat16* __restrict__ hdn)
{
    const int c4  = threadIdx.x;
    const int bid = blockIdx.x;
    const int x0  = (bid & 7) * 8;
    const int y0  = ((bid >> 3) & 31) * 2;
    const int z   = bid >> 8;

    float4 acc[2][8];
#pragma unroll
    for (int yi = 0; yi < 2; yi++)
#pragma unroll
        for (int i = 0; i < 8; i++) acc[yi][i] = make_float4(0.f, 0.f, 0.f, 0.f);

    for (int kd = 0; kd < 3; kd++) {
        int zz = z + kd - 1;
        if (zz < 0 || zz >= DD) continue;
#pragma unroll
        for (int r = 0; r < 4; r++) {
            int yy = y0 - 1 + r;
            if (yy < 0 || yy >= HHH) continue;
            const __nv_bfloat16* base =
                hid + ((size_t)(zz * HHH + yy) * WWW) * HID + c4 * 4;
            float4 hv[10];
#pragma unroll
            for (int i = 0; i < 10; i++) {
                int xx = x0 - 1 + i;
                hv[i] = (xx >= 0 && xx < WWW) ? ldbf4(base + (size_t)xx * HID)
                                              : make_float4(0.f, 0.f, 0.f, 0.f);
            }
#pragma unroll
            for (int yi = 0; yi < 2; yi++) {
                int kh = r - yi;
                if (kh < 0 || kh > 2) continue;
#pragma unroll
                for (int kw = 0; kw < 3; kw++) {
                    float4 wv = *(const float4*)(wgt + ((kd * 3 + kh) * 3 + kw) * HID + c4 * 4);
#pragma unroll
                    for (int xi = 0; xi < 8; xi++) {
                        acc[yi][xi].x += hv[xi + kw].x * wv.x;
                        acc[yi][xi].y += hv[xi + kw].y * wv.y;
                        acc[yi][xi].z += hv[xi + kw].z * wv.z;
                        acc[yi][xi].w += hv[xi + kw].w * wv.w;
                    }
                }
            }
        }
    }
    float4 bv = *(const float4*)(bias + c4 * 4);
#pragma unroll
    for (int yi = 0; yi < 2; yi++) {
#pragma unroll
        for (int xi = 0; xi < 8; xi++) {
            size_t idx = ((size_t)((z * HHH + y0 + yi) * WWW + x0 + xi)) * HID + c4 * 4;
            float4 h0 = ldbf4(hid + idx);
            float4 o;
            o.x = h0.x + gelu_f(acc[yi][xi].x + bv.x);
            o.y = h0.y + gelu_f(acc[yi][xi].y + bv.y);
            o.z = h0.z + gelu_f(acc[yi][xi].z + bv.z);
            o.w = h0.w + gelu_f(acc[yi][xi].w + bv.w);
            stbf4(hdn + idx, o);
        }
    }
}

// ---------------- launch ----------------------------------------------------
static void* sym_addr(const void* sym) {
    void* p = nullptr;
    cudaGetSymbolAddress(&p, sym);
    return p;
}

extern "C" void kernel_launch(void* const* d_in, const int* in_sizes, int n_in,
                              void* d_out, int out_size)
{
    const float* x    = (const float*)d_in[0];
    const float* n1g  = (const float*)d_in[1];
    const float* n1b  = (const float*)d_in[2];
    const float* q_w  = (const float*)d_in[3];
    const float* q_b  = (const float*)d_in[4];
    const float* kv_w = (const float*)d_in[5];
    const float* kv_b = (const float*)d_in[6];
    const float* btab = (const float*)d_in[7];
    const float* p_w  = (const float*)d_in[8];
    const float* p_b  = (const float*)d_in[9];
    const float* n2g  = (const float*)d_in[10];
    const float* n2b  = (const float*)d_in[11];
    const float* f1w  = (const float*)d_in[12];
    const float* f1b  = (const float*)d_in[13];
    const float* dww  = (const float*)d_in[14];
    const float* dwb  = (const float*)d_in[15];
    const float* f2w  = (const float*)d_in[16];
    const float* f2b  = (const float*)d_in[17];
    float* out = (float*)d_out;

    __nv_bfloat16* xnb  = (__nv_bfloat16*)sym_addr(g_xnb);
    float*         qb_  = (float*)sym_addr(g_q);
    float*         kb_  = (float*)sym_addr(g_k);
    float*         vb_  = (float*)sym_addr(g_v);
    __nv_bfloat16* ob   = (__nv_bfloat16*)sym_addr(g_ob);
    float*         x1   = (float*)sym_addr(g_x1);
    __nv_bfloat16* hidb = (__nv_bfloat16*)sym_addr(g_hidb);
    __nv_bfloat16* hdnb = (__nv_bfloat16*)sym_addr(g_hdnb);
    __nv_bfloat16* qwT  = (__nv_bfloat16*)sym_addr(g_qwT);
    __nv_bfloat16* pwT  = (__nv_bfloat16*)sym_addr(g_pwT);
    __nv_bfloat16* f1wT = (__nv_bfloat16*)sym_addr(g_f1wT);
    __nv_bfloat16* f2wT = (__nv_bfloat16*)sym_addr(g_f2wT);

    const float qscale = 0.17677669529663687f;  // 1/sqrt(32)
    const int attn_smem = ATTN_SMEM_WORDS * 4;
    cudaFuncSetAttribute(attn_mma_kernel,
                         cudaFuncAttributeMaxDynamicSharedMemorySize, attn_smem);
    cudaFuncSetAttribute(gemm_bf16<0>,
                         cudaFuncAttributeMaxDynamicSharedMemorySize, GEMM_SMEM_BYTES);
    cudaFuncSetAttribute(gemm_bf16<1>,
                         cudaFuncAttributeMaxDynamicSharedMemorySize, GEMM_SMEM_BYTES);
    cudaFuncSetAttribute(gemm_bf16<2>,
                         cudaFuncAttributeMaxDynamicSharedMemorySize, GEMM_SMEM_BYTES);

    // 0) convert + transpose weights to bf16 [N][K]
    wconv_kernel<<<(C * C   + 255) / 256, 256>>>(q_w,  qwT,  C,   C);
    wconv_kernel<<<(C * C   + 255) / 256, 256>>>(p_w,  pwT,  C,   C);
    wconv_kernel<<<(C * HID + 255) / 256, 256>>>(f1w,  f1wT, C,   HID);
    wconv_kernel<<<(HID * C + 255) / 256, 256>>>(f2w,  f2wT, HID, C);

    // 1) LN1 -> bf16
    ln_kernel<<<L / 8, 256>>>(x, n1g, n1b, xnb);
    // 2) q = (xn @ q_w + q_b) * scale    [bf16 mma + ldmatrix]
    gemm_bf16<0><<<dim3(C / 64, L / 128), 128, GEMM_SMEM_BYTES>>>(
        xnb, qwT, q_b, nullptr, qb_, L, C, C, qscale);
    // 3) kv projection + permuted scatter
    kvproj_kernel<<<L / 16, 192>>>(xnb, kv_w, kv_b, kb_, vb_);
    // 4) windowed attention (tf32 mma) -> bf16 o
    attn_mma_kernel<<<NWIN * NHD, 256, attn_smem>>>(qb_, kb_, vb_, btab, ob);
    // 5) x1 = x + o @ proj_w + proj_b
    gemm_bf16<1><<<dim3(C / 64, L / 128), 128, GEMM_SMEM_BYTES>>>(
        ob, pwT, p_b, x, x1, L, C, C, 1.f);
    // 6) LN2 -> bf16
    ln_kernel<<<L / 8, 256>>>(x1, n2g, n2b, xnb);
    // 7) hid = gelu(xn @ fc1_w + fc1_b)
    gemm_bf16<2><<<dim3(HID / 64, L / 128), 128, GEMM_SMEM_BYTES>>>(
        xnb, f1wT, f1b, nullptr, hidb, L, HID, C, 1.f);
    // 8) hdn = hid + gelu(dwconv(hid) + dw_b)
    dwconv_kernel<<<(DD * HHH * WWW) / 16, 192>>>(hidb, dww, dwb, hdnb);
    // 9) out = x1 + hdn @ fc2_w + fc2_b
    gemm_bf16<1><<<dim3(C / 64, L / 128), 128, GEMM_SMEM_BYTES>>>(
        hdnb, f2wT, f2b, x1, out, L, C, HID, 1.f);
}

// round 9
// speedup vs baseline: 3.6451x; 1.1344x over previous
#include <cuda_runtime.h>
#include <cuda_bf16.h>
#include <math.h>

// ---------------- problem constants ----------------
#define L     131072
#define C     192
#define NHD   6
#define HD    32
#define NWIN  256
#define NP    64
#define HID   768
#define DD    32
#define HHH   64
#define WWW   64

// ---------------- scratch ----------------
__device__ __nv_bfloat16 g_xnb [L * C];
__device__ float         g_q   [L * C];
__device__ float         g_k   [NWIN * NHD * NP * HD];
__device__ float         g_v   [NWIN * NHD * NP * HD];
__device__ __nv_bfloat16 g_ob  [L * C];
__device__ float         g_x1  [L * C];
__device__ __nv_bfloat16 g_hidb[L * HID];
__device__ __nv_bfloat16 g_hdnb[L * HID];
__device__ __nv_bfloat16 g_qkvT[256 * C];     // fused q(+scale)+kv weights [n][k]
__device__ float         g_qkvb[256];
__device__ __nv_bfloat16 g_pwT [C * C];
__device__ __nv_bfloat16 g_f1wT[HID * C];
__device__ __nv_bfloat16 g_f2wT[C * HID];

__device__ __forceinline__ float gelu_f(float v) {
    return 0.5f * v * (1.0f + erff(v * 0.70710678118654752f));
}

__device__ __forceinline__ void mma_tf32(float* d, const unsigned* a, const unsigned* b) {
    asm volatile(
        "mma.sync.aligned.m16n8k8.row.col.f32.tf32.tf32.f32 "
        "{%0,%1,%2,%3},{%4,%5,%6,%7},{%8,%9},{%0,%1,%2,%3};"
        : "+f"(d[0]), "+f"(d[1]), "+f"(d[2]), "+f"(d[3])
        : "r"(a[0]), "r"(a[1]), "r"(a[2]), "r"(a[3]), "r"(b[0]), "r"(b[1]));
}

__device__ __forceinline__ void mma_bf16(float* d, const unsigned* a, const unsigned* b) {
    asm volatile(
        "mma.sync.aligned.m16n8k16.row.col.f32.bf16.bf16.f32 "
        "{%0,%1,%2,%3},{%4,%5,%6,%7},{%8,%9},{%0,%1,%2,%3};"
        : "+f"(d[0]), "+f"(d[1]), "+f"(d[2]), "+f"(d[3])
        : "r"(a[0]), "r"(a[1]), "r"(a[2]), "r"(a[3]), "r"(b[0]), "r"(b[1]));
}

#define LDSM_X4(r0, r1, r2, r3, addr) \
    asm volatile("ldmatrix.sync.aligned.m8n8.x4.shared.b16 {%0,%1,%2,%3}, [%4];" \
                 : "=r"(r0), "=r"(r1), "=r"(r2), "=r"(r3) : "r"(addr))

#define CP16(dst_smem_u32, src_ptr) \
    asm volatile("cp.async.cg.shared.global [%0], [%1], 16;\n" \
                 :: "r"(dst_smem_u32), "l"(src_ptr))
#define CP_COMMIT() asm volatile("cp.async.commit_group;\n" ::: "memory")
#define CP_WAIT1()  asm volatile("cp.async.wait_group 1;\n" ::: "memory")

__device__ __forceinline__ float4 ldbf4(const __nv_bfloat16* p) {
    uint2 u = *(const uint2*)p;
    float2 a = __bfloat1622float2(*(__nv_bfloat162*)&u.x);
    float2 b = __bfloat1622float2(*(__nv_bfloat162*)&u.y);
    return make_float4(a.x, a.y, b.x, b.y);
}
__device__ __forceinline__ void stbf4(__nv_bfloat16* p, float4 v) {
    uint2 u;
    *(__nv_bfloat162*)&u.x = __floats2bfloat162_rn(v.x, v.y);
    *(__nv_bfloat162*)&u.y = __floats2bfloat162_rn(v.z, v.w);
    *(uint2*)p = u;
}

// ------------- prep: all weight transposes/converts + fused qkv ------------
#define PREP_R0 (256 * 192)
#define PREP_R1 (PREP_R0 + 192 * 192)
#define PREP_R2 (PREP_R1 + 768 * 192)
#define PREP_R3 (PREP_R2 + 192 * 768)
__global__ void prep_kernel(const float* __restrict__ q_w, const float* __restrict__ q_b,
                            const float* __restrict__ kv_w, const float* __restrict__ kv_b,
                            const float* __restrict__ p_w, const float* __restrict__ f1w,
                            const float* __restrict__ f2w)
{
    const float qscale = 0.17677669529663687f;
    int id = blockIdx.x * 256 + threadIdx.x;
    if (id < 256) {
        float b = 0.f;
        if (id < 192)      b = q_b[id] * qscale;
        else if (id < 240) b = kv_b[id - 192];
        g_qkvb[id] = b;
    }
    if (id < PREP_R0) {
        int n = id / 192, k = id % 192;
        float v = 0.f;
        if (n < 192)      v = q_w[k * 192 + n] * qscale;
        else if (n < 240) v = kv_w[k * 48 + (n - 192)];
        g_qkvT[n * 192 + k] = __float2bfloat16(v);
    } else if (id < PREP_R1) {
        int e = id - PREP_R0, n = e / 192, k = e % 192;
        g_pwT[n * 192 + k] = __float2bfloat16(p_w[k * 192 + n]);
    } else if (id < PREP_R2) {
        int e = id - PREP_R1, n = e / 192, k = e % 192;
        g_f1wT[n * 192 + k] = __float2bfloat16(f1w[k * 768 + n]);
    } else if (id < PREP_R3) {
        int e = id - PREP_R2, n = e / 768, k = e % 768;
        g_f2wT[n * 768 + k] = __float2bfloat16(f2w[k * 192 + n]);
    }
}

// ---------------- LayerNorm (fp32 in, bf16 out) ----------------
__global__ void ln_kernel(const float* __restrict__ x, const float* __restrict__ g,
                          const float* __restrict__ b, __nv_bfloat16* __restrict__ y)
{
    int lane = threadIdx.x & 31;
    int wi   = threadIdx.x >> 5;
    int l    = blockIdx.x * 8 + wi;
    const float* row = x + (size_t)l * C;
    float v[6];
    float s = 0.f, ss = 0.f;
#pragma unroll
    for (int i = 0; i < 6; i++) {
        v[i] = row[lane + 32 * i];
        s  += v[i];
        ss += v[i] * v[i];
    }
#pragma unroll
    for (int off = 16; off > 0; off >>= 1) {
        s  += __shfl_xor_sync(0xffffffffu, s,  off);
        ss += __shfl_xor_sync(0xffffffffu, ss, off);
    }
    float mean = s * (1.0f / C);
    float var  = ss * (1.0f / C) - mean * mean;
    float inv  = rsqrtf(var + 1e-5f);
    __nv_bfloat16* yr = y + (size_t)l * C;
#pragma unroll
    for (int i = 0; i < 6; i++) {
        int c = lane + 32 * i;
        yr[c] = __float2bfloat16((v[i] - mean) * inv * g[c] + b[c]);
    }
}

// -------- fused q+kv GEMM: 128x64 block, 4 warps, ldmatrix, scatter epi ----
#define QKV_SMEM_BYTES ((3 * (128 * 20 + 64 * 20)) * 4)
__global__ void __launch_bounds__(128)
gemm_qkv(const __nv_bfloat16* __restrict__ A,
         float* __restrict__ qout, float* __restrict__ ko, float* __restrict__ vo)
{
    extern __shared__ unsigned gsm[];
    unsigned* As = gsm;                    // [3][128][20]
    unsigned* Bs = gsm + 3 * 128 * 20;     // [3][64][20]
    const int K = 192;

    const int tid  = threadIdx.x;
    const int lane = tid & 31, warp = tid >> 5;
    const int wm = warp & 1, wn = warp >> 1;
    const int row0 = blockIdx.y * 128, col0 = blockIdx.x * 64;

    float acc[4][4][4];
#pragma unroll
    for (int i = 0; i < 4; i++)
#pragma unroll
        for (int j = 0; j < 4; j++)
#pragma unroll
            for (int t = 0; t < 4; t++) acc[i][j][t] = 0.f;

    const unsigned sA = (unsigned)__cvta_generic_to_shared(As);
    const unsigned sB = (unsigned)__cvta_generic_to_shared(Bs);
    const __nv_bfloat16* Wt = g_qkvT;

    auto load_tile = [&](int kt, int st) {
        unsigned aOff = sA + (unsigned)(st * 128 * 20) * 4;
#pragma unroll
        for (int i = 0; i < 4; i++) {
            int id = tid + i * 128;
            int r = id >> 2, wc = (id & 3) * 4;
            CP16(aOff + (unsigned)(r * 20 + wc) * 4,
                 A + (size_t)(row0 + r) * K + kt + wc * 2);
        }
        unsigned bOff = sB + (unsigned)(st * 64 * 20) * 4;
#pragma unroll
        for (int i = 0; i < 2; i++) {
            int id = tid + i * 128;
            int r = id >> 2, wc = (id & 3) * 4;
            CP16(bOff + (unsigned)(r * 20 + wc) * 4,
                 Wt + (size_t)(col0 + r) * K + kt + wc * 2);
        }
        CP_COMMIT();
    };

    load_tile(0, 0);
    load_tile(32, 1);

    const int a_row_sel = lane & 15;
    const int a_k_sel   = (lane >> 4) * 4;
    const int b_row_sel = (lane & 7) + (lane >> 4) * 8;
    const int b_k_sel   = ((lane >> 3) & 1) * 4;
    const int rb0 = wm * 64, cb0 = wn * 32;

    int st = 0;
    for (int t = 0; t < 6; t++) {
        CP_WAIT1();
        __syncthreads();
        if (t + 2 < 6) {
            int st2 = st + 2; if (st2 >= 3) st2 -= 3;
            load_tile((t + 2) << 5, st2);
        }
        const unsigned sAst = sA + (unsigned)(st * 128 * 20) * 4;
        const unsigned sBst = sB + (unsigned)(st * 64 * 20) * 4;
#pragma unroll
        for (int ks = 0; ks < 2; ks++) {
            const int koff = ks * 8;
            unsigned af[4][4], bf[4][2];
#pragma unroll
            for (int mi = 0; mi < 4; mi++) {
                unsigned addr = sAst +
                    (unsigned)(((rb0 + mi * 16 + a_row_sel) * 20 + a_k_sel + koff) * 4);
                LDSM_X4(af[mi][0], af[mi][1], af[mi][2], af[mi][3], addr);
            }
#pragma unroll
            for (int g = 0; g < 2; g++) {
                unsigned r0, r1, r2, r3;
                unsigned addr = sBst +
                    (unsigned)(((cb0 + g * 16 + b_row_sel) * 20 + b_k_sel + koff) * 4);
                LDSM_X4(r0, r1, r2, r3, addr);
                bf[g * 2 + 0][0] = r0; bf[g * 2 + 0][1] = r1;
                bf[g * 2 + 1][0] = r2; bf[g * 2 + 1][1] = r3;
            }
#pragma unroll
            for (int mi = 0; mi < 4; mi++)
#pragma unroll
                for (int ni = 0; ni < 4; ni++)
                    mma_bf16(acc[mi][ni], af[mi], bf[ni]);
        }
        if (++st == 3) st = 0;
    }

    const int rq = lane >> 2, tq = lane & 3;
    const int crow0 = row0 + wm * 64 + rq;
    const int ccol  = col0 + wn * 32 + tq * 2;
#pragma unroll
    for (int mi = 0; mi < 4; mi++) {
#pragma unroll
        for (int half = 0; half < 2; half++) {
            int row = crow0 + mi * 16 + half * 8;
#pragma unroll
            for (int ni = 0; ni < 4; ni++) {
                int col = ccol + ni * 8;
                float v0 = acc[mi][ni][half * 2 + 0] + g_qkvb[col];
                float v1 = acc[mi][ni][half * 2 + 1] + g_qkvb[col + 1];
                if (col < 192) {
                    *(float2*)(qout + (size_t)row * 192 + col) = make_float2(v0, v1);
                } else if (col < 240) {
                    int j = col - 192, jg = j >> 2, tt = j & 3;
                    float* dst = (jg < 6) ? ko : vo;
                    int head = (jg < 6) ? jg : jg - 6;
                    int z = row >> 12, y = (row >> 6) & 63, xq = row & 63;
                    int win = ((z >> 3) << 6) | ((y >> 3) << 3) | (xq >> 3);
                    int m = (((z & 7) >> 1) << 4) | (((y & 7) >> 1) << 2) | ((xq & 7) >> 1);
                    int sub = ((z & 1) << 2) | ((y & 1) << 1) | (xq & 1);
                    *(float2*)&dst[(((size_t)(win * 6 + head)) * 64 + m) * 32 + sub * 4 + tt] =
                        make_float2(v0, v1);
                }
            }
        }
    }
}

// -------- wide GEMM: 128x192 tile, 512 thr, 16 warps (4m x 4n), warp 32x48 -
// EPI: 1 = acc+bias+res -> fp32 ; 2 = gelu(acc+bias) -> bf16
#define G192_SMEM_BYTES ((3 * (128 * 20 + 192 * 20)) * 4)
template <int EPI>
__global__ void __launch_bounds__(512)
gemm192(const __nv_bfloat16* __restrict__ A, const __nv_bfloat16* __restrict__ Wt,
        const float* __restrict__ bias, const float* __restrict__ res,
        void* __restrict__ Cm, int N, int K)
{
    extern __shared__ unsigned gsm[];
    unsigned* As = gsm;                    // [3][128][20]
    unsigned* Bs = gsm + 3 * 128 * 20;     // [3][192][20]

    const int tid  = threadIdx.x;
    const int lane = tid & 31, warp = tid >> 5;
    const int wm = warp & 3, wn = warp >> 2;
    const int row0 = blockIdx.y * 128, col0 = blockIdx.x * 192;

    float acc[2][6][4];
#pragma unroll
    for (int i = 0; i < 2; i++)
#pragma unroll
        for (int j = 0; j < 6; j++)
#pragma unroll
            for (int t = 0; t < 4; t++) acc[i][j][t] = 0.f;

    const unsigned sA = (unsigned)__cvta_generic_to_shared(As);
    const unsigned sB = (unsigned)__cvta_generic_to_shared(Bs);
    const int ntiles = K >> 5;

    auto load_tile = [&](int kt, int st) {
        unsigned aOff = sA + (unsigned)(st * 128 * 20) * 4;
        {   // A: 512 chunks, 1 per thread
            int r = tid >> 2, wc = (tid & 3) * 4;
            CP16(aOff + (unsigned)(r * 20 + wc) * 4,
                 A + (size_t)(row0 + r) * K + kt + wc * 2);
        }
        unsigned bOff = sB + (unsigned)(st * 192 * 20) * 4;
        {   // B: 768 chunks: all threads once, first 256 twice
            int r = tid >> 2, wc = (tid & 3) * 4;
            CP16(bOff + (unsigned)(r * 20 + wc) * 4,
                 Wt + (size_t)(col0 + r) * K + kt + wc * 2);
            if (tid < 256) {
                int id = tid + 512;
                int r2 = id >> 2, wc2 = (id & 3) * 4;
                CP16(bOff + (unsigned)(r2 * 20 + wc2) * 4,
                     Wt + (size_t)(col0 + r2) * K + kt + wc2 * 2);
            }
        }
        CP_COMMIT();
    };

    load_tile(0, 0);
    load_tile(32, 1);

    const int a_row_sel = lane & 15;
    const int a_k_sel   = (lane >> 4) * 4;
    const int b_row_sel = (lane & 7) + (lane >> 4) * 8;
    const int b_k_sel   = ((lane >> 3) & 1) * 4;
    const int rb0 = wm * 32, cb0 = wn * 48;

    int st = 0;
    for (int t = 0; t < ntiles; t++) {
        CP_WAIT1();
        __syncthreads();
        if (t + 2 < ntiles) {
            int st2 = st + 2; if (st2 >= 3) st2 -= 3;
            load_tile((t + 2) << 5, st2);
        }
        const unsigned sAst = sA + (unsigned)(st * 128 * 20) * 4;
        const unsigned sBst = sB + (unsigned)(st * 192 * 20) * 4;
#pragma unroll
        for (int ks = 0; ks < 2; ks++) {
            const int koff = ks * 8;
            unsigned af[2][4], bf[6][2];
#pragma unroll
            for (int mi = 0; mi < 2; mi++) {
                unsigned addr = sAst +
                    (unsigned)(((rb0 + mi * 16 + a_row_sel) * 20 + a_k_sel + koff) * 4);
                LDSM_X4(af[mi][0], af[mi][1], af[mi][2], af[mi][3], addr);
            }
#pragma unroll
            for (int g = 0; g < 3; g++) {
                unsigned r0, r1, r2, r3;
                unsigned addr = sBst +
                    (unsigned)(((cb0 + g * 16 + b_row_sel) * 20 + b_k_sel + koff) * 4);
                LDSM_X4(r0, r1, r2, r3, addr);
                bf[g * 2 + 0][0] = r0; bf[g * 2 + 0][1] = r1;
                bf[g * 2 + 1][0] = r2; bf[g * 2 + 1][1] = r3;
            }
#pragma unroll
            for (int mi = 0; mi < 2; mi++)
#pragma unroll
                for (int ni = 0; ni < 6; ni++)
                    mma_bf16(acc[mi][ni], af[mi], bf[ni]);
        }
        if (++st == 3) st = 0;
    }

    const int rq = lane >> 2, tq = lane & 3;
    const int crow0 = row0 + wm * 32 + rq;
    const int ccol  = col0 + wn * 48 + tq * 2;
#pragma unroll
    for (int mi = 0; mi < 2; mi++) {
#pragma unroll
        for (int half = 0; half < 2; half++) {
            int row = crow0 + mi * 16 + half * 8;
#pragma unroll
            for (int ni = 0; ni < 6; ni++) {
                int col = ccol + ni * 8;
                float v0 = acc[mi][ni][half * 2 + 0] + bias[col];
                float v1 = acc[mi][ni][half * 2 + 1] + bias[col + 1];
                if (EPI == 1) {
                    float2 rv = *(const float2*)(res + (size_t)row * N + col);
                    *(float2*)((float*)Cm + (size_t)row * N + col) =
                        make_float2(v0 + rv.x, v1 + rv.y);
                } else {
                    *(__nv_bfloat162*)((__nv_bfloat16*)Cm + (size_t)row * N + col) =
                        __floats2bfloat162_rn(gelu_f(v0), gelu_f(v1));
                }
            }
        }
    }
}

// ---------------- attention via tensor cores ----------------
#define ATTN_SMEM_WORDS (64*36 + 32*68 + 128*36 + 8*16*68 + 343)
__global__ void __launch_bounds__(256)
attn_mma_kernel(const float* __restrict__ q, const float* __restrict__ kbuf,
                const float* __restrict__ vbuf, const float* __restrict__ btab,
                __nv_bfloat16* __restrict__ o)
{
    extern __shared__ unsigned sm[];
    unsigned* Ks = sm;
    unsigned* Vt = Ks + 64 * 36;
    unsigned* Qs = Vt + 32 * 68;
    unsigned* Pw = Qs + 128 * 36;
    float*    bt = (float*)(Pw + 8 * 16 * 68);

    const int win  = blockIdx.x / NHD;
    const int head = blockIdx.x % NHD;
    const int tid = threadIdx.x, lane = tid & 31, w = tid >> 5;
    const int rq = lane >> 2, tq = lane & 3;

    const float* kb = kbuf + (size_t)(win * NHD + head) * NP * HD;
    const float* vb = vbuf + (size_t)(win * NHD + head) * NP * HD;
    for (int i = tid; i < NP * HD; i += 256) {
        int m = i >> 5, c = i & 31;
        Ks[m * 36 + c] = __float_as_uint(kb[i]);
    }
    for (int i = tid; i < NP * HD; i += 256) {
        int c = i >> 6, m = i & 63;
        Vt[c * 68 + m] = __float_as_uint(vb[m * 32 + c]);
    }
    for (int i = tid; i < 343; i += 256) bt[i] = btab[i * NHD + head];

    const int wz = win >> 6, wy = (win >> 3) & 7, wx = win & 7;
    const int wbase = wz * 32768 + wy * 512 + wx * 8;
    unsigned* Pme = Pw + w * 16 * 68;

#pragma unroll 1
    for (int p = 0; p < 4; p++) {
        __syncthreads();
#pragma unroll
        for (int i = 0; i < 4; i++) {
            int idx = tid + i * 256;
            int r = idx >> 3, c4 = (idx & 7) * 4;
            int n = p * 128 + r;
            int l = wbase + (n >> 6) * 4096 + ((n >> 3) & 7) * 64 + (n & 7);
            float4 v4 = *(const float4*)(q + (size_t)l * C + head * HD + c4);
            Qs[r * 36 + c4 + 0] = __float_as_uint(v4.x);
            Qs[r * 36 + c4 + 1] = __float_as_uint(v4.y);
            Qs[r * 36 + c4 + 2] = __float_as_uint(v4.z);
            Qs[r * 36 + c4 + 3] = __float_as_uint(v4.w);
        }
        __syncthreads();

        float s[8][4];
#pragma unroll
        for (int j = 0; j < 8; j++)
#pragma unroll
            for (int t = 0; t < 4; t++) s[j][t] = 0.f;

        const unsigned* Qrow = Qs + (w * 16 + rq) * 36;
#pragma unroll
        for (int kb0 = 0; kb0 < 32; kb0 += 8) {
            unsigned a[4];
            a[0] = Qrow[kb0 + tq];
            a[1] = Qrow[8 * 36 + kb0 + tq];
            a[2] = Qrow[kb0 + tq + 4];
            a[3] = Qrow[8 * 36 + kb0 + tq + 4];
#pragma unroll
            for (int j = 0; j < 8; j++) {
                unsigned b[2];
                const unsigned* Kr = Ks + (j * 8 + rq) * 36 + kb0 + tq;
                b[0] = Kr[0];
                b[1] = Kr[4];
                mma_tf32(s[j], a, b);
            }
        }

        const int n0 = p * 128 + w * 16 + rq;
        const int n1 = n0 + 8;
        int qb0, qb1;
        {
            int zz = n0 >> 6, yy = (n0 >> 3) & 7, xx = n0 & 7;
            qb0 = ((zz >> 1) + 3) * 49 + ((yy >> 1) + 3) * 7 + (xx >> 1) + 3;
            zz = n1 >> 6; yy = (n1 >> 3) & 7; xx = n1 & 7;
            qb1 = ((zz >> 1) + 3) * 49 + ((yy >> 1) + 3) * 7 + (xx >> 1) + 3;
        }
        float mx0 = -1e30f, mx1 = -1e30f;
#pragma unroll
        for (int j = 0; j < 8; j++) {
#pragma unroll
            for (int s2 = 0; s2 < 2; s2++) {
                int m = j * 8 + tq * 2 + s2;
                int koff = (m >> 4) * 49 + ((m >> 2) & 3) * 7 + (m & 3);
                s[j][s2]     += bt[qb0 - koff];
                s[j][2 + s2] += bt[qb1 - koff];
                mx0 = fmaxf(mx0, s[j][s2]);
                mx1 = fmaxf(mx1, s[j][2 + s2]);
            }
        }
        mx0 = fmaxf(mx0, __shfl_xor_sync(0xffffffffu, mx0, 1));
        mx0 = fmaxf(mx0, __shfl_xor_sync(0xffffffffu, mx0, 2));
        mx1 = fmaxf(mx1, __shfl_xor_sync(0xffffffffu, mx1, 1));
        mx1 = fmaxf(mx1, __shfl_xor_sync(0xffffffffu, mx1, 2));
        float sum0 = 0.f, sum1 = 0.f;
#pragma unroll
        for (int j = 0; j < 8; j++) {
#pragma unroll
            for (int s2 = 0; s2 < 2; s2++) {
                s[j][s2]     = __expf(s[j][s2]     - mx0);
                s[j][2 + s2] = __expf(s[j][2 + s2] - mx1);
                sum0 += s[j][s2];
                sum1 += s[j][2 + s2];
            }
        }
        sum0 += __shfl_xor_sync(0xffffffffu, sum0, 1);
        sum0 += __shfl_xor_sync(0xffffffffu, sum0, 2);
        sum1 += __shfl_xor_sync(0xffffffffu, sum1, 1);
        sum1 += __shfl_xor_sync(0xffffffffu, sum1, 2);
        const float inv0 = 1.0f / sum0, inv1 = 1.0f / sum1;

#pragma unroll
        for (int j = 0; j < 8; j++) {
#pragma unroll
            for (int s2 = 0; s2 < 2; s2++) {
                int m = j * 8 + tq * 2 + s2;
                Pme[rq * 68 + m]       = __float_as_uint(s[j][s2] * inv0);
                Pme[(rq + 8) * 68 + m] = __float_as_uint(s[j][2 + s2] * inv1);
            }
        }
        __syncwarp();

        float oa[4][4];
#pragma unroll
        for (int j = 0; j < 4; j++)
#pragma unroll
            for (int t = 0; t < 4; t++) oa[j][t] = 0.f;

        const unsigned* Prow = Pme + rq * 68;
#pragma unroll
        for (int kb0 = 0; kb0 < 64; kb0 += 8) {
            unsigned a[4];
            a[0] = Prow[kb0 + tq];
            a[1] = Prow[8 * 68 + kb0 + tq];
            a[2] = Prow[kb0 + tq + 4];
            a[3] = Prow[8 * 68 + kb0 + tq + 4];
#pragma unroll
            for (int jn = 0; jn < 4; jn++) {
                unsigned b[2];
                const unsigned* Vr = Vt + (jn * 8 + rq) * 68 + kb0 + tq;
                b[0] = Vr[0];
                b[1] = Vr[4];
                mma_tf32(oa[jn], a, b);
            }
        }

        const int l0 = wbase + (n0 >> 6) * 4096 + ((n0 >> 3) & 7) * 64 + (n0 & 7);
        const int l1 = wbase + (n1 >> 6) * 4096 + ((n1 >> 3) & 7) * 64 + (n1 & 7);
        __nv_bfloat16* o0 = o + (size_t)l0 * C + head * HD + tq * 2;
        __nv_bfloat16* o1 = o + (size_t)l1 * C + head * HD + tq * 2;
#pragma unroll
        for (int jn = 0; jn < 4; jn++) {
            *(__nv_bfloat162*)(o0 + jn * 8) = __floats2bfloat162_rn(oa[jn][0], oa[jn][1]);
            *(__nv_bfloat162*)(o1 + jn * 8) = __floats2bfloat162_rn(oa[jn][2], oa[jn][3]);
        }
    }
}

// ---------------- depthwise 3x3x3 conv (bf16 io) + gelu + residual ---------
__global__ void dwconv_kernel(const __nv_bfloat16* __restrict__ hid,
                              const float* __restrict__ wgt, const float* __restrict__ bias,
                              __nv_bfloat16* __restrict__ hdn)
{
    const int c4  = threadIdx.x;
    const int bid = blockIdx.x;
    const int x0  = (bid & 7) * 8;
    const int y0  = ((bid >> 3) & 31) * 2;
    const int z   = bid >> 8;

    float4 acc[2][8];
#pragma unroll
    for (int yi = 0; yi < 2; yi++)
#pragma unroll
        for (int i = 0; i < 8; i++) acc[yi][i] = make_float4(0.f, 0.f, 0.f, 0.f);

    for (int kd = 0; kd < 3; kd++) {
        int zz = z + kd - 1;
        if (zz < 0 || zz >= DD) continue;
#pragma unroll
        for (int r = 0; r < 4; r++) {
            int yy = y0 - 1 + r;
            if (yy < 0 || yy >= HHH) continue;
            const __nv_bfloat16* base =
                hid + ((size_t)(zz * HHH + yy) * WWW) * HID + c4 * 4;
            float4 hv[10];
#pragma unroll
            for (int i = 0; i < 10; i++) {
                int xx = x0 - 1 + i;
                hv[i] = (xx >= 0 && xx < WWW) ? ldbf4(base + (size_t)xx * HID)
                                              : make_float4(0.f, 0.f, 0.f, 0.f);
            }
#pragma unroll
            for (int yi = 0; yi < 2; yi++) {
                int kh = r - yi;
                if (kh < 0 || kh > 2) continue;
#pragma unroll
                for (int kw = 0; kw < 3; kw++) {
                    float4 wv = *(const float4*)(wgt + ((kd * 3 + kh) * 3 + kw) * HID + c4 * 4);
#pragma unroll
                    for (int xi = 0; xi < 8; xi++) {
                        acc[yi][xi].x += hv[xi + kw].x * wv.x;
                        acc[yi][xi].y += hv[xi + kw].y * wv.y;
                        acc[yi][xi].z += hv[xi + kw].z * wv.z;
                        acc[yi][xi].w += hv[xi + kw].w * wv.w;
                    }
                }
            }
        }
    }
    float4 bv = *(const float4*)(bias + c4 * 4);
#pragma unroll
    for (int yi = 0; yi < 2; yi++) {
#pragma unroll
        for (int xi = 0; xi < 8; xi++) {
            size_t idx = ((size_t)((z * HHH + y0 + yi) * WWW + x0 + xi)) * HID + c4 * 4;
            float4 h0 = ldbf4(hid + idx);
            float4 o;
            o.x = h0.x + gelu_f(acc[yi][xi].x + bv.x);
            o.y = h0.y + gelu_f(acc[yi][xi].y + bv.y);
            o.z = h0.z + gelu_f(acc[yi][xi].z + bv.z);
            o.w = h0.w + gelu_f(acc[yi][xi].w + bv.w);
            stbf4(hdn + idx, o);
        }
    }
}

// ---------------- launch ----------------------------------------------------
static void* sym_addr(const void* sym) {
    void* p = nullptr;
    cudaGetSymbolAddress(&p, sym);
    return p;
}

extern "C" void kernel_launch(void* const* d_in, const int* in_sizes, int n_in,
                              void* d_out, int out_size)
{
    const float* x    = (const float*)d_in[0];
    const float* n1g  = (const float*)d_in[1];
    const float* n1b  = (const float*)d_in[2];
    const float* q_w  = (const float*)d_in[3];
    const float* q_b  = (const float*)d_in[4];
    const float* kv_w = (const float*)d_in[5];
    const float* kv_b = (const float*)d_in[6];
    const float* btab = (const float*)d_in[7];
    const float* p_w  = (const float*)d_in[8];
    const float* p_b  = (const float*)d_in[9];
    const float* n2g  = (const float*)d_in[10];
    const float* n2b  = (const float*)d_in[11];
    const float* f1w  = (const float*)d_in[12];
    const float* f1b  = (const float*)d_in[13];
    const float* dww  = (const float*)d_in[14];
    const float* dwb  = (const float*)d_in[15];
    const float* f2w  = (const float*)d_in[16];
    const float* f2b  = (const float*)d_in[17];
    float* out = (float*)d_out;

    __nv_bfloat16* xnb  = (__nv_bfloat16*)sym_addr(g_xnb);
    float*         qb_  = (float*)sym_addr(g_q);
    float*         kb_  = (float*)sym_addr(g_k);
    float*         vb_  = (float*)sym_addr(g_v);
    __nv_bfloat16* ob   = (__nv_bfloat16*)sym_addr(g_ob);
    float*         x1   = (float*)sym_addr(g_x1);
    __nv_bfloat16* hidb = (__nv_bfloat16*)sym_addr(g_hidb);
    __nv_bfloat16* hdnb = (__nv_bfloat16*)sym_addr(g_hdnb);
    __nv_bfloat16* pwT  = (__nv_bfloat16*)sym_addr(g_pwT);
    __nv_bfloat16* f1wT = (__nv_bfloat16*)sym_addr(g_f1wT);
    __nv_bfloat16* f2wT = (__nv_bfloat16*)sym_addr(g_f2wT);

    const int attn_smem = ATTN_SMEM_WORDS * 4;
    cudaFuncSetAttribute(attn_mma_kernel,
                         cudaFuncAttributeMaxDynamicSharedMemorySize, attn_smem);
    cudaFuncSetAttribute(gemm_qkv,
                         cudaFuncAttributeMaxDynamicSharedMemorySize, QKV_SMEM_BYTES);
    cudaFuncSetAttribute(gemm192<1>,
                         cudaFuncAttributeMaxDynamicSharedMemorySize, G192_SMEM_BYTES);
    cudaFuncSetAttribute(gemm192<2>,
                         cudaFuncAttributeMaxDynamicSharedMemorySize, G192_SMEM_BYTES);

    // 0) all weight prep in one launch
    prep_kernel<<<(PREP_R3 + 255) / 256, 256>>>(q_w, q_b, kv_w, kv_b, p_w, f1w, f2w);
    // 1) LN1 -> bf16
    ln_kernel<<<L / 8, 256>>>(x, n1g, n1b, xnb);
    // 2) fused q + kv projection (scatter epilogue)
    gemm_qkv<<<dim3(4, L / 128), 128, QKV_SMEM_BYTES>>>(xnb, qb_, kb_, vb_);
    // 3) windowed attention
    attn_mma_kernel<<<NWIN * NHD, 256, attn_smem>>>(qb_, kb_, vb_, btab, ob);
    // 4) x1 = x + o @ proj_w + proj_b  [full-width tile]
    gemm192<1><<<dim3(1, L / 128), 512, G192_SMEM_BYTES>>>(
        ob, pwT, p_b, x, x1, C, C);
    // 5) LN2 -> bf16
    ln_kernel<<<L / 8, 256>>>(x1, n2g, n2b, xnb);
    // 6) hid = gelu(xn @ fc1_w + fc1_b)
    gemm192<2><<<dim3(HID / 192, L / 128), 512, G192_SMEM_BYTES>>>(
        xnb, f1wT, f1b, nullptr, hidb, HID, C);
    // 7) hdn = hid + gelu(dwconv(hid) + dw_b)
    dwconv_kernel<<<(DD * HHH * WWW) / 16, 192>>>(hidb, dww, dwb, hdnb);
    // 8) out = x1 + hdn @ fc2_w + fc2_b  [A read exactly once]
    gemm192<1><<<dim3(1, L / 128), 512, G192_SMEM_BYTES>>>(
        hdnb, f2wT, f2b, x1, out, C, HID);
}

// round 10
// speedup vs baseline: 3.8029x; 1.0433x over previous
#include <cuda_runtime.h>
#include <cuda_bf16.h>
#include <math.h>

// ---------------- problem constants ----------------
#define L     131072
#define C     192
#define NHD   6
#define HD    32
#define NWIN  256
#define NP    64
#define HID   768
#define DD    32
#define HHH   64
#define WWW   64

// ---------------- scratch ----------------
__device__ __nv_bfloat16 g_xnb [L * C];
__device__ __nv_bfloat16 g_qb  [L * C];
__device__ __nv_bfloat16 g_kb  [NWIN * NHD * NP * HD];
__device__ __nv_bfloat16 g_vb2 [NWIN * NHD * NP * HD];
__device__ __nv_bfloat16 g_ob  [L * C];
__device__ float         g_x1  [L * C];
__device__ __nv_bfloat16 g_hidb[L * HID];
__device__ __nv_bfloat16 g_hdnb[L * HID];
__device__ __nv_bfloat16 g_qkvT[256 * C];
__device__ float         g_qkvb[256];
__device__ __nv_bfloat16 g_pwT [C * C];
__device__ __nv_bfloat16 g_f1wT[HID * C];
__device__ __nv_bfloat16 g_f2wT[C * HID];

__device__ __forceinline__ float gelu_f(float v) {
    return 0.5f * v * (1.0f + erff(v * 0.70710678118654752f));
}

__device__ __forceinline__ void mma_bf16(float* d, const unsigned* a, const unsigned* b) {
    asm volatile(
        "mma.sync.aligned.m16n8k16.row.col.f32.bf16.bf16.f32 "
        "{%0,%1,%2,%3},{%4,%5,%6,%7},{%8,%9},{%0,%1,%2,%3};"
        : "+f"(d[0]), "+f"(d[1]), "+f"(d[2]), "+f"(d[3])
        : "r"(a[0]), "r"(a[1]), "r"(a[2]), "r"(a[3]), "r"(b[0]), "r"(b[1]));
}

#define LDSM_X4(r0, r1, r2, r3, addr) \
    asm volatile("ldmatrix.sync.aligned.m8n8.x4.shared.b16 {%0,%1,%2,%3}, [%4];" \
                 : "=r"(r0), "=r"(r1), "=r"(r2), "=r"(r3) : "r"(addr))

#define CP16(dst_smem_u32, src_ptr) \
    asm volatile("cp.async.cg.shared.global [%0], [%1], 16;\n" \
                 :: "r"(dst_smem_u32), "l"(src_ptr))
#define CP_COMMIT() asm volatile("cp.async.commit_group;\n" ::: "memory")
#define CP_WAIT1()  asm volatile("cp.async.wait_group 1;\n" ::: "memory")

__device__ __forceinline__ float4 ldbf4(const __nv_bfloat16* p) {
    uint2 u = *(const uint2*)p;
    float2 a = __bfloat1622float2(*(__nv_bfloat162*)&u.x);
    float2 b = __bfloat1622float2(*(__nv_bfloat162*)&u.y);
    return make_float4(a.x, a.y, b.x, b.y);
}
__device__ __forceinline__ void stbf4(__nv_bfloat16* p, float4 v) {
    uint2 u;
    *(__nv_bfloat162*)&u.x = __floats2bfloat162_rn(v.x, v.y);
    *(__nv_bfloat162*)&u.y = __floats2bfloat162_rn(v.z, v.w);
    *(uint2*)p = u;
}
__device__ __forceinline__ unsigned packbf(float a, float b) {
    __nv_bfloat162 t = __floats2bfloat162_rn(a, b);
    return *(unsigned*)&t;
}

// ------------- prep ------------
#define PREP_R0 (256 * 192)
#define PREP_R1 (PREP_R0 + 192 * 192)
#define PREP_R2 (PREP_R1 + 768 * 192)
#define PREP_R3 (PREP_R2 + 192 * 768)
__global__ void prep_kernel(const float* __restrict__ q_w, const float* __restrict__ q_b,
                            const float* __restrict__ kv_w, const float* __restrict__ kv_b,
                            const float* __restrict__ p_w, const float* __restrict__ f1w,
                            const float* __restrict__ f2w)
{
    const float qscale = 0.17677669529663687f;
    int id = blockIdx.x * 256 + threadIdx.x;
    if (id < 256) {
        float b = 0.f;
        if (id < 192)      b = q_b[id] * qscale;
        else if (id < 240) b = kv_b[id - 192];
        g_qkvb[id] = b;
    }
    if (id < PREP_R0) {
        int n = id / 192, k = id % 192;
        float v = 0.f;
        if (n < 192)      v = q_w[k * 192 + n] * qscale;
        else if (n < 240) v = kv_w[k * 48 + (n - 192)];
        g_qkvT[n * 192 + k] = __float2bfloat16(v);
    } else if (id < PREP_R1) {
        int e = id - PREP_R0, n = e / 192, k = e % 192;
        g_pwT[n * 192 + k] = __float2bfloat16(p_w[k * 192 + n]);
    } else if (id < PREP_R2) {
        int e = id - PREP_R1, n = e / 192, k = e % 192;
        g_f1wT[n * 192 + k] = __float2bfloat16(f1w[k * 768 + n]);
    } else if (id < PREP_R3) {
        int e = id - PREP_R2, n = e / 768, k = e % 768;
        g_f2wT[n * 768 + k] = __float2bfloat16(f2w[k * 192 + n]);
    }
}

// ---------------- LayerNorm (fp32 in, bf16 out) — LN1 only -----------------
__global__ void ln_kernel(const float* __restrict__ x, const float* __restrict__ g,
                          const float* __restrict__ b, __nv_bfloat16* __restrict__ y)
{
    int lane = threadIdx.x & 31;
    int wi   = threadIdx.x >> 5;
    int l    = blockIdx.x * 8 + wi;
    const float* row = x + (size_t)l * C;
    float v[6];
    float s = 0.f, ss = 0.f;
#pragma unroll
    for (int i = 0; i < 6; i++) {
        v[i] = row[lane + 32 * i];
        s  += v[i];
        ss += v[i] * v[i];
    }
#pragma unroll
    for (int off = 16; off > 0; off >>= 1) {
        s  += __shfl_xor_sync(0xffffffffu, s,  off);
        ss += __shfl_xor_sync(0xffffffffu, ss, off);
    }
    float mean = s * (1.0f / C);
    float var  = ss * (1.0f / C) - mean * mean;
    float inv  = rsqrtf(var + 1e-5f);
    __nv_bfloat16* yr = y + (size_t)l * C;
#pragma unroll
    for (int i = 0; i < 6; i++) {
        int c = lane + 32 * i;
        yr[c] = __float2bfloat16((v[i] - mean) * inv * g[c] + b[c]);
    }
}

// -------- fused q+kv GEMM: bf16 outputs, scatter epilogue ------------------
#define QKV_SMEM_BYTES ((3 * (128 * 20 + 64 * 20)) * 4)
__global__ void __launch_bounds__(128)
gemm_qkv(const __nv_bfloat16* __restrict__ A,
         __nv_bfloat16* __restrict__ qout, __nv_bfloat16* __restrict__ ko,
         __nv_bfloat16* __restrict__ vo)
{
    extern __shared__ unsigned gsm[];
    unsigned* As = gsm;
    unsigned* Bs = gsm + 3 * 128 * 20;
    const int K = 192;

    const int tid  = threadIdx.x;
    const int lane = tid & 31, warp = tid >> 5;
    const int wm = warp & 1, wn = warp >> 1;
    const int row0 = blockIdx.y * 128, col0 = blockIdx.x * 64;

    float acc[4][4][4];
#pragma unroll
    for (int i = 0; i < 4; i++)
#pragma unroll
        for (int j = 0; j < 4; j++)
#pragma unroll
            for (int t = 0; t < 4; t++) acc[i][j][t] = 0.f;

    const unsigned sA = (unsigned)__cvta_generic_to_shared(As);
    const unsigned sB = (unsigned)__cvta_generic_to_shared(Bs);
    const __nv_bfloat16* Wt = g_qkvT;

    auto load_tile = [&](int kt, int st) {
        unsigned aOff = sA + (unsigned)(st * 128 * 20) * 4;
#pragma unroll
        for (int i = 0; i < 4; i++) {
            int id = tid + i * 128;
            int r = id >> 2, wc = (id & 3) * 4;
            CP16(aOff + (unsigned)(r * 20 + wc) * 4,
                 A + (size_t)(row0 + r) * K + kt + wc * 2);
        }
        unsigned bOff = sB + (unsigned)(st * 64 * 20) * 4;
#pragma unroll
        for (int i = 0; i < 2; i++) {
            int id = tid + i * 128;
            int r = id >> 2, wc = (id & 3) * 4;
            CP16(bOff + (unsigned)(r * 20 + wc) * 4,
                 Wt + (size_t)(col0 + r) * K + kt + wc * 2);
        }
        CP_COMMIT();
    };

    load_tile(0, 0);
    load_tile(32, 1);

    const int a_row_sel = lane & 15;
    const int a_k_sel   = (lane >> 4) * 4;
    const int b_row_sel = (lane & 7) + (lane >> 4) * 8;
    const int b_k_sel   = ((lane >> 3) & 1) * 4;
    const int rb0 = wm * 64, cb0 = wn * 32;

    int st = 0;
    for (int t = 0; t < 6; t++) {
        CP_WAIT1();
        __syncthreads();
        if (t + 2 < 6) {
            int st2 = st + 2; if (st2 >= 3) st2 -= 3;
            load_tile((t + 2) << 5, st2);
        }
        const unsigned sAst = sA + (unsigned)(st * 128 * 20) * 4;
        const unsigned sBst = sB + (unsigned)(st * 64 * 20) * 4;
#pragma unroll
        for (int ks = 0; ks < 2; ks++) {
            const int koff = ks * 8;
            unsigned af[4][4], bf[4][2];
#pragma unroll
            for (int mi = 0; mi < 4; mi++) {
                unsigned addr = sAst +
                    (unsigned)(((rb0 + mi * 16 + a_row_sel) * 20 + a_k_sel + koff) * 4);
                LDSM_X4(af[mi][0], af[mi][1], af[mi][2], af[mi][3], addr);
            }
#pragma unroll
            for (int g = 0; g < 2; g++) {
                unsigned r0, r1, r2, r3;
                unsigned addr = sBst +
                    (unsigned)(((cb0 + g * 16 + b_row_sel) * 20 + b_k_sel + koff) * 4);
                LDSM_X4(r0, r1, r2, r3, addr);
                bf[g * 2 + 0][0] = r0; bf[g * 2 + 0][1] = r1;
                bf[g * 2 + 1][0] = r2; bf[g * 2 + 1][1] = r3;
            }
#pragma unroll
            for (int mi = 0; mi < 4; mi++)
#pragma unroll
                for (int ni = 0; ni < 4; ni++)
                    mma_bf16(acc[mi][ni], af[mi], bf[ni]);
        }
        if (++st == 3) st = 0;
    }

    const int rq = lane >> 2, tq = lane & 3;
    const int crow0 = row0 + wm * 64 + rq;
    const int ccol  = col0 + wn * 32 + tq * 2;
#pragma unroll
    for (int mi = 0; mi < 4; mi++) {
#pragma unroll
        for (int half = 0; half < 2; half++) {
            int row = crow0 + mi * 16 + half * 8;
#pragma unroll
            for (int ni = 0; ni < 4; ni++) {
                int col = ccol + ni * 8;
                float v0 = acc[mi][ni][half * 2 + 0] + g_qkvb[col];
                float v1 = acc[mi][ni][half * 2 + 1] + g_qkvb[col + 1];
                if (col < 192) {
                    *(unsigned*)(qout + (size_t)row * 192 + col) = packbf(v0, v1);
                } else if (col < 240) {
                    int j = col - 192, jg = j >> 2, tt = j & 3;
                    __nv_bfloat16* dst = (jg < 6) ? ko : vo;
                    int head = (jg < 6) ? jg : jg - 6;
                    int z = row >> 12, y = (row >> 6) & 63, xq = row & 63;
                    int win = ((z >> 3) << 6) | ((y >> 3) << 3) | (xq >> 3);
                    int m = (((z & 7) >> 1) << 4) | (((y & 7) >> 1) << 2) | ((xq & 7) >> 1);
                    int sub = ((z & 1) << 2) | ((y & 1) << 1) | (xq & 1);
                    *(unsigned*)&dst[(((size_t)(win * 6 + head)) * 64 + m) * 32 + sub * 4 + tt] =
                        packbf(v0, v1);
                }
            }
        }
    }
}

// -------- wide GEMM 128x192, 512 thr; EPI: 1=+res fp32, 2=gelu bf16,
//          3 = +res -> x1 fp32 AND fused LayerNorm -> bf16 xout --------------
#define G192_SMEM_BYTES ((3 * (128 * 20 + 192 * 20)) * 4)
template <int EPI>
__global__ void __launch_bounds__(512)
gemm192(const __nv_bfloat16* __restrict__ A, const __nv_bfloat16* __restrict__ Wt,
        const float* __restrict__ bias, const float* __restrict__ res,
        float* __restrict__ Cf, __nv_bfloat16* __restrict__ Cb,
        const float* __restrict__ lng, const float* __restrict__ lnb,
        int N, int K)
{
    extern __shared__ unsigned gsm[];
    unsigned* As = gsm;
    unsigned* Bs = gsm + 3 * 128 * 20;

    const int tid  = threadIdx.x;
    const int lane = tid & 31, warp = tid >> 5;
    const int wm = warp & 3, wn = warp >> 2;
    const int row0 = blockIdx.y * 128, col0 = blockIdx.x * 192;

    float acc[2][6][4];
#pragma unroll
    for (int i = 0; i < 2; i++)
#pragma unroll
        for (int j = 0; j < 6; j++)
#pragma unroll
            for (int t = 0; t < 4; t++) acc[i][j][t] = 0.f;

    const unsigned sA = (unsigned)__cvta_generic_to_shared(As);
    const unsigned sB = (unsigned)__cvta_generic_to_shared(Bs);
    const int ntiles = K >> 5;

    auto load_tile = [&](int kt, int st) {
        unsigned aOff = sA + (unsigned)(st * 128 * 20) * 4;
        {
            int r = tid >> 2, wc = (tid & 3) * 4;
            CP16(aOff + (unsigned)(r * 20 + wc) * 4,
                 A + (size_t)(row0 + r) * K + kt + wc * 2);
        }
        unsigned bOff = sB + (unsigned)(st * 192 * 20) * 4;
        {
            int r = tid >> 2, wc = (tid & 3) * 4;
            CP16(bOff + (unsigned)(r * 20 + wc) * 4,
                 Wt + (size_t)(col0 + r) * K + kt + wc * 2);
            if (tid < 256) {
                int id = tid + 512;
                int r2 = id >> 2, wc2 = (id & 3) * 4;
                CP16(bOff + (unsigned)(r2 * 20 + wc2) * 4,
                     Wt + (size_t)(col0 + r2) * K + kt + wc2 * 2);
            }
        }
        CP_COMMIT();
    };

    load_tile(0, 0);
    load_tile(32, 1);

    const int a_row_sel = lane & 15;
    const int a_k_sel   = (lane >> 4) * 4;
    const int b_row_sel = (lane & 7) + (lane >> 4) * 8;
    const int b_k_sel   = ((lane >> 3) & 1) * 4;
    const int rb0 = wm * 32, cb0 = wn * 48;

    int st = 0;
    for (int t = 0; t < ntiles; t++) {
        CP_WAIT1();
        __syncthreads();
        if (t + 2 < ntiles) {
            int st2 = st + 2; if (st2 >= 3) st2 -= 3;
            load_tile((t + 2) << 5, st2);
        }
        const unsigned sAst = sA + (unsigned)(st * 128 * 20) * 4;
        const unsigned sBst = sB + (unsigned)(st * 192 * 20) * 4;
#pragma unroll
        for (int ks = 0; ks < 2; ks++) {
            const int koff = ks * 8;
            unsigned af[2][4], bf[6][2];
#pragma unroll
            for (int mi = 0; mi < 2; mi++) {
                unsigned addr = sAst +
                    (unsigned)(((rb0 + mi * 16 + a_row_sel) * 20 + a_k_sel + koff) * 4);
                LDSM_X4(af[mi][0], af[mi][1], af[mi][2], af[mi][3], addr);
            }
#pragma unroll
            for (int g = 0; g < 3; g++) {
                unsigned r0, r1, r2, r3;
                unsigned addr = sBst +
                    (unsigned)(((cb0 + g * 16 + b_row_sel) * 20 + b_k_sel + koff) * 4);
                LDSM_X4(r0, r1, r2, r3, addr);
                bf[g * 2 + 0][0] = r0; bf[g * 2 + 0][1] = r1;
                bf[g * 2 + 1][0] = r2; bf[g * 2 + 1][1] = r3;
            }
#pragma unroll
            for (int mi = 0; mi < 2; mi++)
#pragma unroll
                for (int ni = 0; ni < 6; ni++)
                    mma_bf16(acc[mi][ni], af[mi], bf[ni]);
        }
        if (++st == 3) st = 0;
    }

    const int rq = lane >> 2, tq = lane & 3;
    const int crow0 = row0 + wm * 32 + rq;
    const int ccol  = col0 + wn * 48 + tq * 2;

    if (EPI == 3) {
        // val = acc + bias + res (the x1 value), stored back into acc
        __syncthreads();               // done with gsm mainloop buffers
        float* st_s  = (float*)gsm;            // [128][4]
        float* st_ss = (float*)gsm + 512;      // [128][4]
#pragma unroll
        for (int mi = 0; mi < 2; mi++)
#pragma unroll
            for (int half = 0; half < 2; half++) {
                int row = crow0 + mi * 16 + half * 8;
                float s = 0.f, ss = 0.f;
#pragma unroll
                for (int ni = 0; ni < 6; ni++) {
                    int col = ccol + ni * 8;
                    float2 rv = *(const float2*)(res + (size_t)row * 192 + col);
                    float v0 = acc[mi][ni][half * 2 + 0] + bias[col]     + rv.x;
                    float v1 = acc[mi][ni][half * 2 + 1] + bias[col + 1] + rv.y;
                    acc[mi][ni][half * 2 + 0] = v0;
                    acc[mi][ni][half * 2 + 1] = v1;
                    s += v0 + v1; ss += v0 * v0 + v1 * v1;
                }
                s  += __shfl_xor_sync(0xffffffffu, s, 1);
                s  += __shfl_xor_sync(0xffffffffu, s, 2);
                ss += __shfl_xor_sync(0xffffffffu, ss, 1);
                ss += __shfl_xor_sync(0xffffffffu, ss, 2);
                if (tq == 0) {
                    int rowl = wm * 32 + mi * 16 + half * 8 + rq;
                    st_s [rowl * 4 + wn] = s;
                    st_ss[rowl * 4 + wn] = ss;
                }
            }
        __syncthreads();
#pragma unroll
        for (int mi = 0; mi < 2; mi++)
#pragma unroll
            for (int half = 0; half < 2; half++) {
                int rowl = wm * 32 + mi * 16 + half * 8 + rq;
                int row  = row0 + rowl;
                float S  = st_s[rowl*4] + st_s[rowl*4+1] + st_s[rowl*4+2] + st_s[rowl*4+3];
                float SS = st_ss[rowl*4] + st_ss[rowl*4+1] + st_ss[rowl*4+2] + st_ss[rowl*4+3];
                float mean = S * (1.0f / 192.0f);
                float var  = SS * (1.0f / 192.0f) - mean * mean;
                float inv  = rsqrtf(var + 1e-5f);
#pragma unroll
                for (int ni = 0; ni < 6; ni++) {
                    int col = ccol + ni * 8;
                    float v0 = acc[mi][ni][half * 2 + 0];
                    float v1 = acc[mi][ni][half * 2 + 1];
                    *(float2*)(Cf + (size_t)row * 192 + col) = make_float2(v0, v1);
                    float n0 = (v0 - mean) * inv * lng[col]     + lnb[col];
                    float n1 = (v1 - mean) * inv * lng[col + 1] + lnb[col + 1];
                    *(unsigned*)(Cb + (size_t)row * 192 + col) = packbf(n0, n1);
                }
            }
        return;
    }

#pragma unroll
    for (int mi = 0; mi < 2; mi++) {
#pragma unroll
        for (int half = 0; half < 2; half++) {
            int row = crow0 + mi * 16 + half * 8;
#pragma unroll
            for (int ni = 0; ni < 6; ni++) {
                int col = ccol + ni * 8;
                float v0 = acc[mi][ni][half * 2 + 0] + bias[col];
                float v1 = acc[mi][ni][half * 2 + 1] + bias[col + 1];
                if (EPI == 1) {
                    float2 rv = *(const float2*)(res + (size_t)row * N + col);
                    *(float2*)(Cf + (size_t)row * N + col) =
                        make_float2(v0 + rv.x, v1 + rv.y);
                } else {
                    *(unsigned*)(Cb + (size_t)row * N + col) =
                        packbf(gelu_f(v0), gelu_f(v1));
                }
            }
        }
    }
}

// ---------------- attention: full bf16, m16n8k16 ----------------
// Ks[64][20]w, Vt[32][36]w, Qs[128][20]w, Pw[8][16][36]w, bt[343]
#define ATTN_SMEM_WORDS (64*20 + 32*36 + 128*20 + 8*16*36 + 343)
__global__ void __launch_bounds__(256)
attn_mma_kernel(const __nv_bfloat16* __restrict__ q, const __nv_bfloat16* __restrict__ kbuf,
                const __nv_bfloat16* __restrict__ vbuf, const float* __restrict__ btab,
                __nv_bfloat16* __restrict__ o)
{
    extern __shared__ unsigned sm[];
    unsigned* Ks = sm;                     // [64][20]  K words (2 bf16 along c)
    unsigned* Vt = Ks + 64 * 20;           // [32][36]  V^T words (2 bf16 along m)
    unsigned* Qs = Vt + 32 * 36;           // [128][20] Q words
    unsigned* Pw = Qs + 128 * 20;          // [8][16][36] per-warp P
    float*    bt = (float*)(Pw + 8 * 16 * 36);

    const int win  = blockIdx.x / NHD;
    const int head = blockIdx.x % NHD;
    const int tid = threadIdx.x, lane = tid & 31, w = tid >> 5;
    const int rq = lane >> 2, tq = lane & 3;

    const __nv_bfloat16* kb = kbuf + (size_t)(win * NHD + head) * NP * HD;
    const __nv_bfloat16* vb = vbuf + (size_t)(win * NHD + head) * NP * HD;
    for (int i = tid; i < 64 * 16; i += 256) {
        int m = i >> 4, wp = i & 15;
        Ks[m * 20 + wp] = ((const unsigned*)kb)[i];
    }
    for (int i = tid; i < 32 * 32; i += 256) {
        int c = i >> 5, mp = i & 31;
        Vt[c * 36 + mp] = packbf(__bfloat162float(vb[(2 * mp) * 32 + c]),
                                 __bfloat162float(vb[(2 * mp + 1) * 32 + c]));
    }
    for (int i = tid; i < 343; i += 256) bt[i] = btab[i * NHD + head];

    const int wz = win >> 6, wy = (win >> 3) & 7, wx = win & 7;
    const int wbase = wz * 32768 + wy * 512 + wx * 8;
    unsigned* Pme = Pw + w * 16 * 36;

#pragma unroll 1
    for (int p = 0; p < 4; p++) {
        __syncthreads();
        // Q chunk: 128 rows x 16 words, 512 x 16B chunks over 256 thr x 2
#pragma unroll
        for (int i = 0; i < 2; i++) {
            int idx = tid + i * 256;
            int r = idx >> 2, wc = (idx & 3) * 4;
            int n = p * 128 + r;
            int l = wbase + (n >> 6) * 4096 + ((n >> 3) & 7) * 64 + (n & 7);
            uint4 v4 = *(const uint4*)(q + (size_t)l * C + head * HD + wc * 2);
            *(uint4*)&Qs[r * 20 + wc] = v4;
        }
        __syncthreads();

        float s[8][4];
#pragma unroll
        for (int j = 0; j < 8; j++)
#pragma unroll
            for (int t = 0; t < 4; t++) s[j][t] = 0.f;

        const unsigned* Qrow = Qs + (w * 16 + rq) * 20;
#pragma unroll
        for (int kc = 0; kc < 2; kc++) {
            const int kw = kc * 8;
            unsigned a[4];
            a[0] = Qrow[kw + tq];
            a[1] = Qrow[8 * 20 + kw + tq];
            a[2] = Qrow[kw + tq + 4];
            a[3] = Qrow[8 * 20 + kw + tq + 4];
#pragma unroll
            for (int j = 0; j < 8; j++) {
                unsigned b[2];
                const unsigned* Kr = Ks + (j * 8 + rq) * 20 + kw + tq;
                b[0] = Kr[0];
                b[1] = Kr[4];
                mma_bf16(s[j], a, b);
            }
        }

        const int n0 = p * 128 + w * 16 + rq;
        const int n1 = n0 + 8;
        int qb0, qb1;
        {
            int zz = n0 >> 6, yy = (n0 >> 3) & 7, xx = n0 & 7;
            qb0 = ((zz >> 1) + 3) * 49 + ((yy >> 1) + 3) * 7 + (xx >> 1) + 3;
            zz = n1 >> 6; yy = (n1 >> 3) & 7; xx = n1 & 7;
            qb1 = ((zz >> 1) + 3) * 49 + ((yy >> 1) + 3) * 7 + (xx >> 1) + 3;
        }
        float mx0 = -1e30f, mx1 = -1e30f;
#pragma unroll
        for (int j = 0; j < 8; j++) {
#pragma unroll
            for (int s2 = 0; s2 < 2; s2++) {
                int m = j * 8 + tq * 2 + s2;
                int koff = (m >> 4) * 49 + ((m >> 2) & 3) * 7 + (m & 3);
                s[j][s2]     += bt[qb0 - koff];
                s[j][2 + s2] += bt[qb1 - koff];
                mx0 = fmaxf(mx0, s[j][s2]);
                mx1 = fmaxf(mx1, s[j][2 + s2]);
            }
        }
        mx0 = fmaxf(mx0, __shfl_xor_sync(0xffffffffu, mx0, 1));
        mx0 = fmaxf(mx0, __shfl_xor_sync(0xffffffffu, mx0, 2));
        mx1 = fmaxf(mx1, __shfl_xor_sync(0xffffffffu, mx1, 1));
        mx1 = fmaxf(mx1, __shfl_xor_sync(0xffffffffu, mx1, 2));
        float sum0 = 0.f, sum1 = 0.f;
#pragma unroll
        for (int j = 0; j < 8; j++) {
#pragma unroll
            for (int s2 = 0; s2 < 2; s2++) {
                s[j][s2]     = __expf(s[j][s2]     - mx0);
                s[j][2 + s2] = __expf(s[j][2 + s2] - mx1);
                sum0 += s[j][s2];
                sum1 += s[j][2 + s2];
            }
        }
        sum0 += __shfl_xor_sync(0xffffffffu, sum0, 1);
        sum0 += __shfl_xor_sync(0xffffffffu, sum0, 2);
        sum1 += __shfl_xor_sync(0xffffffffu, sum1, 1);
        sum1 += __shfl_xor_sync(0xffffffffu, sum1, 2);
        const float inv0 = 1.0f / sum0, inv1 = 1.0f / sum1;

        // P -> bf16 words: Pme[row][mpair], mpair = j*4 + tq
#pragma unroll
        for (int j = 0; j < 8; j++) {
            Pme[rq * 36 + j * 4 + tq]       = packbf(s[j][0] * inv0, s[j][1] * inv0);
            Pme[(rq + 8) * 36 + j * 4 + tq] = packbf(s[j][2] * inv1, s[j][3] * inv1);
        }
        __syncwarp();

        float oa[4][4];
#pragma unroll
        for (int j = 0; j < 4; j++)
#pragma unroll
            for (int t = 0; t < 4; t++) oa[j][t] = 0.f;

        const unsigned* Prow = Pme + rq * 36;
#pragma unroll
        for (int kc = 0; kc < 4; kc++) {
            const int base = kc * 8;
            unsigned a[4];
            a[0] = Prow[base + tq];
            a[1] = Prow[8 * 36 + base + tq];
            a[2] = Prow[base + tq + 4];
            a[3] = Prow[8 * 36 + base + tq + 4];
#pragma unroll
            for (int jn = 0; jn < 4; jn++) {
                unsigned b[2];
                const unsigned* Vr = Vt + (jn * 8 + rq) * 36 + base + tq;
                b[0] = Vr[0];
                b[1] = Vr[4];
                mma_bf16(oa[jn], a, b);
            }
        }

        const int l0 = wbase + (n0 >> 6) * 4096 + ((n0 >> 3) & 7) * 64 + (n0 & 7);
        const int l1 = wbase + (n1 >> 6) * 4096 + ((n1 >> 3) & 7) * 64 + (n1 & 7);
        __nv_bfloat16* o0 = o + (size_t)l0 * C + head * HD + tq * 2;
        __nv_bfloat16* o1 = o + (size_t)l1 * C + head * HD + tq * 2;
#pragma unroll
        for (int jn = 0; jn < 4; jn++) {
            *(unsigned*)(o0 + jn * 8) = packbf(oa[jn][0], oa[jn][1]);
            *(unsigned*)(o1 + jn * 8) = packbf(oa[jn][2], oa[jn][3]);
        }
    }
}

// ---------------- depthwise 3x3x3 conv (bf16 io) + gelu + residual ---------
__global__ void dwconv_kernel(const __nv_bfloat16* __restrict__ hid,
                              const float* __restrict__ wgt, const float* __restrict__ bias,
                              __nv_bfloat16* __restrict__ hdn)
{
    const int c4  = threadIdx.x;
    const int bid = blockIdx.x;
    const int x0  = (bid & 7) * 8;
    const int y0  = ((bid >> 3) & 31) * 2;
    const int z   = bid >> 8;

    float4 acc[2][8];
#pragma unroll
    for (int yi = 0; yi < 2; yi++)
#pragma unroll
        for (int i = 0; i < 8; i++) acc[yi][i] = make_float4(0.f, 0.f, 0.f, 0.f);

    for (int kd = 0; kd < 3; kd++) {
        int zz = z + kd - 1;
        if (zz < 0 || zz >= DD) continue;
#pragma unroll
        for (int r = 0; r < 4; r++) {
            int yy = y0 - 1 + r;
            if (yy < 0 || yy >= HHH) continue;
            const __nv_bfloat16* base =
                hid + ((size_t)(zz * HHH + yy) * WWW) * HID + c4 * 4;
            float4 hv[10];
#pragma unroll
            for (int i = 0; i < 10; i++) {
                int xx = x0 - 1 + i;
                hv[i] = (xx >= 0 && xx < WWW) ? ldbf4(base + (size_t)xx * HID)
                                              : make_float4(0.f, 0.f, 0.f, 0.f);
            }
#pragma unroll
            for (int yi = 0; yi < 2; yi++) {
                int kh = r - yi;
                if (kh < 0 || kh > 2) continue;
#pragma unroll
                for (int kw = 0; kw < 3; kw++) {
                    float4 wv = *(const float4*)(wgt + ((kd * 3 + kh) * 3 + kw) * HID + c4 * 4);
#pragma unroll
                    for (int xi = 0; xi < 8; xi++) {
                        acc[yi][xi].x += hv[xi + kw].x * wv.x;
                        acc[yi][xi].y += hv[xi + kw].y * wv.y;
                        acc[yi][xi].z += hv[xi + kw].z * wv.z;
                        acc[yi][xi].w += hv[xi + kw].w * wv.w;
                    }
                }
            }
        }
    }
    float4 bv = *(const float4*)(bias + c4 * 4);
#pragma unroll
    for (int yi = 0; yi < 2; yi++) {
#pragma unroll
        for (int xi = 0; xi < 8; xi++) {
            size_t idx = ((size_t)((z * HHH + y0 + yi) * WWW + x0 + xi)) * HID + c4 * 4;
            float4 h0 = ldbf4(hid + idx);
            float4 o;
            o.x = h0.x + gelu_f(acc[yi][xi].x + bv.x);
            o.y = h0.y + gelu_f(acc[yi][xi].y + bv.y);
            o.z = h0.z + gelu_f(acc[yi][xi].z + bv.z);
            o.w = h0.w + gelu_f(acc[yi][xi].w + bv.w);
            stbf4(hdn + idx, o);
        }
    }
}

// ---------------- launch ----------------------------------------------------
static void* sym_addr(const void* sym) {
    void* p = nullptr;
    cudaGetSymbolAddress(&p, sym);
    return p;
}

extern "C" void kernel_launch(void* const* d_in, const int* in_sizes, int n_in,
                              void* d_out, int out_size)
{
    const float* x    = (const float*)d_in[0];
    const float* n1g  = (const float*)d_in[1];
    const float* n1b  = (const float*)d_in[2];
    const float* q_w  = (const float*)d_in[3];
    const float* q_b  = (const float*)d_in[4];
    const float* kv_w = (const float*)d_in[5];
    const float* kv_b = (const float*)d_in[6];
    const float* btab = (const float*)d_in[7];
    const float* p_w  = (const float*)d_in[8];
    const float* p_b  = (const float*)d_in[9];
    const float* n2g  = (const float*)d_in[10];
    const float* n2b  = (const float*)d_in[11];
    const float* f1w  = (const float*)d_in[12];
    const float* f1b  = (const float*)d_in[13];
    const float* dww  = (const float*)d_in[14];
    const float* dwb  = (const float*)d_in[15];
    const float* f2w  = (const float*)d_in[16];
    const float* f2b  = (const float*)d_in[17];
    float* out = (float*)d_out;

    __nv_bfloat16* xnb  = (__nv_bfloat16*)sym_addr(g_xnb);
    __nv_bfloat16* qb_  = (__nv_bfloat16*)sym_addr(g_qb);
    __nv_bfloat16* kb_  = (__nv_bfloat16*)sym_addr(g_kb);
    __nv_bfloat16* vb_  = (__nv_bfloat16*)sym_addr(g_vb2);
    __nv_bfloat16* ob   = (__nv_bfloat16*)sym_addr(g_ob);
    float*         x1   = (float*)sym_addr(g_x1);
    __nv_bfloat16* hidb = (__nv_bfloat16*)sym_addr(g_hidb);
    __nv_bfloat16* hdnb = (__nv_bfloat16*)sym_addr(g_hdnb);
    __nv_bfloat16* pwT  = (__nv_bfloat16*)sym_addr(g_pwT);
    __nv_bfloat16* f1wT = (__nv_bfloat16*)sym_addr(g_f1wT);
    __nv_bfloat16* f2wT = (__nv_bfloat16*)sym_addr(g_f2wT);

    const int attn_smem = ATTN_SMEM_WORDS * 4;
    cudaFuncSetAttribute(attn_mma_kernel,
                         cudaFuncAttributeMaxDynamicSharedMemorySize, attn_smem);
    cudaFuncSetAttribute(gemm_qkv,
                         cudaFuncAttributeMaxDynamicSharedMemorySize, QKV_SMEM_BYTES);
    cudaFuncSetAttribute(gemm192<1>,
                         cudaFuncAttributeMaxDynamicSharedMemorySize, G192_SMEM_BYTES);
    cudaFuncSetAttribute(gemm192<2>,
                         cudaFuncAttributeMaxDynamicSharedMemorySize, G192_SMEM_BYTES);
    cudaFuncSetAttribute(gemm192<3>,
                         cudaFuncAttributeMaxDynamicSharedMemorySize, G192_SMEM_BYTES);

    // 0) weight prep
    prep_kernel<<<(PREP_R3 + 255) / 256, 256>>>(q_w, q_b, kv_w, kv_b, p_w, f1w, f2w);
    // 1) LN1 -> bf16
    ln_kernel<<<L / 8, 256>>>(x, n1g, n1b, xnb);
    // 2) fused q + kv projection -> bf16 q/k/v
    gemm_qkv<<<dim3(4, L / 128), 128, QKV_SMEM_BYTES>>>(xnb, qb_, kb_, vb_);
    // 3) windowed attention (all bf16 mma)
    attn_mma_kernel<<<NWIN * NHD, 256, attn_smem>>>(qb_, kb_, vb_, btab, ob);
    // 4) proj + residual + FUSED LN2: x1 fp32 + xnb bf16
    gemm192<3><<<dim3(1, L / 128), 512, G192_SMEM_BYTES>>>(
        ob, pwT, p_b, x, x1, xnb, n2g, n2b, C, C);
    // 5) hid = gelu(xn @ fc1_w + fc1_b)
    gemm192<2><<<dim3(HID / 192, L / 128), 512, G192_SMEM_BYTES>>>(
        xnb, f1wT, f1b, nullptr, nullptr, hidb, nullptr, nullptr, HID, C);
    // 6) hdn = hid + gelu(dwconv(hid) + dw_b)
    dwconv_kernel<<<(DD * HHH * WWW) / 16, 192>>>(hidb, dww, dwb, hdnb);
    // 7) out = x1 + hdn @ fc2_w + fc2_b
    gemm192<1><<<dim3(1, L / 128), 512, G192_SMEM_BYTES>>>(
        hdnb, f2wT, f2b, x1, out, nullptr, nullptr, nullptr, C, HID);
}